// round 8
// baseline (speedup 1.0000x reference)
#include <cuda_runtime.h>
#include <math.h>
#include <stdint.h>

// ---------------- problem constants ----------------
#define BB 32
#define LL 512
#define CC 512
#define HH 512
#define KC 16          // clusters
#define PP 96
#define NBITER 4
#define ROWS (BB*CC)   // 16384
#define EPSV 1e-5f
#define GN 512         // GEMM N (all GEMMs are 16384x512x512)
#define GK 512         // GEMM K

// ---------------- scratch (static device globals; no allocation) ----------------
__device__ float g_xt   [(size_t)ROWS*HH];
__device__ float g_t    [(size_t)ROWS*HH];
__device__ float g_h    [(size_t)ROWS*HH];
__device__ float g_kk   [(size_t)ROWS*HH];
__device__ float g_v    [(size_t)ROWS*HH];
__device__ float g_z    [(size_t)ROWS*HH];
__device__ float g_z2   [(size_t)ROWS*HH];
__device__ float g_prod [(size_t)ROWS*HH];
__device__ float g_wts  [(size_t)7*GK*GN];    // tf32-rounded weights
__device__ float g_mean [ROWS];
__device__ float g_std  [ROWS];
__device__ float g_rm   [ROWS];   // per-row LN mean
__device__ float g_rs   [ROWS];   // per-row LN rstd
__device__ float g_acc  [ROWS];   // LN sum accumulator
__device__ float g_acc2 [ROWS];   // LN sumsq accumulator
__device__ float g_cn   [KC*HH];
__device__ float g_q    [KC*HH];
__device__ float g_p    [ROWS*KC];
__device__ float g_mask [ROWS*KC];
__device__ float g_am   [ROWS*KC];
__device__ float g_asum [BB*KC];
__device__ float g_cc   [BB*KC*HH];
__device__ float g_ce   [KC*HH];

// ---------------- helpers ----------------
__device__ __forceinline__ float gelu_f(float x) {
    return 0.5f * x * (1.0f + erff(x * 0.7071067811865476f));
}

__device__ __forceinline__ float f2tf32(float x) {
    uint32_t r;
    asm("cvt.rna.tf32.f32 %0, %1;" : "=r"(r) : "f"(x));
    return __uint_as_float(r);
}

__device__ __forceinline__ void cp16(uint32_t dst_smem, const void* src) {
    asm volatile("cp.async.ca.shared.global [%0], [%1], 16;"
                 :: "r"(dst_smem), "l"(src) : "memory");
}
__device__ __forceinline__ void cp_commit() {
    asm volatile("cp.async.commit_group;" ::: "memory");
}
__device__ __forceinline__ void cp_wait0() {
    asm volatile("cp.async.wait_group 0;" ::: "memory");
}

__device__ __forceinline__ uint32_t rotl32(uint32_t x, uint32_t d) {
    return (x << d) | (x >> (32u - d));
}

// JAX threefry2x32, PARTITIONABLE path. key = {0,42}; counter (0, idx);
// output word = out0 ^ out1.
__device__ uint32_t threefry_rand(uint32_t idx) {
    uint32_t x0 = 0u, x1 = idx;
    const uint32_t k0 = 0u, k1 = 42u;
    const uint32_t k2 = k0 ^ k1 ^ 0x1BD11BDAu;
    uint32_t ks[3] = {k0, k1, k2};
    x0 += ks[0]; x1 += ks[1];
    const uint32_t R[2][4] = {{13u,15u,26u,6u},{17u,29u,16u,24u}};
    #pragma unroll
    for (int i = 0; i < 5; i++) {
        #pragma unroll
        for (int j = 0; j < 4; j++) {
            x0 += x1; x1 = rotl32(x1, R[i & 1][j]); x1 ^= x0;
        }
        x0 += ks[(i + 1) % 3];
        x1 += ks[(i + 2) % 3] + (uint32_t)(i + 1);
    }
    return x0 ^ x1;
}

// ---------------- zero LN accumulators (once) ----------------
__global__ void zacc_kernel() {
    int i = blockIdx.x * 256 + threadIdx.x;
    g_acc[i] = 0.f;
    g_acc2[i] = 0.f;
}

// ---------------- weight pre-round: all 7 matrices in one launch ----------------
__global__ void round_all_kernel(const float* s0, const float* s1, const float* s2,
                                 const float* s3, const float* s4, const float* s5,
                                 const float* s6) {
    int i = blockIdx.x * 256 + threadIdx.x;
    const float* s;
    switch (blockIdx.y) {
        case 0: s = s0; break; case 1: s = s1; break; case 2: s = s2; break;
        case 3: s = s3; break; case 4: s = s4; break; case 5: s = s5; break;
        default: s = s6; break;
    }
    g_wts[(size_t)blockIdx.y * GK * GN + i] = f2tf32(s[i]);
}

// ---------------- RevIN stats ----------------
__global__ void revin_stats_kernel(const float* __restrict__ x) {
    int b = blockIdx.y;
    int c = blockIdx.x * 256 + threadIdx.x;
    float s = 0.f, s2 = 0.f;
    const float* xp = x + (size_t)b * LL * CC + c;
    for (int l = 0; l < LL; l++) {
        float v = xp[(size_t)l * CC];
        s += v; s2 += v * v;
    }
    float m = s * (1.0f / LL);
    float var = fmaxf(s2 * (1.0f / LL) - m * m, 0.0f);
    g_mean[b * CC + c] = m;
    g_std [b * CC + c] = sqrtf(var + EPSV);
}

// xt[b,c,l] = (x[b,l,c]-mean)/std*rev_w[c]+rev_b[c]   (tiled transpose)
__global__ void build_xt_kernel(const float* __restrict__ x,
                                const float* __restrict__ rev_w,
                                const float* __restrict__ rev_b) {
    __shared__ float sh[32][33];
    int b = blockIdx.z;
    int l0 = blockIdx.x * 32, c0 = blockIdx.y * 32;
    const float* xb = x + (size_t)b * LL * CC;
    float* ob = g_xt + (size_t)b * CC * LL;
    #pragma unroll
    for (int r = 0; r < 32; r += 8)
        sh[threadIdx.y + r][threadIdx.x] = xb[(size_t)(l0 + threadIdx.y + r) * CC + c0 + threadIdx.x];
    __syncthreads();
    #pragma unroll
    for (int r = 0; r < 32; r += 8) {
        int c = c0 + threadIdx.y + r;
        float mn = g_mean[b * CC + c];
        float sd = g_std[b * CC + c];
        float v = sh[threadIdx.x][threadIdx.y + r];
        ob[(size_t)c * LL + l0 + threadIdx.x] = (v - mn) / sd * rev_w[c] + rev_b[c];
    }
}

// ---------------- LN stats finalize: (sum,sumsq) -> (mean,rstd), reset acc ----
__global__ void lnfin_kernel() {
    int i = blockIdx.x * 256 + threadIdx.x;
    float s = g_acc[i], s2 = g_acc2[i];
    float m = s * (1.0f / CC);
    float var = fmaxf(s2 * (1.0f / CC) - m * m, 0.0f);
    g_rm[i] = m;
    g_rs[i] = rsqrtf(var + EPSV);
    g_acc[i] = 0.f;
    g_acc2[i] = 0.f;
}

// ---------------- TF32 tensor-core GEMM, K-tile 32, cp.async B ----
// C[M,512] = A'[M,512] @ W[512,512] (+bias, +epilogue), A' = A or LayerNorm(A).
// W must be tf32-pre-rounded. A is truncated to tf32 by the MMA itself.
// Dual-output: blockIdx.z selects (W,bias,out) vs (W2,bias2,out2).
#define E_RELU    0
#define E_BIAS    1
#define E_GELU    2
#define E_RESGELU 3
#define E_RESBIAS 4

__device__ __forceinline__ void mma_tf32(float c[4],
                                         uint32_t a0, uint32_t a1, uint32_t a2, uint32_t a3,
                                         uint32_t b0, uint32_t b1) {
    asm volatile(
        "mma.sync.aligned.m16n8k8.row.col.f32.tf32.tf32.f32 "
        "{%0,%1,%2,%3}, {%4,%5,%6,%7}, {%8,%9}, {%0,%1,%2,%3};"
        : "+f"(c[0]), "+f"(c[1]), "+f"(c[2]), "+f"(c[3])
        : "r"(a0), "r"(a1), "r"(a2), "r"(a3), "r"(b0), "r"(b1));
}

// A smem: As[m][32], element (m,k) at m*32 + ((k&3)^((m>>1)&3))*8 + (k>>2).
//   Thread fragment k-pairs {ks*8+tig, ks*8+tig+4} are aligned float2.
// B smem: Bs[k][132] (k-major rows, +4 pad), filled by cp.async.
template<int EPI, bool LNA, bool STATS>
__global__ __launch_bounds__(256, 2) void gemm_tc(
    const float* __restrict__ A, const float* __restrict__ W,
    const float* __restrict__ bias, const float* __restrict__ res,
    float* __restrict__ out,
    const float* __restrict__ ln_g, const float* __restrict__ ln_b,
    const float* __restrict__ W2, const float* __restrict__ bias2,
    float* __restrict__ out2) {
    __shared__ float As[2][128 * 32];
    __shared__ float Bs[2][32 * 132];
    if (blockIdx.z) { W = W2; bias = bias2; out = out2; }
    const int tid = threadIdx.x;
    const int warp = tid >> 5, lane = tid & 31;
    const int wm = (warp >> 2) * 64;    // warp M offset: 0 or 64
    const int wn = (warp & 3) * 32;     // warp N offset: 0,32,64,96
    const int gid = lane >> 2;          // 0..7
    const int tig = lane & 3;           // 0..3
    const int bx = blockIdx.x, by = blockIdx.y;

    const int arow = tid >> 1;          // 0..127
    const int ak   = (tid & 1) * 16;    // 0 or 16
    const int ssw  = (arow >> 1) & 3;   // store swizzle
    const int brow = tid >> 5;          // 0..7
    const int bn   = lane * 4;          // 0..124

    float acc[4][4][4];
    #pragma unroll
    for (int i = 0; i < 4; i++)
        #pragma unroll
        for (int j = 0; j < 4; j++)
            #pragma unroll
            for (int r = 0; r < 4; r++) acc[i][j][r] = 0.f;

    const float* Ap  = A + (size_t)(by * 128 + arow) * GK + ak;
    const float* Wp0 = W + (size_t)brow * GN + bx * 128 + bn;

    uint32_t bbase[2];
    #pragma unroll
    for (int b = 0; b < 2; b++)
        bbase[b] = (uint32_t)__cvta_generic_to_shared(&Bs[b][brow * 132 + bn]);

    float mu = 0.f, rsd = 1.f;
    if (LNA) {
        mu  = g_rm[by * 128 + arow];
        rsd = g_rs[by * 128 + arow];
    }

    float4 pa[4];
    #pragma unroll
    for (int q = 0; q < 4; q++) pa[q] = *(const float4*)(Ap + q * 4);

    const int NT = GK >> 5;   // 16 tiles of K=32

    auto issueB = [&](int buf, int kt) {
        const float* ws = Wp0 + (size_t)kt * 32 * GN;
        #pragma unroll
        for (int r = 0; r < 4; r++)
            cp16(bbase[buf] + r * 8 * 132 * 4, ws + (size_t)r * 8 * GN);
        cp_commit();
    };

    auto store_tileA = [&](int buf, int kt) {
        float va[16];
        #pragma unroll
        for (int q = 0; q < 4; q++) {
            va[q * 4 + 0] = pa[q].x; va[q * 4 + 1] = pa[q].y;
            va[q * 4 + 2] = pa[q].z; va[q * 4 + 3] = pa[q].w;
        }
        if (LNA) {
            const float* gp = ln_g + kt * 32 + ak;
            const float* bp = ln_b + kt * 32 + ak;
            #pragma unroll
            for (int j = 0; j < 16; j++) {
                float t = rsd * gp[j];
                va[j] = (va[j] - mu) * t + bp[j];
            }
        }
        float* Ab = As[buf];
        const int abase = arow * 32 + (ak >> 2);  // ak/4: 0 or 4
        #pragma unroll
        for (int g = 0; g < 4; g++) {
            int p0 = abase + ((g ^ ssw) << 3);
            *(float2*)(Ab + p0)     = make_float2(va[g],     va[g + 4]);
            *(float2*)(Ab + p0 + 2) = make_float2(va[g + 8], va[g + 12]);
        }
    };

    auto compute = [&](int buf) {
        const float* Ab = As[buf];
        const float* Bb = Bs[buf];
        #pragma unroll
        for (int ks = 0; ks < 4; ks++) {
            float2 fa0[4], fa1[4];
            #pragma unroll
            for (int i = 0; i < 4; i++) {
                int m0 = wm + i * 16 + gid;
                int sw = (m0 >> 1) & 3;
                int w = m0 * 32 + ((tig ^ sw) << 3) + ks * 2;
                fa0[i] = *(const float2*)(Ab + w);
                fa1[i] = *(const float2*)(Ab + w + 256);   // row m0+8
            }
            float fb0[4], fb1[4];
            #pragma unroll
            for (int j = 0; j < 4; j++) {
                int n0 = wn + j * 8 + gid;
                fb0[j] = Bb[(ks * 8 + tig) * 132 + n0];
                fb1[j] = Bb[(ks * 8 + tig + 4) * 132 + n0];
            }
            #pragma unroll
            for (int i = 0; i < 4; i++)
                #pragma unroll
                for (int j = 0; j < 4; j++)
                    mma_tf32(acc[i][j],
                             __float_as_uint(fa0[i].x), __float_as_uint(fa1[i].x),
                             __float_as_uint(fa0[i].y), __float_as_uint(fa1[i].y),
                             __float_as_uint(fb0[j]), __float_as_uint(fb1[j]));
        }
    };

    // prologue
    issueB(0, 0);
    store_tileA(0, 0);
    cp_wait0();
    __syncthreads();

    for (int kt = 0; kt < NT; kt++) {
        const int cur = kt & 1;
        const bool more = (kt + 1 < NT);
        if (more) {
            issueB(cur ^ 1, kt + 1);
            #pragma unroll
            for (int q = 0; q < 4; q++)
                pa[q] = *(const float4*)(Ap + (kt + 1) * 32 + q * 4);
        }
        compute(cur);
        if (more) store_tileA(cur ^ 1, kt + 1);
        cp_wait0();
        __syncthreads();
    }

    // epilogue (+ optional fused LN-stats accumulation of the OUTPUT rows)
    #pragma unroll
    for (int i = 0; i < 4; i++) {
        int gr0 = by * 128 + wm + i * 16 + gid;
        int gr1 = gr0 + 8;
        float slo = 0.f, qlo = 0.f, shi = 0.f, qhi = 0.f;
        #pragma unroll
        for (int j = 0; j < 4; j++) {
            int gc = bx * 128 + wn + j * 8 + 2 * tig;
            float b0v = bias[gc], b1v = bias[gc + 1];
            float v0 = acc[i][j][0] + b0v, v1 = acc[i][j][1] + b1v;
            float v2 = acc[i][j][2] + b0v, v3 = acc[i][j][3] + b1v;
            if (EPI == E_RELU) {
                v0 = fmaxf(v0, 0.f); v1 = fmaxf(v1, 0.f);
                v2 = fmaxf(v2, 0.f); v3 = fmaxf(v3, 0.f);
            } else if (EPI == E_GELU) {
                v0 = gelu_f(v0); v1 = gelu_f(v1);
                v2 = gelu_f(v2); v3 = gelu_f(v3);
            } else if (EPI == E_RESGELU) {
                const float2 r0 = *(const float2*)(res + (size_t)gr0 * GN + gc);
                const float2 r1 = *(const float2*)(res + (size_t)gr1 * GN + gc);
                v0 = r0.x + gelu_f(v0); v1 = r0.y + gelu_f(v1);
                v2 = r1.x + gelu_f(v2); v3 = r1.y + gelu_f(v3);
            } else if (EPI == E_RESBIAS) {
                const float2 r0 = *(const float2*)(res + (size_t)gr0 * GN + gc);
                const float2 r1 = *(const float2*)(res + (size_t)gr1 * GN + gc);
                v0 += r0.x; v1 += r0.y; v2 += r1.x; v3 += r1.y;
            }
            if (STATS) {
                slo += v0 + v1; qlo += v0 * v0 + v1 * v1;
                shi += v2 + v3; qhi += v2 * v2 + v3 * v3;
            }
            *(float2*)(out + (size_t)gr0 * GN + gc) = make_float2(v0, v1);
            *(float2*)(out + (size_t)gr1 * GN + gc) = make_float2(v2, v3);
        }
        if (STATS) {
            slo += __shfl_xor_sync(0xffffffffu, slo, 1);
            slo += __shfl_xor_sync(0xffffffffu, slo, 2);
            qlo += __shfl_xor_sync(0xffffffffu, qlo, 1);
            qlo += __shfl_xor_sync(0xffffffffu, qlo, 2);
            shi += __shfl_xor_sync(0xffffffffu, shi, 1);
            shi += __shfl_xor_sync(0xffffffffu, shi, 2);
            qhi += __shfl_xor_sync(0xffffffffu, qhi, 1);
            qhi += __shfl_xor_sync(0xffffffffu, qhi, 2);
            if (tig == 0) {
                atomicAdd(&g_acc[gr0], slo);
                atomicAdd(&g_acc2[gr0], qlo);
                atomicAdd(&g_acc[gr1], shi);
                atomicAdd(&g_acc2[gr1], qhi);
            }
        }
    }
}

// ---------------- cluster normalize (cn) ----------------
__global__ void cn_kernel(const float* __restrict__ ce) {
    __shared__ float red[256];
    int k = blockIdx.x, tid = threadIdx.x;
    float v0 = ce[k * HH + tid], v1 = ce[k * HH + tid + 256];
    red[tid] = v0 * v0 + v1 * v1;
    __syncthreads();
    for (int off = 128; off > 0; off >>= 1) {
        if (tid < off) red[tid] += red[tid + off];
        __syncthreads();
    }
    float nrm = fmaxf(sqrtf(red[0]), 1e-12f);
    g_cn[k * HH + tid] = v0 / nrm;
    g_cn[k * HH + tid + 256] = v1 / nrm;
}

// ---------------- Q = cluster_embeds @ wq + bq ----------------
__global__ void q_kernel(const float* __restrict__ ce,
                         const float* __restrict__ wq,
                         const float* __restrict__ bq) {
    __shared__ float csh[HH];
    int k = blockIdx.x, tid = threadIdx.x;
    csh[tid] = ce[k * HH + tid];
    csh[tid + 256] = ce[k * HH + tid + 256];
    __syncthreads();
    for (int n = tid; n < HH; n += 256) {
        float a = bq[n];
        for (int h = 0; h < HH; h++) a += csh[h] * wq[(size_t)h * HH + n];
        g_q[k * HH + n] = a;
    }
}

// ---------------- routing: warp per row; p = softmax(hn @ cn^T), bernoulli mask
__global__ __launch_bounds__(256) void routing_kernel(const float* __restrict__ h) {
    __shared__ float cnsh[KC * HH];   // 32KB
    int tid = threadIdx.x;
    for (int i = tid; i < KC * HH; i += 256) cnsh[i] = g_cn[i];
    __syncthreads();
    int w = tid >> 5, lane = tid & 31;
    int row = blockIdx.x * 8 + w;
    const float* hp = h + (size_t)row * HH;
    float acc[KC];
    #pragma unroll
    for (int k = 0; k < KC; k++) acc[k] = 0.f;
    float nsq = 0.f;
    #pragma unroll 4
    for (int i = 0; i < 16; i++) {
        int hh = i * 32 + lane;
        float hv = hp[hh];
        nsq += hv * hv;
        #pragma unroll
        for (int k = 0; k < KC; k++) acc[k] += hv * cnsh[k * HH + hh];
    }
    #pragma unroll
    for (int o = 16; o > 0; o >>= 1) nsq += __shfl_xor_sync(0xffffffffu, nsq, o);
    #pragma unroll
    for (int k = 0; k < KC; k++) {
        #pragma unroll
        for (int o = 16; o > 0; o >>= 1)
            acc[k] += __shfl_xor_sync(0xffffffffu, acc[k], o);
    }
    float inv = 1.0f / fmaxf(sqrtf(nsq), 1e-12f);
    float d = 0.f;
    #pragma unroll
    for (int k = 0; k < KC; k++) if (lane == k) d = acc[k];
    d *= inv;
    float mx = d;
    #pragma unroll
    for (int o = 8; o > 0; o >>= 1)
        mx = fmaxf(mx, __shfl_xor_sync(0xffffffffu, mx, o, 16));
    float e = expf(d - mx);
    float tot = e;
    #pragma unroll
    for (int o = 8; o > 0; o >>= 1)
        tot += __shfl_xor_sync(0xffffffffu, tot, o, 16);
    if (lane < KC) {
        float pv = e / tot;
        int idx = row * KC + lane;
        g_p[idx] = pv;
        uint32_t bits = threefry_rand((uint32_t)idx);
        float u = __uint_as_float((bits >> 9) | 0x3f800000u) - 1.0f;
        g_mask[idx] = (u < pv) ? 1.0f : 0.0f;
    }
}

// ---------------- attention phase 1: am = exp(score)*mask per row ----------------
__global__ __launch_bounds__(256) void scores_kernel() {
    __shared__ float qsh[KC * HH];   // [k][h], 32KB
    int tid = threadIdx.x;
    for (int i = tid; i < KC * HH; i += 256) qsh[i] = g_q[i];
    __syncthreads();
    int w = tid >> 5, lane = tid & 31;
    int row = blockIdx.x * 8 + w;
    const float* kp = g_kk + (size_t)row * HH;
    float acc[KC];
    #pragma unroll
    for (int k = 0; k < KC; k++) acc[k] = 0.f;
    #pragma unroll 4
    for (int i = 0; i < 16; i++) {
        int hh = i * 32 + lane;
        float kv = kp[hh];
        #pragma unroll
        for (int k = 0; k < KC; k++) acc[k] += kv * qsh[k * HH + hh];
    }
    #pragma unroll
    for (int k = 0; k < KC; k++) {
        #pragma unroll
        for (int o = 16; o > 0; o >>= 1)
            acc[k] += __shfl_xor_sync(0xffffffffu, acc[k], o);
    }
    if (lane < KC) {
        float am = expf(acc[lane] * 0.04419417382415922f) * g_mask[row * KC + lane];
        g_am[row * KC + lane] = am;
    }
}

// ---------------- attention phase 2: asum[b][k] = sum_c am ----------------
__global__ void asum_kernel() {
    int b = blockIdx.x;
    int k = threadIdx.x >> 5, lane = threadIdx.x & 31;
    float s = 0.f;
    for (int c = lane; c < CC; c += 32)
        s += g_am[((size_t)b * CC + c) * KC + k];
    #pragma unroll
    for (int o = 16; o > 0; o >>= 1) s += __shfl_down_sync(0xffffffffu, s, o);
    if (lane == 0) g_asum[b * KC + k] = s;
}

// ---------------- attention phase 3: Cc[b][k][h] = sum_c aw * V ----------------
__global__ __launch_bounds__(256) void vweight_kernel() {
    __shared__ float aw[KC * 514];
    __shared__ float inv_sh[KC];
    int b = blockIdx.x, h0 = blockIdx.y * 128;
    int tid = threadIdx.x;
    if (tid < KC) inv_sh[tid] = 1.0f / g_asum[b * KC + tid];
    __syncthreads();
    for (int idx = tid; idx < CC * KC; idx += 256) {
        int c = idx >> 4, k = idx & 15;
        aw[k * 514 + c] = g_am[((size_t)b * CC + c) * KC + k] * inv_sh[k];
    }
    __syncthreads();
    int kg = tid >> 6;
    int hg = tid & 63;
    const float* vp = g_v + (size_t)b * CC * HH + h0 + hg * 2;
    float a0[4], a1[4];
    #pragma unroll
    for (int k = 0; k < 4; k++) { a0[k] = 0.f; a1[k] = 0.f; }
    for (int c = 0; c < CC; c += 2) {
        float2 v0 = *(const float2*)(vp + (size_t)c * HH);
        float2 v1 = *(const float2*)(vp + (size_t)(c + 1) * HH);
        #pragma unroll
        for (int k = 0; k < 4; k++) {
            float2 a2 = *(const float2*)(&aw[(kg * 4 + k) * 514 + c]);
            a0[k] += a2.x * v0.x + a2.y * v1.x;
            a1[k] += a2.x * v0.y + a2.y * v1.y;
        }
    }
    #pragma unroll
    for (int k = 0; k < 4; k++) {
        size_t o = ((size_t)b * KC + kg * 4 + k) * HH + h0 + hg * 2;
        g_cc[o]     = a0[k];
        g_cc[o + 1] = a1[k];
    }
}

__global__ void ce_kernel() {
    int idx = blockIdx.x * 256 + threadIdx.x;
    float s = 0.f;
    for (int b = 0; b < BB; b++) s += g_cc[(size_t)b * KC * HH + idx];
    g_ce[idx] = s * (1.0f / BB);
}

// transpose per batch (h -> z) WITH fused LN-stats accumulation
__global__ void transpose_stats_kernel(const float* __restrict__ in, float* __restrict__ out) {
    __shared__ float sh[32][33];
    int b = blockIdx.z;
    int i0 = blockIdx.y * 32, j0 = blockIdx.x * 32;
    const float* ib = in + (size_t)b * CC * HH;
    float* ob = out + (size_t)b * CC * HH;
    #pragma unroll
    for (int r = 0; r < 32; r += 8)
        sh[threadIdx.y + r][threadIdx.x] = ib[(size_t)(i0 + threadIdx.y + r) * HH + j0 + threadIdx.x];
    __syncthreads();
    #pragma unroll
    for (int r = 0; r < 32; r += 8) {
        float v = sh[threadIdx.x][threadIdx.y + r];
        ob[(size_t)(j0 + threadIdx.y + r) * HH + i0 + threadIdx.x] = v;
        float s = v, q = v * v;
        #pragma unroll
        for (int o = 16; o > 0; o >>= 1) {
            s += __shfl_xor_sync(0xffffffffu, s, o);
            q += __shfl_xor_sync(0xffffffffu, q, o);
        }
        if (threadIdx.x == 0) {
            int row = b * HH + j0 + threadIdx.y + r;
            atomicAdd(&g_acc[row], s);
            atomicAdd(&g_acc2[row], q);
        }
    }
}

// prod[b,c,h] = z[b,h,c] * theta[b,c,h], theta computed on the fly from p & ce
__global__ void prod_kernel() {
    __shared__ float sh[32][33];
    __shared__ float cesh[KC][32];
    __shared__ float psh[32][KC + 1];
    int b = blockIdx.z;
    int h0 = blockIdx.y * 32, c0 = blockIdx.x * 32;
    const float* zb = g_z + (size_t)b * HH * CC;
    float* ob = g_prod + (size_t)b * CC * HH;
    int tid = threadIdx.y * 32 + threadIdx.x;
    #pragma unroll
    for (int r = 0; r < 32; r += 8)
        sh[threadIdx.y + r][threadIdx.x] = zb[(size_t)(h0 + threadIdx.y + r) * CC + c0 + threadIdx.x];
    for (int t = tid; t < KC * 32; t += 256) {
        int k = t >> 5, xx = t & 31;
        cesh[k][xx] = g_ce[k * HH + h0 + xx];
    }
    for (int t = tid; t < 32 * KC; t += 256) {
        int c = t >> 4, k = t & 15;
        psh[c][k] = g_p[((size_t)b * CC + c0 + c) * KC + k];
    }
    __syncthreads();
    #pragma unroll
    for (int r = 0; r < 32; r += 8) {
        int cl = threadIdx.y + r;
        float th = 0.f;
        #pragma unroll
        for (int k = 0; k < KC; k++) th += psh[cl][k] * cesh[k][threadIdx.x];
        size_t o = (size_t)(c0 + cl) * HH + h0 + threadIdx.x;
        ob[o] = sh[threadIdx.x][cl] * th;
    }
}

// final: y[b,p,c] = denorm( sum_h prod[b,c,h]*out_w[c,h,p] + out_b[c,p] )
__global__ void final_kernel(const float* __restrict__ out_w,
                             const float* __restrict__ out_b,
                             const float* __restrict__ rev_w,
                             const float* __restrict__ rev_b,
                             float* __restrict__ y) {
    int c = blockIdx.x;
    __shared__ float Ws[32][PP];
    __shared__ float As[32][33];
    int tid = threadIdx.x;
    int tb = tid >> 3;
    int tp = (tid & 7) * 12;
    float acc[12];
    #pragma unroll
    for (int j = 0; j < 12; j++) acc[j] = 0.f;

    for (int h0 = 0; h0 < HH; h0 += 32) {
        for (int t = tid; t < 32 * PP; t += 256) {
            int i = t / PP, pp = t % PP;
            Ws[i][pp] = out_w[((size_t)c * HH + h0 + i) * PP + pp];
        }
        for (int t = tid; t < 32 * 32; t += 256) {
            int b = t >> 5, i = t & 31;
            As[b][i] = g_prod[((size_t)b * CC + c) * HH + h0 + i];
        }
        __syncthreads();
        #pragma unroll
        for (int i = 0; i < 32; i++) {
            float a = As[tb][i];
            #pragma unroll
            for (int j = 0; j < 12; j++) acc[j] += a * Ws[i][tp + j];
        }
        __syncthreads();
    }
    float rb = rev_b[c];
    float rwinv = 1.0f / (rev_w[c] + 1e-10f);
    float sd = g_std[tb * CC + c];
    float mn = g_mean[tb * CC + c];
    #pragma unroll
    for (int j = 0; j < 12; j++) {
        float v = acc[j] + out_b[(size_t)c * PP + tp + j];
        v = (v - rb) * rwinv;
        v = v * sd + mn;
        y[((size_t)tb * PP + tp + j) * CC + c] = v;
    }
}

// ---------------- host orchestration ----------------
extern "C" void kernel_launch(void* const* d_in, const int* in_sizes, int n_in,
                              void* d_out, int out_size) {
    const float* x       = (const float*)d_in[0];
    const float* rev_w   = (const float*)d_in[1];
    const float* rev_b   = (const float*)d_in[2];
    const float* mlp_w1  = (const float*)d_in[3];
    const float* mlp_b1  = (const float*)d_in[4];
    const float* mlp_w2  = (const float*)d_in[5];
    const float* mlp_b2  = (const float*)d_in[6];
    const float* cle     = (const float*)d_in[7];
    const float* wq      = (const float*)d_in[8];
    const float* bq      = (const float*)d_in[9];
    const float* wk      = (const float*)d_in[10];
    const float* bk      = (const float*)d_in[11];
    const float* wv      = (const float*)d_in[12];
    const float* bv      = (const float*)d_in[13];
    const float* ts_ln_g = (const float*)d_in[14];
    const float* ts_ln_b = (const float*)d_in[15];
    const float* ts_w    = (const float*)d_in[16];
    const float* ts_b    = (const float*)d_in[17];
    const float* ch_ln_g = (const float*)d_in[18];
    const float* ch_ln_b = (const float*)d_in[19];
    const float* ch_w1   = (const float*)d_in[20];
    const float* ch_b1   = (const float*)d_in[21];
    const float* ch_w2   = (const float*)d_in[22];
    const float* ch_b2   = (const float*)d_in[23];
    const float* out_w   = (const float*)d_in[24];
    const float* out_b   = (const float*)d_in[25];
    float* y = (float*)d_out;

    float *p_xt, *p_t, *p_h, *p_kk, *p_v, *p_z, *p_z2, *p_w;
    cudaGetSymbolAddress((void**)&p_xt, g_xt);
    cudaGetSymbolAddress((void**)&p_t,  g_t);
    cudaGetSymbolAddress((void**)&p_h,  g_h);
    cudaGetSymbolAddress((void**)&p_kk, g_kk);
    cudaGetSymbolAddress((void**)&p_v,  g_v);
    cudaGetSymbolAddress((void**)&p_z,  g_z);
    cudaGetSymbolAddress((void**)&p_z2, g_z2);
    cudaGetSymbolAddress((void**)&p_w,  g_wts);

    const size_t WSZ = (size_t)GK * GN;
    float* w_mlp1 = p_w + 0 * WSZ;
    float* w_mlp2 = p_w + 1 * WSZ;
    float* w_k    = p_w + 2 * WSZ;
    float* w_v    = p_w + 3 * WSZ;
    float* w_ts   = p_w + 4 * WSZ;
    float* w_ch1  = p_w + 5 * WSZ;
    float* w_ch2  = p_w + 6 * WSZ;

    dim3 tgrid(16, 16, BB), tblk(32, 8);
    dim3 ggrid(GN / 128, ROWS / 128);
    dim3 ggrid2(GN / 128, ROWS / 128, 2);
    const int RWB = (int)(WSZ / 256);

    // 0) zero LN accumulators + pre-round all weights to tf32
    zacc_kernel<<<ROWS / 256, 256>>>();
    round_all_kernel<<<dim3(RWB, 7), 256>>>(mlp_w1, mlp_w2, wk, wv, ts_w, ch_w1, ch_w2);

    // 1) RevIN stats + normalized transpose
    revin_stats_kernel<<<dim3(CC / 256, BB), 256>>>(x);
    build_xt_kernel<<<tgrid, tblk>>>(x, rev_w, rev_b);

    // 2) channel MLP: h = relu(xt@w1+b1)@w2+b2
    gemm_tc<E_RELU, false, false><<<ggrid, 256>>>(p_xt, w_mlp1, mlp_b1, nullptr, p_t,
                                                  nullptr, nullptr, w_mlp1, mlp_b1, p_t);
    gemm_tc<E_BIAS, false, false><<<ggrid, 256>>>(p_t, w_mlp2, mlp_b2, nullptr, p_h,
                                                  nullptr, nullptr, w_mlp2, mlp_b2, p_h);

    // 3) routing (p + threefry bernoulli mask)
    cn_kernel<<<KC, 256>>>(cle);
    q_kernel<<<KC, 256>>>(cle, wq, bq);
    routing_kernel<<<ROWS / 8, 256>>>(p_h);

    // 4) K/V projections (ONE launch, grid.z selects) + attention + ce_new
    gemm_tc<E_BIAS, false, false><<<ggrid2, 256>>>(p_h, w_k, bk, nullptr, p_kk,
                                                   nullptr, nullptr, w_v, bv, p_v);
    scores_kernel<<<ROWS / 8, 256>>>();
    asum_kernel<<<BB, 512>>>();
    vweight_kernel<<<dim3(BB, HH / 128), 256>>>();
    ce_kernel<<<KC * HH / 256, 256>>>();

    // 5) mixer: state in [B,H,C] layout; LN fused into GEMM A-path,
    //    LN stats fused into producer epilogues
    transpose_stats_kernel<<<tgrid, tblk>>>(p_h, p_z);
    for (int it = 0; it < NBITER; it++) {
        lnfin_kernel<<<ROWS / 256, 256>>>();                        // stats(z)
        gemm_tc<E_RESGELU, true, true><<<ggrid, 256>>>(p_z, w_ts, ts_b, p_z, p_z2,
                                                       ts_ln_g, ts_ln_b, w_ts, ts_b, p_z2);
        lnfin_kernel<<<ROWS / 256, 256>>>();                        // stats(z2)
        gemm_tc<E_GELU, true, false><<<ggrid, 256>>>(p_z2, w_ch1, ch_b1, nullptr, p_t,
                                                     ch_ln_g, ch_ln_b, w_ch1, ch_b1, p_t);
        if (it < NBITER - 1)
            gemm_tc<E_RESBIAS, false, true><<<ggrid, 256>>>(p_t, w_ch2, ch_b2, p_z2, p_z,
                                                            nullptr, nullptr, w_ch2, ch_b2, p_z);
        else
            gemm_tc<E_RESBIAS, false, false><<<ggrid, 256>>>(p_t, w_ch2, ch_b2, p_z2, p_z,
                                                             nullptr, nullptr, w_ch2, ch_b2, p_z);
    }

    // 6) expert projection (theta fused) + RevIN denorm
    prod_kernel<<<tgrid, tblk>>>();
    final_kernel<<<CC, 256>>>(out_w, out_b, rev_w, rev_b, y);
}

// round 9
// speedup vs baseline: 1.2092x; 1.2092x over previous
#include <cuda_runtime.h>
#include <math.h>
#include <stdint.h>

// ---------------- problem constants ----------------
#define BB 32
#define LL 512
#define CC 512
#define HH 512
#define KC 16          // clusters
#define PP 96
#define NBITER 4
#define ROWS (BB*CC)   // 16384
#define EPSV 1e-5f
#define GN 512         // GEMM N (all GEMMs are 16384x512x512)
#define GK 512         // GEMM K

// ---------------- scratch (static device globals; no allocation) ----------------
__device__ float g_xt   [(size_t)ROWS*HH];
__device__ float g_t    [(size_t)ROWS*HH];
__device__ float g_h    [(size_t)ROWS*HH];
__device__ float g_kk   [(size_t)ROWS*HH];
__device__ float g_v    [(size_t)ROWS*HH];
__device__ float g_z    [(size_t)ROWS*HH];
__device__ float g_z2   [(size_t)ROWS*HH];
__device__ float g_prod [(size_t)ROWS*HH];
__device__ float g_wts  [(size_t)7*GK*GN];    // tf32-rounded weights
__device__ float g_mean [ROWS];
__device__ float g_std  [ROWS];
__device__ float g_rm   [ROWS];   // per-row LN mean
__device__ float g_rs   [ROWS];   // per-row LN rstd
__device__ float g_acc  [ROWS];   // LN sum accumulator
__device__ float g_acc2 [ROWS];   // LN sumsq accumulator
__device__ float g_cn   [KC*HH];
__device__ float g_q    [KC*HH];
__device__ float g_p    [ROWS*KC];
__device__ float g_mask [ROWS*KC];
__device__ float g_am   [ROWS*KC];
__device__ float g_asum [BB*KC];
__device__ float g_cc   [BB*KC*HH];
__device__ float g_ce   [KC*HH];

// ---------------- helpers ----------------
__device__ __forceinline__ float gelu_f(float x) {
    return 0.5f * x * (1.0f + erff(x * 0.7071067811865476f));
}

__device__ __forceinline__ float f2tf32(float x) {
    uint32_t r;
    asm("cvt.rna.tf32.f32 %0, %1;" : "=r"(r) : "f"(x));
    return __uint_as_float(r);
}

__device__ __forceinline__ void cp16(uint32_t dst_smem, const void* src) {
    asm volatile("cp.async.ca.shared.global [%0], [%1], 16;"
                 :: "r"(dst_smem), "l"(src) : "memory");
}
__device__ __forceinline__ void cp_commit() {
    asm volatile("cp.async.commit_group;" ::: "memory");
}
__device__ __forceinline__ void cp_wait0() {
    asm volatile("cp.async.wait_group 0;" ::: "memory");
}

__device__ __forceinline__ uint32_t rotl32(uint32_t x, uint32_t d) {
    return (x << d) | (x >> (32u - d));
}

// JAX threefry2x32, PARTITIONABLE path. key = {0,42}; counter (0, idx);
// output word = out0 ^ out1.
__device__ uint32_t threefry_rand(uint32_t idx) {
    uint32_t x0 = 0u, x1 = idx;
    const uint32_t k0 = 0u, k1 = 42u;
    const uint32_t k2 = k0 ^ k1 ^ 0x1BD11BDAu;
    uint32_t ks[3] = {k0, k1, k2};
    x0 += ks[0]; x1 += ks[1];
    const uint32_t R[2][4] = {{13u,15u,26u,6u},{17u,29u,16u,24u}};
    #pragma unroll
    for (int i = 0; i < 5; i++) {
        #pragma unroll
        for (int j = 0; j < 4; j++) {
            x0 += x1; x1 = rotl32(x1, R[i & 1][j]); x1 ^= x0;
        }
        x0 += ks[(i + 1) % 3];
        x1 += ks[(i + 2) % 3] + (uint32_t)(i + 1);
    }
    return x0 ^ x1;
}

// ---------------- zero LN accumulators (once) ----------------
__global__ void zacc_kernel() {
    int i = blockIdx.x * 256 + threadIdx.x;
    g_acc[i] = 0.f;
    g_acc2[i] = 0.f;
}

// ---------------- weight pre-round: all 7 matrices in one launch ----------------
__global__ void round_all_kernel(const float* s0, const float* s1, const float* s2,
                                 const float* s3, const float* s4, const float* s5,
                                 const float* s6) {
    int i = blockIdx.x * 256 + threadIdx.x;
    const float* s;
    switch (blockIdx.y) {
        case 0: s = s0; break; case 1: s = s1; break; case 2: s = s2; break;
        case 3: s = s3; break; case 4: s = s4; break; case 5: s = s5; break;
        default: s = s6; break;
    }
    g_wts[(size_t)blockIdx.y * GK * GN + i] = f2tf32(s[i]);
}

// ---------------- RevIN stats ----------------
__global__ void revin_stats_kernel(const float* __restrict__ x) {
    int b = blockIdx.y;
    int c = blockIdx.x * 256 + threadIdx.x;
    float s = 0.f, s2 = 0.f;
    const float* xp = x + (size_t)b * LL * CC + c;
    for (int l = 0; l < LL; l++) {
        float v = xp[(size_t)l * CC];
        s += v; s2 += v * v;
    }
    float m = s * (1.0f / LL);
    float var = fmaxf(s2 * (1.0f / LL) - m * m, 0.0f);
    g_mean[b * CC + c] = m;
    g_std [b * CC + c] = sqrtf(var + EPSV);
}

// xt[b,c,l] = (x[b,l,c]-mean)/std*rev_w[c]+rev_b[c]   (tiled transpose)
__global__ void build_xt_kernel(const float* __restrict__ x,
                                const float* __restrict__ rev_w,
                                const float* __restrict__ rev_b) {
    __shared__ float sh[32][33];
    int b = blockIdx.z;
    int l0 = blockIdx.x * 32, c0 = blockIdx.y * 32;
    const float* xb = x + (size_t)b * LL * CC;
    float* ob = g_xt + (size_t)b * CC * LL;
    #pragma unroll
    for (int r = 0; r < 32; r += 8)
        sh[threadIdx.y + r][threadIdx.x] = xb[(size_t)(l0 + threadIdx.y + r) * CC + c0 + threadIdx.x];
    __syncthreads();
    #pragma unroll
    for (int r = 0; r < 32; r += 8) {
        int c = c0 + threadIdx.y + r;
        float mn = g_mean[b * CC + c];
        float sd = g_std[b * CC + c];
        float v = sh[threadIdx.x][threadIdx.y + r];
        ob[(size_t)c * LL + l0 + threadIdx.x] = (v - mn) / sd * rev_w[c] + rev_b[c];
    }
}

// ---------------- LN stats finalize: (sum,sumsq) -> (mean,rstd), reset acc ----
__global__ void lnfin_kernel() {
    int i = blockIdx.x * 256 + threadIdx.x;
    float s = g_acc[i], s2 = g_acc2[i];
    float m = s * (1.0f / CC);
    float var = fmaxf(s2 * (1.0f / CC) - m * m, 0.0f);
    g_rm[i] = m;
    g_rs[i] = rsqrtf(var + EPSV);
    g_acc[i] = 0.f;
    g_acc2[i] = 0.f;
}

// ---------------- TF32 tensor-core GEMM, K-tile 16, cp.async B ----
// C[M,512] = A'[M,512] @ W[512,512] (+bias, +epilogue), A' = A or LayerNorm(A).
// W must be tf32-pre-rounded. A is truncated to tf32 by the MMA itself.
// Dual-output: blockIdx.z selects (W,bias,out) vs (W2,bias2,out2).
#define E_RELU    0
#define E_BIAS    1
#define E_GELU    2
#define E_RESGELU 3
#define E_RESBIAS 4

__device__ __forceinline__ void mma_tf32(float c[4],
                                         uint32_t a0, uint32_t a1, uint32_t a2, uint32_t a3,
                                         uint32_t b0, uint32_t b1) {
    asm volatile(
        "mma.sync.aligned.m16n8k8.row.col.f32.tf32.tf32.f32 "
        "{%0,%1,%2,%3}, {%4,%5,%6,%7}, {%8,%9}, {%0,%1,%2,%3};"
        : "+f"(c[0]), "+f"(c[1]), "+f"(c[2]), "+f"(c[3])
        : "r"(a0), "r"(a1), "r"(a2), "r"(a3), "r"(b0), "r"(b1));
}

// A smem layout: As[m][16], element (m,k) at word m*16 + ((k&3)^((m>>1)&3))*4 + (k>>2)
// B smem layout: Bs[k][132] (k-major rows, +4 pad), filled by cp.async.
template<int EPI, bool LNA, bool STATS>
__global__ __launch_bounds__(256, 2) void gemm_tc(
    const float* __restrict__ A, const float* __restrict__ W,
    const float* __restrict__ bias, const float* __restrict__ res,
    float* __restrict__ out,
    const float* __restrict__ ln_g, const float* __restrict__ ln_b,
    const float* __restrict__ W2, const float* __restrict__ bias2,
    float* __restrict__ out2) {
    __shared__ float As[2][128 * 16];
    __shared__ float Bs[2][16 * 132];
    if (blockIdx.z) { W = W2; bias = bias2; out = out2; }
    const int tid = threadIdx.x;
    const int warp = tid >> 5, lane = tid & 31;
    const int wm = (warp >> 2) * 64;    // warp M offset: 0 or 64
    const int wn = (warp & 3) * 32;     // warp N offset: 0,32,64,96
    const int gid = lane >> 2;          // 0..7
    const int tig = lane & 3;           // 0..3
    const int bx = blockIdx.x, by = blockIdx.y;

    const int arow = tid >> 1;          // 0..127
    const int ak   = (tid & 1) * 8;     // 0 or 8
    const int ssw  = (arow >> 1) & 3;   // store swizzle
    const int brow = tid >> 5;          // 0..7
    const int bn   = lane * 4;          // 0..124

    float acc[4][4][4];
    #pragma unroll
    for (int i = 0; i < 4; i++)
        #pragma unroll
        for (int j = 0; j < 4; j++)
            #pragma unroll
            for (int r = 0; r < 4; r++) acc[i][j][r] = 0.f;

    const float* Ap  = A + (size_t)(by * 128 + arow) * GK + ak;
    const float* Wp0 = W + (size_t)brow * GN + bx * 128 + bn;

    uint32_t ba0[2], ba1[2];
    #pragma unroll
    for (int b = 0; b < 2; b++) {
        ba0[b] = (uint32_t)__cvta_generic_to_shared(&Bs[b][brow * 132 + bn]);
        ba1[b] = (uint32_t)__cvta_generic_to_shared(&Bs[b][(brow + 8) * 132 + bn]);
    }

    float mu = 0.f, rsd = 1.f;
    if (LNA) {
        mu  = g_rm[by * 128 + arow];
        rsd = g_rs[by * 128 + arow];
    }

    float4 pa0 = *(const float4*)Ap;
    float4 pa1 = *(const float4*)(Ap + 4);

    const int NT = GK >> 4;

    auto store_tileA = [&](int buf, int kt) {
        float va[8] = {pa0.x, pa0.y, pa0.z, pa0.w, pa1.x, pa1.y, pa1.z, pa1.w};
        if (LNA) {
            const float* gp = ln_g + kt * 16 + ak;
            const float* bp = ln_b + kt * 16 + ak;
            #pragma unroll
            for (int j = 0; j < 8; j++) {
                float t = rsd * gp[j];
                va[j] = (va[j] - mu) * t + bp[j];
            }
        }
        float* Ab = As[buf];
        const int abase = arow * 16 + (ak >> 2);
        #pragma unroll
        for (int j = 0; j < 4; j++) {
            *(float2*)(Ab + abase + ((j ^ ssw) << 2)) = make_float2(va[j], va[j + 4]);
        }
    };

    auto compute = [&](int buf) {
        const float* Ab = As[buf];
        const float* Bb = Bs[buf];
        #pragma unroll
        for (int ks = 0; ks < 2; ks++) {
            float2 fa0[4], fa1[4];
            #pragma unroll
            for (int i = 0; i < 4; i++) {
                int m0 = wm + i * 16 + gid;
                int sw = (m0 >> 1) & 3;
                int w = m0 * 16 + ((tig ^ sw) << 2) + ks * 2;
                fa0[i] = *(const float2*)(Ab + w);
                fa1[i] = *(const float2*)(Ab + w + 128);   // row m0+8: same swizzle
            }
            float fb0[4], fb1[4];
            #pragma unroll
            for (int j = 0; j < 4; j++) {
                int n0 = wn + j * 8 + gid;
                fb0[j] = Bb[(ks * 8 + tig) * 132 + n0];
                fb1[j] = Bb[(ks * 8 + tig + 4) * 132 + n0];
            }
            #pragma unroll
            for (int i = 0; i < 4; i++)
                #pragma unroll
                for (int j = 0; j < 4; j++)
                    mma_tf32(acc[i][j],
                             __float_as_uint(fa0[i].x), __float_as_uint(fa1[i].x),
                             __float_as_uint(fa0[i].y), __float_as_uint(fa1[i].y),
                             __float_as_uint(fb0[j]), __float_as_uint(fb1[j]));
        }
    };

    // prologue: B tile 0 async, A tile 0 via registers
    cp16(ba0[0], Wp0);
    cp16(ba1[0], Wp0 + (size_t)8 * GN);
    cp_commit();
    store_tileA(0, 0);
    cp_wait0();
    __syncthreads();

    for (int kt = 0; kt < NT; kt++) {
        const int cur = kt & 1;
        const bool more = (kt + 1 < NT);
        if (more) {
            const float* ws = Wp0 + (size_t)(kt + 1) * 16 * GN;
            cp16(ba0[cur ^ 1], ws);
            cp16(ba1[cur ^ 1], ws + (size_t)8 * GN);
            cp_commit();
            pa0 = *(const float4*)(Ap + (kt + 1) * 16);
            pa1 = *(const float4*)(Ap + (kt + 1) * 16 + 4);
        }
        compute(cur);
        if (more) store_tileA(cur ^ 1, kt + 1);
        cp_wait0();
        __syncthreads();
    }

    // epilogue (+ optional fused LN-stats accumulation of the OUTPUT rows)
    #pragma unroll
    for (int i = 0; i < 4; i++) {
        int gr0 = by * 128 + wm + i * 16 + gid;
        int gr1 = gr0 + 8;
        float slo = 0.f, qlo = 0.f, shi = 0.f, qhi = 0.f;
        #pragma unroll
        for (int j = 0; j < 4; j++) {
            int gc = bx * 128 + wn + j * 8 + 2 * tig;
            float b0v = bias[gc], b1v = bias[gc + 1];
            float v0 = acc[i][j][0] + b0v, v1 = acc[i][j][1] + b1v;
            float v2 = acc[i][j][2] + b0v, v3 = acc[i][j][3] + b1v;
            if (EPI == E_RELU) {
                v0 = fmaxf(v0, 0.f); v1 = fmaxf(v1, 0.f);
                v2 = fmaxf(v2, 0.f); v3 = fmaxf(v3, 0.f);
            } else if (EPI == E_GELU) {
                v0 = gelu_f(v0); v1 = gelu_f(v1);
                v2 = gelu_f(v2); v3 = gelu_f(v3);
            } else if (EPI == E_RESGELU) {
                const float2 r0 = *(const float2*)(res + (size_t)gr0 * GN + gc);
                const float2 r1 = *(const float2*)(res + (size_t)gr1 * GN + gc);
                v0 = r0.x + gelu_f(v0); v1 = r0.y + gelu_f(v1);
                v2 = r1.x + gelu_f(v2); v3 = r1.y + gelu_f(v3);
            } else if (EPI == E_RESBIAS) {
                const float2 r0 = *(const float2*)(res + (size_t)gr0 * GN + gc);
                const float2 r1 = *(const float2*)(res + (size_t)gr1 * GN + gc);
                v0 += r0.x; v1 += r0.y; v2 += r1.x; v3 += r1.y;
            }
            if (STATS) {
                slo += v0 + v1; qlo += v0 * v0 + v1 * v1;
                shi += v2 + v3; qhi += v2 * v2 + v3 * v3;
            }
            *(float2*)(out + (size_t)gr0 * GN + gc) = make_float2(v0, v1);
            *(float2*)(out + (size_t)gr1 * GN + gc) = make_float2(v2, v3);
        }
        if (STATS) {
            slo += __shfl_xor_sync(0xffffffffu, slo, 1);
            slo += __shfl_xor_sync(0xffffffffu, slo, 2);
            qlo += __shfl_xor_sync(0xffffffffu, qlo, 1);
            qlo += __shfl_xor_sync(0xffffffffu, qlo, 2);
            shi += __shfl_xor_sync(0xffffffffu, shi, 1);
            shi += __shfl_xor_sync(0xffffffffu, shi, 2);
            qhi += __shfl_xor_sync(0xffffffffu, qhi, 1);
            qhi += __shfl_xor_sync(0xffffffffu, qhi, 2);
            if (tig == 0) {
                atomicAdd(&g_acc[gr0], slo);
                atomicAdd(&g_acc2[gr0], qlo);
                atomicAdd(&g_acc[gr1], shi);
                atomicAdd(&g_acc2[gr1], qhi);
            }
        }
    }
}

// ---------------- cluster normalize (cn) ----------------
__global__ void cn_kernel(const float* __restrict__ ce) {
    __shared__ float red[256];
    int k = blockIdx.x, tid = threadIdx.x;
    float v0 = ce[k * HH + tid], v1 = ce[k * HH + tid + 256];
    red[tid] = v0 * v0 + v1 * v1;
    __syncthreads();
    for (int off = 128; off > 0; off >>= 1) {
        if (tid < off) red[tid] += red[tid + off];
        __syncthreads();
    }
    float nrm = fmaxf(sqrtf(red[0]), 1e-12f);
    g_cn[k * HH + tid] = v0 / nrm;
    g_cn[k * HH + tid + 256] = v1 / nrm;
}

// ---------------- Q = cluster_embeds @ wq + bq ----------------
__global__ void q_kernel(const float* __restrict__ ce,
                         const float* __restrict__ wq,
                         const float* __restrict__ bq) {
    __shared__ float csh[HH];
    int k = blockIdx.x, tid = threadIdx.x;
    csh[tid] = ce[k * HH + tid];
    csh[tid + 256] = ce[k * HH + tid + 256];
    __syncthreads();
    for (int n = tid; n < HH; n += 256) {
        float a = bq[n];
        for (int h = 0; h < HH; h++) a += csh[h] * wq[(size_t)h * HH + n];
        g_q[k * HH + n] = a;
    }
}

// ---------------- routing: warp per row; p = softmax(hn @ cn^T), bernoulli mask
__global__ __launch_bounds__(256) void routing_kernel(const float* __restrict__ h) {
    __shared__ float cnsh[KC * HH];   // 32KB
    int tid = threadIdx.x;
    for (int i = tid; i < KC * HH; i += 256) cnsh[i] = g_cn[i];
    __syncthreads();
    int w = tid >> 5, lane = tid & 31;
    int row = blockIdx.x * 8 + w;
    const float* hp = h + (size_t)row * HH;
    float acc[KC];
    #pragma unroll
    for (int k = 0; k < KC; k++) acc[k] = 0.f;
    float nsq = 0.f;
    #pragma unroll 4
    for (int i = 0; i < 16; i++) {
        int hh = i * 32 + lane;
        float hv = hp[hh];
        nsq += hv * hv;
        #pragma unroll
        for (int k = 0; k < KC; k++) acc[k] += hv * cnsh[k * HH + hh];
    }
    #pragma unroll
    for (int o = 16; o > 0; o >>= 1) nsq += __shfl_xor_sync(0xffffffffu, nsq, o);
    #pragma unroll
    for (int k = 0; k < KC; k++) {
        #pragma unroll
        for (int o = 16; o > 0; o >>= 1)
            acc[k] += __shfl_xor_sync(0xffffffffu, acc[k], o);
    }
    float inv = 1.0f / fmaxf(sqrtf(nsq), 1e-12f);
    float d = 0.f;
    #pragma unroll
    for (int k = 0; k < KC; k++) if (lane == k) d = acc[k];
    d *= inv;
    float mx = d;
    #pragma unroll
    for (int o = 8; o > 0; o >>= 1)
        mx = fmaxf(mx, __shfl_xor_sync(0xffffffffu, mx, o, 16));
    float e = expf(d - mx);
    float tot = e;
    #pragma unroll
    for (int o = 8; o > 0; o >>= 1)
        tot += __shfl_xor_sync(0xffffffffu, tot, o, 16);
    if (lane < KC) {
        float pv = e / tot;
        int idx = row * KC + lane;
        g_p[idx] = pv;
        uint32_t bits = threefry_rand((uint32_t)idx);
        float u = __uint_as_float((bits >> 9) | 0x3f800000u) - 1.0f;
        g_mask[idx] = (u < pv) ? 1.0f : 0.0f;
    }
}

// ---------------- attention phase 1: am = exp(score)*mask per row ----------------
__global__ __launch_bounds__(256) void scores_kernel() {
    __shared__ float qsh[KC * HH];   // [k][h], 32KB
    int tid = threadIdx.x;
    for (int i = tid; i < KC * HH; i += 256) qsh[i] = g_q[i];
    __syncthreads();
    int w = tid >> 5, lane = tid & 31;
    int row = blockIdx.x * 8 + w;
    const float* kp = g_kk + (size_t)row * HH;
    float acc[KC];
    #pragma unroll
    for (int k = 0; k < KC; k++) acc[k] = 0.f;
    #pragma unroll 4
    for (int i = 0; i < 16; i++) {
        int hh = i * 32 + lane;
        float kv = kp[hh];
        #pragma unroll
        for (int k = 0; k < KC; k++) acc[k] += kv * qsh[k * HH + hh];
    }
    #pragma unroll
    for (int k = 0; k < KC; k++) {
        #pragma unroll
        for (int o = 16; o > 0; o >>= 1)
            acc[k] += __shfl_xor_sync(0xffffffffu, acc[k], o);
    }
    if (lane < KC) {
        float am = expf(acc[lane] * 0.04419417382415922f) * g_mask[row * KC + lane];
        g_am[row * KC + lane] = am;
    }
}

// ---------------- attention phase 2: asum[b][k] = sum_c am ----------------
__global__ void asum_kernel() {
    int b = blockIdx.x;
    int k = threadIdx.x >> 5, lane = threadIdx.x & 31;
    float s = 0.f;
    for (int c = lane; c < CC; c += 32)
        s += g_am[((size_t)b * CC + c) * KC + k];
    #pragma unroll
    for (int o = 16; o > 0; o >>= 1) s += __shfl_down_sync(0xffffffffu, s, o);
    if (lane == 0) g_asum[b * KC + k] = s;
}

// ---------------- attention phase 3: Cc[b][k][h] = sum_c aw * V ----------------
__global__ __launch_bounds__(256) void vweight_kernel() {
    __shared__ float aw[KC * 514];
    __shared__ float inv_sh[KC];
    int b = blockIdx.x, h0 = blockIdx.y * 128;
    int tid = threadIdx.x;
    if (tid < KC) inv_sh[tid] = 1.0f / g_asum[b * KC + tid];
    __syncthreads();
    for (int idx = tid; idx < CC * KC; idx += 256) {
        int c = idx >> 4, k = idx & 15;
        aw[k * 514 + c] = g_am[((size_t)b * CC + c) * KC + k] * inv_sh[k];
    }
    __syncthreads();
    int kg = tid >> 6;
    int hg = tid & 63;
    const float* vp = g_v + (size_t)b * CC * HH + h0 + hg * 2;
    float a0[4], a1[4];
    #pragma unroll
    for (int k = 0; k < 4; k++) { a0[k] = 0.f; a1[k] = 0.f; }
    for (int c = 0; c < CC; c += 2) {
        float2 v0 = *(const float2*)(vp + (size_t)c * HH);
        float2 v1 = *(const float2*)(vp + (size_t)(c + 1) * HH);
        #pragma unroll
        for (int k = 0; k < 4; k++) {
            float2 a2 = *(const float2*)(&aw[(kg * 4 + k) * 514 + c]);
            a0[k] += a2.x * v0.x + a2.y * v1.x;
            a1[k] += a2.x * v0.y + a2.y * v1.y;
        }
    }
    #pragma unroll
    for (int k = 0; k < 4; k++) {
        size_t o = ((size_t)b * KC + kg * 4 + k) * HH + h0 + hg * 2;
        g_cc[o]     = a0[k];
        g_cc[o + 1] = a1[k];
    }
}

__global__ void ce_kernel() {
    int idx = blockIdx.x * 256 + threadIdx.x;
    float s = 0.f;
    for (int b = 0; b < BB; b++) s += g_cc[(size_t)b * KC * HH + idx];
    g_ce[idx] = s * (1.0f / BB);
}

// transpose per batch (h -> z) WITH fused LN-stats accumulation
__global__ void transpose_stats_kernel(const float* __restrict__ in, float* __restrict__ out) {
    __shared__ float sh[32][33];
    int b = blockIdx.z;
    int i0 = blockIdx.y * 32, j0 = blockIdx.x * 32;
    const float* ib = in + (size_t)b * CC * HH;
    float* ob = out + (size_t)b * CC * HH;
    #pragma unroll
    for (int r = 0; r < 32; r += 8)
        sh[threadIdx.y + r][threadIdx.x] = ib[(size_t)(i0 + threadIdx.y + r) * HH + j0 + threadIdx.x];
    __syncthreads();
    #pragma unroll
    for (int r = 0; r < 32; r += 8) {
        float v = sh[threadIdx.x][threadIdx.y + r];
        ob[(size_t)(j0 + threadIdx.y + r) * HH + i0 + threadIdx.x] = v;
        float s = v, q = v * v;
        #pragma unroll
        for (int o = 16; o > 0; o >>= 1) {
            s += __shfl_xor_sync(0xffffffffu, s, o);
            q += __shfl_xor_sync(0xffffffffu, q, o);
        }
        if (threadIdx.x == 0) {
            int row = b * HH + j0 + threadIdx.y + r;
            atomicAdd(&g_acc[row], s);
            atomicAdd(&g_acc2[row], q);
        }
    }
}

// prod[b,c,h] = z[b,h,c] * theta[b,c,h], theta computed on the fly from p & ce
__global__ void prod_kernel() {
    __shared__ float sh[32][33];
    __shared__ float cesh[KC][32];
    __shared__ float psh[32][KC + 1];
    int b = blockIdx.z;
    int h0 = blockIdx.y * 32, c0 = blockIdx.x * 32;
    const float* zb = g_z + (size_t)b * HH * CC;
    float* ob = g_prod + (size_t)b * CC * HH;
    int tid = threadIdx.y * 32 + threadIdx.x;
    #pragma unroll
    for (int r = 0; r < 32; r += 8)
        sh[threadIdx.y + r][threadIdx.x] = zb[(size_t)(h0 + threadIdx.y + r) * CC + c0 + threadIdx.x];
    for (int t = tid; t < KC * 32; t += 256) {
        int k = t >> 5, xx = t & 31;
        cesh[k][xx] = g_ce[k * HH + h0 + xx];
    }
    for (int t = tid; t < 32 * KC; t += 256) {
        int c = t >> 4, k = t & 15;
        psh[c][k] = g_p[((size_t)b * CC + c0 + c) * KC + k];
    }
    __syncthreads();
    #pragma unroll
    for (int r = 0; r < 32; r += 8) {
        int cl = threadIdx.y + r;
        float th = 0.f;
        #pragma unroll
        for (int k = 0; k < KC; k++) th += psh[cl][k] * cesh[k][threadIdx.x];
        size_t o = (size_t)(c0 + cl) * HH + h0 + threadIdx.x;
        ob[o] = sh[threadIdx.x][cl] * th;
    }
}

// final: y[b,p,c] = denorm( sum_h prod[b,c,h]*out_w[c,h,p] + out_b[c,p] )
__global__ void final_kernel(const float* __restrict__ out_w,
                             const float* __restrict__ out_b,
                             const float* __restrict__ rev_w,
                             const float* __restrict__ rev_b,
                             float* __restrict__ y) {
    int c = blockIdx.x;
    __shared__ float Ws[32][PP];
    __shared__ float As[32][33];
    int tid = threadIdx.x;
    int tb = tid >> 3;
    int tp = (tid & 7) * 12;
    float acc[12];
    #pragma unroll
    for (int j = 0; j < 12; j++) acc[j] = 0.f;

    for (int h0 = 0; h0 < HH; h0 += 32) {
        for (int t = tid; t < 32 * PP; t += 256) {
            int i = t / PP, pp = t % PP;
            Ws[i][pp] = out_w[((size_t)c * HH + h0 + i) * PP + pp];
        }
        for (int t = tid; t < 32 * 32; t += 256) {
            int b = t >> 5, i = t & 31;
            As[b][i] = g_prod[((size_t)b * CC + c) * HH + h0 + i];
        }
        __syncthreads();
        #pragma unroll
        for (int i = 0; i < 32; i++) {
            float a = As[tb][i];
            #pragma unroll
            for (int j = 0; j < 12; j++) acc[j] += a * Ws[i][tp + j];
        }
        __syncthreads();
    }
    float rb = rev_b[c];
    float rwinv = 1.0f / (rev_w[c] + 1e-10f);
    float sd = g_std[tb * CC + c];
    float mn = g_mean[tb * CC + c];
    #pragma unroll
    for (int j = 0; j < 12; j++) {
        float v = acc[j] + out_b[(size_t)c * PP + tp + j];
        v = (v - rb) * rwinv;
        v = v * sd + mn;
        y[((size_t)tb * PP + tp + j) * CC + c] = v;
    }
}

// ---------------- host orchestration ----------------
extern "C" void kernel_launch(void* const* d_in, const int* in_sizes, int n_in,
                              void* d_out, int out_size) {
    const float* x       = (const float*)d_in[0];
    const float* rev_w   = (const float*)d_in[1];
    const float* rev_b   = (const float*)d_in[2];
    const float* mlp_w1  = (const float*)d_in[3];
    const float* mlp_b1  = (const float*)d_in[4];
    const float* mlp_w2  = (const float*)d_in[5];
    const float* mlp_b2  = (const float*)d_in[6];
    const float* cle     = (const float*)d_in[7];
    const float* wq      = (const float*)d_in[8];
    const float* bq      = (const float*)d_in[9];
    const float* wk      = (const float*)d_in[10];
    const float* bk      = (const float*)d_in[11];
    const float* wv      = (const float*)d_in[12];
    const float* bv      = (const float*)d_in[13];
    const float* ts_ln_g = (const float*)d_in[14];
    const float* ts_ln_b = (const float*)d_in[15];
    const float* ts_w    = (const float*)d_in[16];
    const float* ts_b    = (const float*)d_in[17];
    const float* ch_ln_g = (const float*)d_in[18];
    const float* ch_ln_b = (const float*)d_in[19];
    const float* ch_w1   = (const float*)d_in[20];
    const float* ch_b1   = (const float*)d_in[21];
    const float* ch_w2   = (const float*)d_in[22];
    const float* ch_b2   = (const float*)d_in[23];
    const float* out_w   = (const float*)d_in[24];
    const float* out_b   = (const float*)d_in[25];
    float* y = (float*)d_out;

    float *p_xt, *p_t, *p_h, *p_kk, *p_v, *p_z, *p_z2, *p_w;
    cudaGetSymbolAddress((void**)&p_xt, g_xt);
    cudaGetSymbolAddress((void**)&p_t,  g_t);
    cudaGetSymbolAddress((void**)&p_h,  g_h);
    cudaGetSymbolAddress((void**)&p_kk, g_kk);
    cudaGetSymbolAddress((void**)&p_v,  g_v);
    cudaGetSymbolAddress((void**)&p_z,  g_z);
    cudaGetSymbolAddress((void**)&p_z2, g_z2);
    cudaGetSymbolAddress((void**)&p_w,  g_wts);

    const size_t WSZ = (size_t)GK * GN;
    float* w_mlp1 = p_w + 0 * WSZ;
    float* w_mlp2 = p_w + 1 * WSZ;
    float* w_k    = p_w + 2 * WSZ;
    float* w_v    = p_w + 3 * WSZ;
    float* w_ts   = p_w + 4 * WSZ;
    float* w_ch1  = p_w + 5 * WSZ;
    float* w_ch2  = p_w + 6 * WSZ;

    dim3 tgrid(16, 16, BB), tblk(32, 8);
    dim3 ggrid(GN / 128, ROWS / 128);
    dim3 ggrid2(GN / 128, ROWS / 128, 2);
    const int RWB = (int)(WSZ / 256);

    // 0) zero LN accumulators + pre-round all weights to tf32
    zacc_kernel<<<ROWS / 256, 256>>>();
    round_all_kernel<<<dim3(RWB, 7), 256>>>(mlp_w1, mlp_w2, wk, wv, ts_w, ch_w1, ch_w2);

    // 1) RevIN stats + normalized transpose
    revin_stats_kernel<<<dim3(CC / 256, BB), 256>>>(x);
    build_xt_kernel<<<tgrid, tblk>>>(x, rev_w, rev_b);

    // 2) channel MLP: h = relu(xt@w1+b1)@w2+b2
    gemm_tc<E_RELU, false, false><<<ggrid, 256>>>(p_xt, w_mlp1, mlp_b1, nullptr, p_t,
                                                  nullptr, nullptr, w_mlp1, mlp_b1, p_t);
    gemm_tc<E_BIAS, false, false><<<ggrid, 256>>>(p_t, w_mlp2, mlp_b2, nullptr, p_h,
                                                  nullptr, nullptr, w_mlp2, mlp_b2, p_h);

    // 3) routing (p + threefry bernoulli mask)
    cn_kernel<<<KC, 256>>>(cle);
    q_kernel<<<KC, 256>>>(cle, wq, bq);
    routing_kernel<<<ROWS / 8, 256>>>(p_h);

    // 4) K/V projections (ONE launch, grid.z selects) + attention + ce_new
    gemm_tc<E_BIAS, false, false><<<ggrid2, 256>>>(p_h, w_k, bk, nullptr, p_kk,
                                                   nullptr, nullptr, w_v, bv, p_v);
    scores_kernel<<<ROWS / 8, 256>>>();
    asum_kernel<<<BB, 512>>>();
    vweight_kernel<<<dim3(BB, HH / 128), 256>>>();
    ce_kernel<<<KC * HH / 256, 256>>>();

    // 5) mixer: state in [B,H,C] layout; LN fused into GEMM A-path,
    //    LN stats fused into producer epilogues
    transpose_stats_kernel<<<tgrid, tblk>>>(p_h, p_z);
    for (int it = 0; it < NBITER; it++) {
        lnfin_kernel<<<ROWS / 256, 256>>>();                        // stats(z)
        gemm_tc<E_RESGELU, true, true><<<ggrid, 256>>>(p_z, w_ts, ts_b, p_z, p_z2,
                                                       ts_ln_g, ts_ln_b, w_ts, ts_b, p_z2);
        lnfin_kernel<<<ROWS / 256, 256>>>();                        // stats(z2)
        gemm_tc<E_GELU, true, false><<<ggrid, 256>>>(p_z2, w_ch1, ch_b1, nullptr, p_t,
                                                     ch_ln_g, ch_ln_b, w_ch1, ch_b1, p_t);
        if (it < NBITER - 1)
            gemm_tc<E_RESBIAS, false, true><<<ggrid, 256>>>(p_t, w_ch2, ch_b2, p_z2, p_z,
                                                            nullptr, nullptr, w_ch2, ch_b2, p_z);
        else
            gemm_tc<E_RESBIAS, false, false><<<ggrid, 256>>>(p_t, w_ch2, ch_b2, p_z2, p_z,
                                                             nullptr, nullptr, w_ch2, ch_b2, p_z);
    }

    // 6) expert projection (theta fused) + RevIN denorm
    prod_kernel<<<tgrid, tblk>>>();
    final_kernel<<<CC, 256>>>(out_w, out_b, rev_w, rev_b, y);
}

// round 10
// speedup vs baseline: 1.2270x; 1.0147x over previous
#include <cuda_runtime.h>
#include <math.h>
#include <stdint.h>

// ---------------- problem constants ----------------
#define BB 32
#define LL 512
#define CC 512
#define HH 512
#define KC 16          // clusters
#define PP 96
#define NBITER 4
#define ROWS (BB*CC)   // 16384
#define EPSV 1e-5f
#define GN 512         // GEMM N (all GEMMs are 16384x512x512)
#define GK 512         // GEMM K

// ---------------- scratch (static device globals; no allocation) ----------------
__device__ float g_xt   [(size_t)ROWS*HH];
__device__ float g_t    [(size_t)ROWS*HH];
__device__ float g_h    [(size_t)ROWS*HH];
__device__ float g_kk   [(size_t)ROWS*HH];
__device__ float g_v    [(size_t)ROWS*HH];
__device__ float g_z    [(size_t)ROWS*HH];
__device__ float g_z2   [(size_t)ROWS*HH];
__device__ float g_prod [(size_t)ROWS*HH];
__device__ float g_wts  [(size_t)7*GK*GN];    // tf32-rounded weights
__device__ float g_mean [ROWS];
__device__ float g_std  [ROWS];
__device__ float g_rm   [ROWS];   // per-row LN mean
__device__ float g_rs   [ROWS];   // per-row LN rstd
__device__ float g_acc  [ROWS];   // LN sum accumulator
__device__ float g_acc2 [ROWS];   // LN sumsq accumulator
__device__ float g_cn   [KC*HH];
__device__ float g_q    [KC*HH];
__device__ float g_p    [ROWS*KC];
__device__ float g_mask [ROWS*KC];
__device__ float g_am   [ROWS*KC];
__device__ float g_asum [BB*KC];
__device__ float g_cc   [BB*KC*HH];
__device__ float g_ce   [KC*HH];

// ---------------- helpers ----------------
__device__ __forceinline__ float gelu_f(float x) {
    return 0.5f * x * (1.0f + erff(x * 0.7071067811865476f));
}

__device__ __forceinline__ float f2tf32(float x) {
    uint32_t r;
    asm("cvt.rna.tf32.f32 %0, %1;" : "=r"(r) : "f"(x));
    return __uint_as_float(r);
}

__device__ __forceinline__ void cp16(uint32_t dst_smem, const void* src) {
    asm volatile("cp.async.ca.shared.global [%0], [%1], 16;"
                 :: "r"(dst_smem), "l"(src) : "memory");
}
__device__ __forceinline__ void cp_commit() {
    asm volatile("cp.async.commit_group;" ::: "memory");
}
template<int N>
__device__ __forceinline__ void cp_waitg() {
    asm volatile("cp.async.wait_group %0;" :: "n"(N) : "memory");
}

__device__ __forceinline__ uint32_t rotl32(uint32_t x, uint32_t d) {
    return (x << d) | (x >> (32u - d));
}

// JAX threefry2x32, PARTITIONABLE path. key = {0,42}; counter (0, idx);
// output word = out0 ^ out1.
__device__ uint32_t threefry_rand(uint32_t idx) {
    uint32_t x0 = 0u, x1 = idx;
    const uint32_t k0 = 0u, k1 = 42u;
    const uint32_t k2 = k0 ^ k1 ^ 0x1BD11BDAu;
    uint32_t ks[3] = {k0, k1, k2};
    x0 += ks[0]; x1 += ks[1];
    const uint32_t R[2][4] = {{13u,15u,26u,6u},{17u,29u,16u,24u}};
    #pragma unroll
    for (int i = 0; i < 5; i++) {
        #pragma unroll
        for (int j = 0; j < 4; j++) {
            x0 += x1; x1 = rotl32(x1, R[i & 1][j]); x1 ^= x0;
        }
        x0 += ks[(i + 1) % 3];
        x1 += ks[(i + 2) % 3] + (uint32_t)(i + 1);
    }
    return x0 ^ x1;
}

// ---------------- zero LN accumulators (once) ----------------
__global__ void zacc_kernel() {
    int i = blockIdx.x * 256 + threadIdx.x;
    g_acc[i] = 0.f;
    g_acc2[i] = 0.f;
}

// ---------------- weight pre-round: all 7 matrices in one launch ----------------
__global__ void round_all_kernel(const float* s0, const float* s1, const float* s2,
                                 const float* s3, const float* s4, const float* s5,
                                 const float* s6) {
    int i = blockIdx.x * 256 + threadIdx.x;
    const float* s;
    switch (blockIdx.y) {
        case 0: s = s0; break; case 1: s = s1; break; case 2: s = s2; break;
        case 3: s = s3; break; case 4: s = s4; break; case 5: s = s5; break;
        default: s = s6; break;
    }
    g_wts[(size_t)blockIdx.y * GK * GN + i] = f2tf32(s[i]);
}

// ---------------- RevIN stats ----------------
__global__ void revin_stats_kernel(const float* __restrict__ x) {
    int b = blockIdx.y;
    int c = blockIdx.x * 256 + threadIdx.x;
    float s = 0.f, s2 = 0.f;
    const float* xp = x + (size_t)b * LL * CC + c;
    for (int l = 0; l < LL; l++) {
        float v = xp[(size_t)l * CC];
        s += v; s2 += v * v;
    }
    float m = s * (1.0f / LL);
    float var = fmaxf(s2 * (1.0f / LL) - m * m, 0.0f);
    g_mean[b * CC + c] = m;
    g_std [b * CC + c] = sqrtf(var + EPSV);
}

// xt[b,c,l] = (x[b,l,c]-mean)/std*rev_w[c]+rev_b[c]   (tiled transpose)
__global__ void build_xt_kernel(const float* __restrict__ x,
                                const float* __restrict__ rev_w,
                                const float* __restrict__ rev_b) {
    __shared__ float sh[32][33];
    int b = blockIdx.z;
    int l0 = blockIdx.x * 32, c0 = blockIdx.y * 32;
    const float* xb = x + (size_t)b * LL * CC;
    float* ob = g_xt + (size_t)b * CC * LL;
    #pragma unroll
    for (int r = 0; r < 32; r += 8)
        sh[threadIdx.y + r][threadIdx.x] = xb[(size_t)(l0 + threadIdx.y + r) * CC + c0 + threadIdx.x];
    __syncthreads();
    #pragma unroll
    for (int r = 0; r < 32; r += 8) {
        int c = c0 + threadIdx.y + r;
        float mn = g_mean[b * CC + c];
        float sd = g_std[b * CC + c];
        float v = sh[threadIdx.x][threadIdx.y + r];
        ob[(size_t)c * LL + l0 + threadIdx.x] = (v - mn) / sd * rev_w[c] + rev_b[c];
    }
}

// ---------------- LN stats finalize: (sum,sumsq) -> (mean,rstd), reset acc ----
__global__ void lnfin_kernel() {
    int i = blockIdx.x * 256 + threadIdx.x;
    float s = g_acc[i], s2 = g_acc2[i];
    float m = s * (1.0f / CC);
    float var = fmaxf(s2 * (1.0f / CC) - m * m, 0.0f);
    g_rm[i] = m;
    g_rs[i] = rsqrtf(var + EPSV);
    g_acc[i] = 0.f;
    g_acc2[i] = 0.f;
}

// ---------------- TF32 tensor-core GEMM, K-tile 16, 3-stage cp.async B ----
// C[M,512] = A'[M,512] @ W[512,512] (+bias, +epilogue), A' = A or LayerNorm(A).
// W must be tf32-pre-rounded. A is truncated to tf32 by the MMA itself.
// Dual-output: blockIdx.z selects (W,bias,out) vs (W2,bias2,out2).
#define E_RELU    0
#define E_BIAS    1
#define E_GELU    2
#define E_RESGELU 3
#define E_RESBIAS 4

#define ASZ (128*16)   // A buffer floats
#define BSZ (16*132)   // B buffer floats

__device__ __forceinline__ void mma_tf32(float c[4],
                                         uint32_t a0, uint32_t a1, uint32_t a2, uint32_t a3,
                                         uint32_t b0, uint32_t b1) {
    asm volatile(
        "mma.sync.aligned.m16n8k8.row.col.f32.tf32.tf32.f32 "
        "{%0,%1,%2,%3}, {%4,%5,%6,%7}, {%8,%9}, {%0,%1,%2,%3};"
        : "+f"(c[0]), "+f"(c[1]), "+f"(c[2]), "+f"(c[3])
        : "r"(a0), "r"(a1), "r"(a2), "r"(a3), "r"(b0), "r"(b1));
}

// A smem layout: As[m][16], element (m,k) at word m*16 + ((k&3)^((m>>1)&3))*4 + (k>>2)
// B smem layout: Bs[k][132] (k-major rows, +4 pad), filled by cp.async (3 stages).
template<int EPI, bool LNA, bool STATS>
__global__ __launch_bounds__(256, 2) void gemm_tc(
    const float* __restrict__ A, const float* __restrict__ W,
    const float* __restrict__ bias, const float* __restrict__ res,
    float* __restrict__ out,
    const float* __restrict__ ln_g, const float* __restrict__ ln_b,
    const float* __restrict__ W2, const float* __restrict__ bias2,
    float* __restrict__ out2) {
    __shared__ float As[2 * ASZ];
    __shared__ float Bs[3 * BSZ];
    if (blockIdx.z) { W = W2; bias = bias2; out = out2; }
    const int tid = threadIdx.x;
    const int warp = tid >> 5, lane = tid & 31;
    const int wm = (warp >> 2) * 64;    // warp M offset: 0 or 64
    const int wn = (warp & 3) * 32;     // warp N offset: 0,32,64,96
    const int gid = lane >> 2;          // 0..7
    const int tig = lane & 3;           // 0..3
    const int bx = blockIdx.x, by = blockIdx.y;

    const int arow = tid >> 1;          // 0..127
    const int ak   = (tid & 1) * 8;     // 0 or 8
    const int ssw  = (arow >> 1) & 3;   // store swizzle
    const int brow = tid >> 5;          // 0..7
    const int bn   = lane * 4;          // 0..124

    float acc[4][4][4];
    #pragma unroll
    for (int i = 0; i < 4; i++)
        #pragma unroll
        for (int j = 0; j < 4; j++)
            #pragma unroll
            for (int r = 0; r < 4; r++) acc[i][j][r] = 0.f;

    const float* Ap  = A + (size_t)(by * 128 + arow) * GK + ak;
    const float* Wp0 = W + (size_t)brow * GN + bx * 128 + bn;

    const uint32_t bdst = (uint32_t)__cvta_generic_to_shared(Bs + brow * 132 + bn);

    float mu = 0.f, rsd = 1.f;
    if (LNA) {
        mu  = g_rm[by * 128 + arow];
        rsd = g_rs[by * 128 + arow];
    }

    const int NT = GK >> 4;

    auto issueB = [&](int buf, int kt) {
        const float* ws = Wp0 + (size_t)kt * 16 * GN;
        uint32_t d = bdst + (uint32_t)buf * (BSZ * 4);
        cp16(d, ws);
        cp16(d + 8 * 132 * 4, ws + (size_t)8 * GN);
        cp_commit();
    };

    float4 pa0, pa1;
    auto loadA = [&](int kt) {
        pa0 = *(const float4*)(Ap + kt * 16);
        pa1 = *(const float4*)(Ap + kt * 16 + 4);
    };

    auto store_tileA = [&](int buf, int kt) {
        float va[8] = {pa0.x, pa0.y, pa0.z, pa0.w, pa1.x, pa1.y, pa1.z, pa1.w};
        if (LNA) {
            const float* gp = ln_g + kt * 16 + ak;
            const float* bp = ln_b + kt * 16 + ak;
            #pragma unroll
            for (int j = 0; j < 8; j++) {
                float t = rsd * gp[j];
                va[j] = (va[j] - mu) * t + bp[j];
            }
        }
        float* Ab = As + buf * ASZ;
        const int abase = arow * 16 + (ak >> 2);
        #pragma unroll
        for (int j = 0; j < 4; j++) {
            *(float2*)(Ab + abase + ((j ^ ssw) << 2)) = make_float2(va[j], va[j + 4]);
        }
    };

    auto compute = [&](int abuf, int bbuf) {
        const float* Ab = As + abuf * ASZ;
        const float* Bb = Bs + bbuf * BSZ;
        #pragma unroll
        for (int ks = 0; ks < 2; ks++) {
            float2 fa0[4], fa1[4];
            #pragma unroll
            for (int i = 0; i < 4; i++) {
                int m0 = wm + i * 16 + gid;
                int sw = (m0 >> 1) & 3;
                int w = m0 * 16 + ((tig ^ sw) << 2) + ks * 2;
                fa0[i] = *(const float2*)(Ab + w);
                fa1[i] = *(const float2*)(Ab + w + 128);   // row m0+8: same swizzle
            }
            float fb0[4], fb1[4];
            #pragma unroll
            for (int j = 0; j < 4; j++) {
                int n0 = wn + j * 8 + gid;
                fb0[j] = Bb[(ks * 8 + tig) * 132 + n0];
                fb1[j] = Bb[(ks * 8 + tig + 4) * 132 + n0];
            }
            #pragma unroll
            for (int i = 0; i < 4; i++)
                #pragma unroll
                for (int j = 0; j < 4; j++)
                    mma_tf32(acc[i][j],
                             __float_as_uint(fa0[i].x), __float_as_uint(fa1[i].x),
                             __float_as_uint(fa0[i].y), __float_as_uint(fa1[i].y),
                             __float_as_uint(fb0[j]), __float_as_uint(fb1[j]));
        }
    };

    // prologue: B0 and B1 in flight, A0 staged, A1 in registers
    issueB(0, 0);
    issueB(1, 1);
    loadA(0);
    store_tileA(0, 0);
    loadA(1);
    cp_waitg<1>();          // B0 complete (B1 may be outstanding)
    __syncthreads();

    int bcur = 0;
    for (int kt = 0; kt < NT; kt++) {
        const int acur = kt & 1;
        int bn2 = bcur + 2; if (bn2 >= 3) bn2 -= 3;
        if (kt + 2 < NT) issueB(bn2, kt + 2);
        compute(acur, bcur);
        if (kt + 1 < NT) {
            store_tileA(acur ^ 1, kt + 1);
            if (kt + 2 < NT) loadA(kt + 2);
        }
        // need B_{kt+1} at the barrier; B_{kt+2} may remain outstanding
        if (kt + 2 < NT) cp_waitg<1>(); else cp_waitg<0>();
        __syncthreads();
        bcur++; if (bcur >= 3) bcur -= 3;
    }

    // epilogue (+ optional fused LN-stats accumulation of the OUTPUT rows)
    #pragma unroll
    for (int i = 0; i < 4; i++) {
        int gr0 = by * 128 + wm + i * 16 + gid;
        int gr1 = gr0 + 8;
        float slo = 0.f, qlo = 0.f, shi = 0.f, qhi = 0.f;
        #pragma unroll
        for (int j = 0; j < 4; j++) {
            int gc = bx * 128 + wn + j * 8 + 2 * tig;
            float b0v = bias[gc], b1v = bias[gc + 1];
            float v0 = acc[i][j][0] + b0v, v1 = acc[i][j][1] + b1v;
            float v2 = acc[i][j][2] + b0v, v3 = acc[i][j][3] + b1v;
            if (EPI == E_RELU) {
                v0 = fmaxf(v0, 0.f); v1 = fmaxf(v1, 0.f);
                v2 = fmaxf(v2, 0.f); v3 = fmaxf(v3, 0.f);
            } else if (EPI == E_GELU) {
                v0 = gelu_f(v0); v1 = gelu_f(v1);
                v2 = gelu_f(v2); v3 = gelu_f(v3);
            } else if (EPI == E_RESGELU) {
                const float2 r0 = *(const float2*)(res + (size_t)gr0 * GN + gc);
                const float2 r1 = *(const float2*)(res + (size_t)gr1 * GN + gc);
                v0 = r0.x + gelu_f(v0); v1 = r0.y + gelu_f(v1);
                v2 = r1.x + gelu_f(v2); v3 = r1.y + gelu_f(v3);
            } else if (EPI == E_RESBIAS) {
                const float2 r0 = *(const float2*)(res + (size_t)gr0 * GN + gc);
                const float2 r1 = *(const float2*)(res + (size_t)gr1 * GN + gc);
                v0 += r0.x; v1 += r0.y; v2 += r1.x; v3 += r1.y;
            }
            if (STATS) {
                slo += v0 + v1; qlo += v0 * v0 + v1 * v1;
                shi += v2 + v3; qhi += v2 * v2 + v3 * v3;
            }
            *(float2*)(out + (size_t)gr0 * GN + gc) = make_float2(v0, v1);
            *(float2*)(out + (size_t)gr1 * GN + gc) = make_float2(v2, v3);
        }
        if (STATS) {
            slo += __shfl_xor_sync(0xffffffffu, slo, 1);
            slo += __shfl_xor_sync(0xffffffffu, slo, 2);
            qlo += __shfl_xor_sync(0xffffffffu, qlo, 1);
            qlo += __shfl_xor_sync(0xffffffffu, qlo, 2);
            shi += __shfl_xor_sync(0xffffffffu, shi, 1);
            shi += __shfl_xor_sync(0xffffffffu, shi, 2);
            qhi += __shfl_xor_sync(0xffffffffu, qhi, 1);
            qhi += __shfl_xor_sync(0xffffffffu, qhi, 2);
            if (tig == 0) {
                atomicAdd(&g_acc[gr0], slo);
                atomicAdd(&g_acc2[gr0], qlo);
                atomicAdd(&g_acc[gr1], shi);
                atomicAdd(&g_acc2[gr1], qhi);
            }
        }
    }
}

// ---------------- cluster normalize (cn) ----------------
__global__ void cn_kernel(const float* __restrict__ ce) {
    __shared__ float red[256];
    int k = blockIdx.x, tid = threadIdx.x;
    float v0 = ce[k * HH + tid], v1 = ce[k * HH + tid + 256];
    red[tid] = v0 * v0 + v1 * v1;
    __syncthreads();
    for (int off = 128; off > 0; off >>= 1) {
        if (tid < off) red[tid] += red[tid + off];
        __syncthreads();
    }
    float nrm = fmaxf(sqrtf(red[0]), 1e-12f);
    g_cn[k * HH + tid] = v0 / nrm;
    g_cn[k * HH + tid + 256] = v1 / nrm;
}

// ---------------- Q = cluster_embeds @ wq + bq ----------------
__global__ void q_kernel(const float* __restrict__ ce,
                         const float* __restrict__ wq,
                         const float* __restrict__ bq) {
    __shared__ float csh[HH];
    int k = blockIdx.x, tid = threadIdx.x;
    csh[tid] = ce[k * HH + tid];
    csh[tid + 256] = ce[k * HH + tid + 256];
    __syncthreads();
    for (int n = tid; n < HH; n += 256) {
        float a = bq[n];
        for (int h = 0; h < HH; h++) a += csh[h] * wq[(size_t)h * HH + n];
        g_q[k * HH + n] = a;
    }
}

// ---------------- routing: warp per row; p = softmax(hn @ cn^T), bernoulli mask
__global__ __launch_bounds__(256) void routing_kernel(const float* __restrict__ h) {
    __shared__ float cnsh[KC * HH];   // 32KB
    int tid = threadIdx.x;
    for (int i = tid; i < KC * HH; i += 256) cnsh[i] = g_cn[i];
    __syncthreads();
    int w = tid >> 5, lane = tid & 31;
    int row = blockIdx.x * 8 + w;
    const float* hp = h + (size_t)row * HH;
    float acc[KC];
    #pragma unroll
    for (int k = 0; k < KC; k++) acc[k] = 0.f;
    float nsq = 0.f;
    #pragma unroll 4
    for (int i = 0; i < 16; i++) {
        int hh = i * 32 + lane;
        float hv = hp[hh];
        nsq += hv * hv;
        #pragma unroll
        for (int k = 0; k < KC; k++) acc[k] += hv * cnsh[k * HH + hh];
    }
    #pragma unroll
    for (int o = 16; o > 0; o >>= 1) nsq += __shfl_xor_sync(0xffffffffu, nsq, o);
    #pragma unroll
    for (int k = 0; k < KC; k++) {
        #pragma unroll
        for (int o = 16; o > 0; o >>= 1)
            acc[k] += __shfl_xor_sync(0xffffffffu, acc[k], o);
    }
    float inv = 1.0f / fmaxf(sqrtf(nsq), 1e-12f);
    float d = 0.f;
    #pragma unroll
    for (int k = 0; k < KC; k++) if (lane == k) d = acc[k];
    d *= inv;
    float mx = d;
    #pragma unroll
    for (int o = 8; o > 0; o >>= 1)
        mx = fmaxf(mx, __shfl_xor_sync(0xffffffffu, mx, o, 16));
    float e = expf(d - mx);
    float tot = e;
    #pragma unroll
    for (int o = 8; o > 0; o >>= 1)
        tot += __shfl_xor_sync(0xffffffffu, tot, o, 16);
    if (lane < KC) {
        float pv = e / tot;
        int idx = row * KC + lane;
        g_p[idx] = pv;
        uint32_t bits = threefry_rand((uint32_t)idx);
        float u = __uint_as_float((bits >> 9) | 0x3f800000u) - 1.0f;
        g_mask[idx] = (u < pv) ? 1.0f : 0.0f;
    }
}

// ---------------- attention phase 1: am = exp(score)*mask per row ----------------
__global__ __launch_bounds__(256) void scores_kernel() {
    __shared__ float qsh[KC * HH];   // [k][h], 32KB
    int tid = threadIdx.x;
    for (int i = tid; i < KC * HH; i += 256) qsh[i] = g_q[i];
    __syncthreads();
    int w = tid >> 5, lane = tid & 31;
    int row = blockIdx.x * 8 + w;
    const float* kp = g_kk + (size_t)row * HH;
    float acc[KC];
    #pragma unroll
    for (int k = 0; k < KC; k++) acc[k] = 0.f;
    #pragma unroll 4
    for (int i = 0; i < 16; i++) {
        int hh = i * 32 + lane;
        float kv = kp[hh];
        #pragma unroll
        for (int k = 0; k < KC; k++) acc[k] += kv * qsh[k * HH + hh];
    }
    #pragma unroll
    for (int k = 0; k < KC; k++) {
        #pragma unroll
        for (int o = 16; o > 0; o >>= 1)
            acc[k] += __shfl_xor_sync(0xffffffffu, acc[k], o);
    }
    if (lane < KC) {
        float am = expf(acc[lane] * 0.04419417382415922f) * g_mask[row * KC + lane];
        g_am[row * KC + lane] = am;
    }
}

// ---------------- attention phase 2: asum[b][k] = sum_c am ----------------
__global__ void asum_kernel() {
    int b = blockIdx.x;
    int k = threadIdx.x >> 5, lane = threadIdx.x & 31;
    float s = 0.f;
    for (int c = lane; c < CC; c += 32)
        s += g_am[((size_t)b * CC + c) * KC + k];
    #pragma unroll
    for (int o = 16; o > 0; o >>= 1) s += __shfl_down_sync(0xffffffffu, s, o);
    if (lane == 0) g_asum[b * KC + k] = s;
}

// ---------------- attention phase 3: Cc[b][k][h] = sum_c aw * V ----------------
__global__ __launch_bounds__(256) void vweight_kernel() {
    __shared__ float aw[KC * 514];
    __shared__ float inv_sh[KC];
    int b = blockIdx.x, h0 = blockIdx.y * 128;
    int tid = threadIdx.x;
    if (tid < KC) inv_sh[tid] = 1.0f / g_asum[b * KC + tid];
    __syncthreads();
    for (int idx = tid; idx < CC * KC; idx += 256) {
        int c = idx >> 4, k = idx & 15;
        aw[k * 514 + c] = g_am[((size_t)b * CC + c) * KC + k] * inv_sh[k];
    }
    __syncthreads();
    int kg = tid >> 6;
    int hg = tid & 63;
    const float* vp = g_v + (size_t)b * CC * HH + h0 + hg * 2;
    float a0[4], a1[4];
    #pragma unroll
    for (int k = 0; k < 4; k++) { a0[k] = 0.f; a1[k] = 0.f; }
    for (int c = 0; c < CC; c += 2) {
        float2 v0 = *(const float2*)(vp + (size_t)c * HH);
        float2 v1 = *(const float2*)(vp + (size_t)(c + 1) * HH);
        #pragma unroll
        for (int k = 0; k < 4; k++) {
            float2 a2 = *(const float2*)(&aw[(kg * 4 + k) * 514 + c]);
            a0[k] += a2.x * v0.x + a2.y * v1.x;
            a1[k] += a2.x * v0.y + a2.y * v1.y;
        }
    }
    #pragma unroll
    for (int k = 0; k < 4; k++) {
        size_t o = ((size_t)b * KC + kg * 4 + k) * HH + h0 + hg * 2;
        g_cc[o]     = a0[k];
        g_cc[o + 1] = a1[k];
    }
}

__global__ void ce_kernel() {
    int idx = blockIdx.x * 256 + threadIdx.x;
    float s = 0.f;
    for (int b = 0; b < BB; b++) s += g_cc[(size_t)b * KC * HH + idx];
    g_ce[idx] = s * (1.0f / BB);
}

// transpose per batch (h -> z) WITH fused LN-stats accumulation
__global__ void transpose_stats_kernel(const float* __restrict__ in, float* __restrict__ out) {
    __shared__ float sh[32][33];
    int b = blockIdx.z;
    int i0 = blockIdx.y * 32, j0 = blockIdx.x * 32;
    const float* ib = in + (size_t)b * CC * HH;
    float* ob = out + (size_t)b * CC * HH;
    #pragma unroll
    for (int r = 0; r < 32; r += 8)
        sh[threadIdx.y + r][threadIdx.x] = ib[(size_t)(i0 + threadIdx.y + r) * HH + j0 + threadIdx.x];
    __syncthreads();
    #pragma unroll
    for (int r = 0; r < 32; r += 8) {
        float v = sh[threadIdx.x][threadIdx.y + r];
        ob[(size_t)(j0 + threadIdx.y + r) * HH + i0 + threadIdx.x] = v;
        float s = v, q = v * v;
        #pragma unroll
        for (int o = 16; o > 0; o >>= 1) {
            s += __shfl_xor_sync(0xffffffffu, s, o);
            q += __shfl_xor_sync(0xffffffffu, q, o);
        }
        if (threadIdx.x == 0) {
            int row = b * HH + j0 + threadIdx.y + r;
            atomicAdd(&g_acc[row], s);
            atomicAdd(&g_acc2[row], q);
        }
    }
}

// prod[b,c,h] = z[b,h,c] * theta[b,c,h], theta computed on the fly from p & ce
__global__ void prod_kernel() {
    __shared__ float sh[32][33];
    __shared__ float cesh[KC][32];
    __shared__ float psh[32][KC + 1];
    int b = blockIdx.z;
    int h0 = blockIdx.y * 32, c0 = blockIdx.x * 32;
    const float* zb = g_z + (size_t)b * HH * CC;
    float* ob = g_prod + (size_t)b * CC * HH;
    int tid = threadIdx.y * 32 + threadIdx.x;
    #pragma unroll
    for (int r = 0; r < 32; r += 8)
        sh[threadIdx.y + r][threadIdx.x] = zb[(size_t)(h0 + threadIdx.y + r) * CC + c0 + threadIdx.x];
    for (int t = tid; t < KC * 32; t += 256) {
        int k = t >> 5, xx = t & 31;
        cesh[k][xx] = g_ce[k * HH + h0 + xx];
    }
    for (int t = tid; t < 32 * KC; t += 256) {
        int c = t >> 4, k = t & 15;
        psh[c][k] = g_p[((size_t)b * CC + c0 + c) * KC + k];
    }
    __syncthreads();
    #pragma unroll
    for (int r = 0; r < 32; r += 8) {
        int cl = threadIdx.y + r;
        float th = 0.f;
        #pragma unroll
        for (int k = 0; k < KC; k++) th += psh[cl][k] * cesh[k][threadIdx.x];
        size_t o = (size_t)(c0 + cl) * HH + h0 + threadIdx.x;
        ob[o] = sh[threadIdx.x][cl] * th;
    }
}

// final: y[b,p,c] = denorm( sum_h prod[b,c,h]*out_w[c,h,p] + out_b[c,p] )
__global__ void final_kernel(const float* __restrict__ out_w,
                             const float* __restrict__ out_b,
                             const float* __restrict__ rev_w,
                             const float* __restrict__ rev_b,
                             float* __restrict__ y) {
    int c = blockIdx.x;
    __shared__ float Ws[32][PP];
    __shared__ float As[32][33];
    int tid = threadIdx.x;
    int tb = tid >> 3;
    int tp = (tid & 7) * 12;
    float acc[12];
    #pragma unroll
    for (int j = 0; j < 12; j++) acc[j] = 0.f;

    for (int h0 = 0; h0 < HH; h0 += 32) {
        for (int t = tid; t < 32 * PP; t += 256) {
            int i = t / PP, pp = t % PP;
            Ws[i][pp] = out_w[((size_t)c * HH + h0 + i) * PP + pp];
        }
        for (int t = tid; t < 32 * 32; t += 256) {
            int b = t >> 5, i = t & 31;
            As[b][i] = g_prod[((size_t)b * CC + c) * HH + h0 + i];
        }
        __syncthreads();
        #pragma unroll
        for (int i = 0; i < 32; i++) {
            float a = As[tb][i];
            #pragma unroll
            for (int j = 0; j < 12; j++) acc[j] += a * Ws[i][tp + j];
        }
        __syncthreads();
    }
    float rb = rev_b[c];
    float rwinv = 1.0f / (rev_w[c] + 1e-10f);
    float sd = g_std[tb * CC + c];
    float mn = g_mean[tb * CC + c];
    #pragma unroll
    for (int j = 0; j < 12; j++) {
        float v = acc[j] + out_b[(size_t)c * PP + tp + j];
        v = (v - rb) * rwinv;
        v = v * sd + mn;
        y[((size_t)tb * PP + tp + j) * CC + c] = v;
    }
}

// ---------------- host orchestration ----------------
extern "C" void kernel_launch(void* const* d_in, const int* in_sizes, int n_in,
                              void* d_out, int out_size) {
    const float* x       = (const float*)d_in[0];
    const float* rev_w   = (const float*)d_in[1];
    const float* rev_b   = (const float*)d_in[2];
    const float* mlp_w1  = (const float*)d_in[3];
    const float* mlp_b1  = (const float*)d_in[4];
    const float* mlp_w2  = (const float*)d_in[5];
    const float* mlp_b2  = (const float*)d_in[6];
    const float* cle     = (const float*)d_in[7];
    const float* wq      = (const float*)d_in[8];
    const float* bq      = (const float*)d_in[9];
    const float* wk      = (const float*)d_in[10];
    const float* bk      = (const float*)d_in[11];
    const float* wv      = (const float*)d_in[12];
    const float* bv      = (const float*)d_in[13];
    const float* ts_ln_g = (const float*)d_in[14];
    const float* ts_ln_b = (const float*)d_in[15];
    const float* ts_w    = (const float*)d_in[16];
    const float* ts_b    = (const float*)d_in[17];
    const float* ch_ln_g = (const float*)d_in[18];
    const float* ch_ln_b = (const float*)d_in[19];
    const float* ch_w1   = (const float*)d_in[20];
    const float* ch_b1   = (const float*)d_in[21];
    const float* ch_w2   = (const float*)d_in[22];
    const float* ch_b2   = (const float*)d_in[23];
    const float* out_w   = (const float*)d_in[24];
    const float* out_b   = (const float*)d_in[25];
    float* y = (float*)d_out;

    float *p_xt, *p_t, *p_h, *p_kk, *p_v, *p_z, *p_z2, *p_w;
    cudaGetSymbolAddress((void**)&p_xt, g_xt);
    cudaGetSymbolAddress((void**)&p_t,  g_t);
    cudaGetSymbolAddress((void**)&p_h,  g_h);
    cudaGetSymbolAddress((void**)&p_kk, g_kk);
    cudaGetSymbolAddress((void**)&p_v,  g_v);
    cudaGetSymbolAddress((void**)&p_z,  g_z);
    cudaGetSymbolAddress((void**)&p_z2, g_z2);
    cudaGetSymbolAddress((void**)&p_w,  g_wts);

    const size_t WSZ = (size_t)GK * GN;
    float* w_mlp1 = p_w + 0 * WSZ;
    float* w_mlp2 = p_w + 1 * WSZ;
    float* w_k    = p_w + 2 * WSZ;
    float* w_v    = p_w + 3 * WSZ;
    float* w_ts   = p_w + 4 * WSZ;
    float* w_ch1  = p_w + 5 * WSZ;
    float* w_ch2  = p_w + 6 * WSZ;

    dim3 tgrid(16, 16, BB), tblk(32, 8);
    dim3 ggrid(GN / 128, ROWS / 128);
    dim3 ggrid2(GN / 128, ROWS / 128, 2);
    const int RWB = (int)(WSZ / 256);

    // 0) zero LN accumulators + pre-round all weights to tf32
    zacc_kernel<<<ROWS / 256, 256>>>();
    round_all_kernel<<<dim3(RWB, 7), 256>>>(mlp_w1, mlp_w2, wk, wv, ts_w, ch_w1, ch_w2);

    // 1) RevIN stats + normalized transpose
    revin_stats_kernel<<<dim3(CC / 256, BB), 256>>>(x);
    build_xt_kernel<<<tgrid, tblk>>>(x, rev_w, rev_b);

    // 2) channel MLP: h = relu(xt@w1+b1)@w2+b2
    gemm_tc<E_RELU, false, false><<<ggrid, 256>>>(p_xt, w_mlp1, mlp_b1, nullptr, p_t,
                                                  nullptr, nullptr, w_mlp1, mlp_b1, p_t);
    gemm_tc<E_BIAS, false, false><<<ggrid, 256>>>(p_t, w_mlp2, mlp_b2, nullptr, p_h,
                                                  nullptr, nullptr, w_mlp2, mlp_b2, p_h);

    // 3) routing (p + threefry bernoulli mask)
    cn_kernel<<<KC, 256>>>(cle);
    q_kernel<<<KC, 256>>>(cle, wq, bq);
    routing_kernel<<<ROWS / 8, 256>>>(p_h);

    // 4) K/V projections (ONE launch, grid.z selects) + attention + ce_new
    gemm_tc<E_BIAS, false, false><<<ggrid2, 256>>>(p_h, w_k, bk, nullptr, p_kk,
                                                   nullptr, nullptr, w_v, bv, p_v);
    scores_kernel<<<ROWS / 8, 256>>>();
    asum_kernel<<<BB, 512>>>();
    vweight_kernel<<<dim3(BB, HH / 128), 256>>>();
    ce_kernel<<<KC * HH / 256, 256>>>();

    // 5) mixer: state in [B,H,C] layout; LN fused into GEMM A-path,
    //    LN stats fused into producer epilogues
    transpose_stats_kernel<<<tgrid, tblk>>>(p_h, p_z);
    for (int it = 0; it < NBITER; it++) {
        lnfin_kernel<<<ROWS / 256, 256>>>();                        // stats(z)
        gemm_tc<E_RESGELU, true, true><<<ggrid, 256>>>(p_z, w_ts, ts_b, p_z, p_z2,
                                                       ts_ln_g, ts_ln_b, w_ts, ts_b, p_z2);
        lnfin_kernel<<<ROWS / 256, 256>>>();                        // stats(z2)
        gemm_tc<E_GELU, true, false><<<ggrid, 256>>>(p_z2, w_ch1, ch_b1, nullptr, p_t,
                                                     ch_ln_g, ch_ln_b, w_ch1, ch_b1, p_t);
        if (it < NBITER - 1)
            gemm_tc<E_RESBIAS, false, true><<<ggrid, 256>>>(p_t, w_ch2, ch_b2, p_z2, p_z,
                                                            nullptr, nullptr, w_ch2, ch_b2, p_z);
        else
            gemm_tc<E_RESBIAS, false, false><<<ggrid, 256>>>(p_t, w_ch2, ch_b2, p_z2, p_z,
                                                             nullptr, nullptr, w_ch2, ch_b2, p_z);
    }

    // 6) expert projection (theta fused) + RevIN denorm
    prod_kernel<<<tgrid, tblk>>>();
    final_kernel<<<CC, 256>>>(out_w, out_b, rev_w, rev_b, y);
}

// round 11
// speedup vs baseline: 1.2506x; 1.0193x over previous
#include <cuda_runtime.h>
#include <math.h>
#include <stdint.h>

// ---------------- problem constants ----------------
#define BB 32
#define LL 512
#define CC 512
#define HH 512
#define KC 16          // clusters
#define PP 96
#define NBITER 4
#define ROWS (BB*CC)   // 16384
#define EPSV 1e-5f
#define GN 512         // GEMM N (all GEMMs are 16384x512x512)
#define GK 512         // GEMM K

// ---------------- scratch (static device globals; no allocation) ----------------
__device__ float g_xt   [(size_t)ROWS*HH];
__device__ float g_t    [(size_t)ROWS*HH];
__device__ float g_h    [(size_t)ROWS*HH];
__device__ float g_kk   [(size_t)ROWS*HH];
__device__ float g_v    [(size_t)ROWS*HH];
__device__ float g_z    [(size_t)ROWS*HH];
__device__ float g_z2   [(size_t)ROWS*HH];
__device__ float g_prod [(size_t)ROWS*HH];
__device__ float g_wts  [(size_t)7*GK*GN];    // tf32-rounded weights
__device__ float g_mean [ROWS];
__device__ float g_std  [ROWS];
__device__ float g_accA [ROWS];   // LN stats (sum) for z
__device__ float g_accA2[ROWS];   // LN stats (sumsq) for z
__device__ float g_accB [ROWS];   // LN stats (sum) for z2
__device__ float g_accB2[ROWS];   // LN stats (sumsq) for z2
__device__ float g_cn   [KC*HH];
__device__ float g_q    [KC*HH];
__device__ float g_p    [ROWS*KC];
__device__ float g_mask [ROWS*KC];
__device__ float g_am   [ROWS*KC];
__device__ float g_asum [BB*KC];
__device__ float g_cc   [BB*KC*HH];
__device__ float g_ce   [KC*HH];

// ---------------- helpers ----------------
__device__ __forceinline__ float gelu_f(float x) {
    return 0.5f * x * (1.0f + erff(x * 0.7071067811865476f));
}

__device__ __forceinline__ float f2tf32(float x) {
    uint32_t r;
    asm("cvt.rna.tf32.f32 %0, %1;" : "=r"(r) : "f"(x));
    return __uint_as_float(r);
}

__device__ __forceinline__ void cp16(uint32_t dst_smem, const void* src) {
    asm volatile("cp.async.ca.shared.global [%0], [%1], 16;"
                 :: "r"(dst_smem), "l"(src) : "memory");
}
__device__ __forceinline__ void cp_commit() {
    asm volatile("cp.async.commit_group;" ::: "memory");
}
template<int N>
__device__ __forceinline__ void cp_waitg() {
    asm volatile("cp.async.wait_group %0;" :: "n"(N) : "memory");
}

__device__ __forceinline__ uint32_t rotl32(uint32_t x, uint32_t d) {
    return (x << d) | (x >> (32u - d));
}

// JAX threefry2x32, PARTITIONABLE path. key = {0,42}; counter (0, idx);
// output word = out0 ^ out1.
__device__ uint32_t threefry_rand(uint32_t idx) {
    uint32_t x0 = 0u, x1 = idx;
    const uint32_t k0 = 0u, k1 = 42u;
    const uint32_t k2 = k0 ^ k1 ^ 0x1BD11BDAu;
    uint32_t ks[3] = {k0, k1, k2};
    x0 += ks[0]; x1 += ks[1];
    const uint32_t R[2][4] = {{13u,15u,26u,6u},{17u,29u,16u,24u}};
    #pragma unroll
    for (int i = 0; i < 5; i++) {
        #pragma unroll
        for (int j = 0; j < 4; j++) {
            x0 += x1; x1 = rotl32(x1, R[i & 1][j]); x1 ^= x0;
        }
        x0 += ks[(i + 1) % 3];
        x1 += ks[(i + 2) % 3] + (uint32_t)(i + 1);
    }
    return x0 ^ x1;
}

// ---------------- zero LN accumulators (once) ----------------
__global__ void zacc_kernel() {
    int i = blockIdx.x * 256 + threadIdx.x;
    g_accA[i] = 0.f;
    g_accA2[i] = 0.f;
    g_accB[i] = 0.f;
    g_accB2[i] = 0.f;
}

// ---------------- weight pre-round: all 7 matrices in one launch ----------------
__global__ void round_all_kernel(const float* s0, const float* s1, const float* s2,
                                 const float* s3, const float* s4, const float* s5,
                                 const float* s6) {
    int i = blockIdx.x * 256 + threadIdx.x;
    const float* s;
    switch (blockIdx.y) {
        case 0: s = s0; break; case 1: s = s1; break; case 2: s = s2; break;
        case 3: s = s3; break; case 4: s = s4; break; case 5: s = s5; break;
        default: s = s6; break;
    }
    g_wts[(size_t)blockIdx.y * GK * GN + i] = f2tf32(s[i]);
}

// ---------------- RevIN stats ----------------
__global__ void revin_stats_kernel(const float* __restrict__ x) {
    int b = blockIdx.y;
    int c = blockIdx.x * 256 + threadIdx.x;
    float s = 0.f, s2 = 0.f;
    const float* xp = x + (size_t)b * LL * CC + c;
    for (int l = 0; l < LL; l++) {
        float v = xp[(size_t)l * CC];
        s += v; s2 += v * v;
    }
    float m = s * (1.0f / LL);
    float var = fmaxf(s2 * (1.0f / LL) - m * m, 0.0f);
    g_mean[b * CC + c] = m;
    g_std [b * CC + c] = sqrtf(var + EPSV);
}

// xt[b,c,l] = (x[b,l,c]-mean)/std*rev_w[c]+rev_b[c]   (tiled transpose)
__global__ void build_xt_kernel(const float* __restrict__ x,
                                const float* __restrict__ rev_w,
                                const float* __restrict__ rev_b) {
    __shared__ float sh[32][33];
    int b = blockIdx.z;
    int l0 = blockIdx.x * 32, c0 = blockIdx.y * 32;
    const float* xb = x + (size_t)b * LL * CC;
    float* ob = g_xt + (size_t)b * CC * LL;
    #pragma unroll
    for (int r = 0; r < 32; r += 8)
        sh[threadIdx.y + r][threadIdx.x] = xb[(size_t)(l0 + threadIdx.y + r) * CC + c0 + threadIdx.x];
    __syncthreads();
    #pragma unroll
    for (int r = 0; r < 32; r += 8) {
        int c = c0 + threadIdx.y + r;
        float mn = g_mean[b * CC + c];
        float sd = g_std[b * CC + c];
        float v = sh[threadIdx.x][threadIdx.y + r];
        ob[(size_t)c * LL + l0 + threadIdx.x] = (v - mn) / sd * rev_w[c] + rev_b[c];
    }
}

// ---------------- TF32 tensor-core GEMM, K-tile 16, 3-stage cp.async B ----
// C[M,512] = A'[M,512] @ W[512,512] (+bias, +epilogue), A' = A or LayerNorm(A).
// W must be tf32-pre-rounded. A is truncated to tf32 by the MMA itself.
// Dual-output: blockIdx.z selects (W,bias,out) vs (W2,bias2,out2).
// LNBUF: -1 none, 0 = LN params from accA, 1 = from accB (raw sum/sumsq -> mu/rstd).
// SBUF : -1 none, 0 = accumulate output stats into accA, 1 = into accB.
// ZBUF : -1 none, 0 = zero accA at entry, 1 = zero accB at entry (bx==0,z==0 CTAs).
#define E_RELU    0
#define E_BIAS    1
#define E_GELU    2
#define E_RESGELU 3
#define E_RESBIAS 4

#define ASZ (128*16)   // A buffer floats
#define BSZ (16*132)   // B buffer floats

__device__ __forceinline__ void mma_tf32(float c[4],
                                         uint32_t a0, uint32_t a1, uint32_t a2, uint32_t a3,
                                         uint32_t b0, uint32_t b1) {
    asm volatile(
        "mma.sync.aligned.m16n8k8.row.col.f32.tf32.tf32.f32 "
        "{%0,%1,%2,%3}, {%4,%5,%6,%7}, {%8,%9}, {%0,%1,%2,%3};"
        : "+f"(c[0]), "+f"(c[1]), "+f"(c[2]), "+f"(c[3])
        : "r"(a0), "r"(a1), "r"(a2), "r"(a3), "r"(b0), "r"(b1));
}

template<int EPI, int LNBUF, int SBUF, int ZBUF>
__global__ __launch_bounds__(256, 2) void gemm_tc(
    const float* __restrict__ A, const float* __restrict__ W,
    const float* __restrict__ bias, const float* __restrict__ res,
    float* __restrict__ out,
    const float* __restrict__ ln_g, const float* __restrict__ ln_b,
    const float* __restrict__ W2, const float* __restrict__ bias2,
    float* __restrict__ out2) {
    __shared__ float As[2 * ASZ];
    __shared__ float Bs[3 * BSZ];
    if (blockIdx.z) { W = W2; bias = bias2; out = out2; }
    const int tid = threadIdx.x;
    const int warp = tid >> 5, lane = tid & 31;
    const int wm = (warp >> 2) * 64;    // warp M offset: 0 or 64
    const int wn = (warp & 3) * 32;     // warp N offset: 0,32,64,96
    const int gid = lane >> 2;          // 0..7
    const int tig = lane & 3;           // 0..3
    const int bx = blockIdx.x, by = blockIdx.y;

    const int arow = tid >> 1;          // 0..127
    const int ak   = (tid & 1) * 8;     // 0 or 8
    const int ssw  = (arow >> 1) & 3;   // store swizzle
    const int brow = tid >> 5;          // 0..7
    const int bn   = lane * 4;          // 0..124

    // zero the requested stats buffer (ordering vs readers/writers is by
    // kernel boundaries in the launch sequence)
    if (ZBUF >= 0) {
        if (bx == 0 && blockIdx.z == 0 && tid < 128) {
            int row = by * 128 + tid;
            if (ZBUF == 0) { g_accA[row] = 0.f; g_accA2[row] = 0.f; }
            else           { g_accB[row] = 0.f; g_accB2[row] = 0.f; }
        }
    }

    float acc[4][4][4];
    #pragma unroll
    for (int i = 0; i < 4; i++)
        #pragma unroll
        for (int j = 0; j < 4; j++)
            #pragma unroll
            for (int r = 0; r < 4; r++) acc[i][j][r] = 0.f;

    const float* Ap  = A + (size_t)(by * 128 + arow) * GK + ak;
    const float* Wp0 = W + (size_t)brow * GN + bx * 128 + bn;

    const uint32_t bdst = (uint32_t)__cvta_generic_to_shared(Bs + brow * 132 + bn);

    float mu = 0.f, rsd = 1.f;
    if (LNBUF >= 0) {
        int row = by * 128 + arow;
        float s  = (LNBUF == 0) ? g_accA[row]  : g_accB[row];
        float s2 = (LNBUF == 0) ? g_accA2[row] : g_accB2[row];
        mu = s * (1.0f / CC);
        float var = fmaxf(s2 * (1.0f / CC) - mu * mu, 0.0f);
        rsd = rsqrtf(var + EPSV);
    }

    const int NT = GK >> 4;

    auto issueB = [&](int buf, int kt) {
        const float* ws = Wp0 + (size_t)kt * 16 * GN;
        uint32_t d = bdst + (uint32_t)buf * (BSZ * 4);
        cp16(d, ws);
        cp16(d + 8 * 132 * 4, ws + (size_t)8 * GN);
        cp_commit();
    };

    float4 pa0, pa1;
    auto loadA = [&](int kt) {
        pa0 = *(const float4*)(Ap + kt * 16);
        pa1 = *(const float4*)(Ap + kt * 16 + 4);
    };

    auto store_tileA = [&](int buf, int kt) {
        float va[8] = {pa0.x, pa0.y, pa0.z, pa0.w, pa1.x, pa1.y, pa1.z, pa1.w};
        if (LNBUF >= 0) {
            const float* gp = ln_g + kt * 16 + ak;
            const float* bp = ln_b + kt * 16 + ak;
            #pragma unroll
            for (int j = 0; j < 8; j++) {
                float t = rsd * gp[j];
                va[j] = (va[j] - mu) * t + bp[j];
            }
        }
        float* Ab = As + buf * ASZ;
        const int abase = arow * 16 + (ak >> 2);
        #pragma unroll
        for (int j = 0; j < 4; j++) {
            *(float2*)(Ab + abase + ((j ^ ssw) << 2)) = make_float2(va[j], va[j + 4]);
        }
    };

    auto compute = [&](int abuf, int bbuf) {
        const float* Ab = As + abuf * ASZ;
        const float* Bb = Bs + bbuf * BSZ;
        #pragma unroll
        for (int ks = 0; ks < 2; ks++) {
            float2 fa0[4], fa1[4];
            #pragma unroll
            for (int i = 0; i < 4; i++) {
                int m0 = wm + i * 16 + gid;
                int sw = (m0 >> 1) & 3;
                int w = m0 * 16 + ((tig ^ sw) << 2) + ks * 2;
                fa0[i] = *(const float2*)(Ab + w);
                fa1[i] = *(const float2*)(Ab + w + 128);   // row m0+8: same swizzle
            }
            float fb0[4], fb1[4];
            #pragma unroll
            for (int j = 0; j < 4; j++) {
                int n0 = wn + j * 8 + gid;
                fb0[j] = Bb[(ks * 8 + tig) * 132 + n0];
                fb1[j] = Bb[(ks * 8 + tig + 4) * 132 + n0];
            }
            #pragma unroll
            for (int i = 0; i < 4; i++)
                #pragma unroll
                for (int j = 0; j < 4; j++)
                    mma_tf32(acc[i][j],
                             __float_as_uint(fa0[i].x), __float_as_uint(fa1[i].x),
                             __float_as_uint(fa0[i].y), __float_as_uint(fa1[i].y),
                             __float_as_uint(fb0[j]), __float_as_uint(fb1[j]));
        }
    };

    // prologue: B0 and B1 in flight, A0 staged, A1 in registers
    issueB(0, 0);
    issueB(1, 1);
    loadA(0);
    store_tileA(0, 0);
    loadA(1);
    cp_waitg<1>();          // B0 complete (B1 may be outstanding)
    __syncthreads();

    int bcur = 0;
    for (int kt = 0; kt < NT; kt++) {
        const int acur = kt & 1;
        int bn2 = bcur + 2; if (bn2 >= 3) bn2 -= 3;
        if (kt + 2 < NT) issueB(bn2, kt + 2);
        compute(acur, bcur);
        if (kt + 1 < NT) {
            store_tileA(acur ^ 1, kt + 1);
            if (kt + 2 < NT) loadA(kt + 2);
        }
        if (kt + 2 < NT) cp_waitg<1>(); else cp_waitg<0>();
        __syncthreads();
        bcur++; if (bcur >= 3) bcur -= 3;
    }

    // epilogue (+ optional fused LN-stats accumulation of the OUTPUT rows)
    #pragma unroll
    for (int i = 0; i < 4; i++) {
        int gr0 = by * 128 + wm + i * 16 + gid;
        int gr1 = gr0 + 8;
        float slo = 0.f, qlo = 0.f, shi = 0.f, qhi = 0.f;
        #pragma unroll
        for (int j = 0; j < 4; j++) {
            int gc = bx * 128 + wn + j * 8 + 2 * tig;
            float b0v = bias[gc], b1v = bias[gc + 1];
            float v0 = acc[i][j][0] + b0v, v1 = acc[i][j][1] + b1v;
            float v2 = acc[i][j][2] + b0v, v3 = acc[i][j][3] + b1v;
            if (EPI == E_RELU) {
                v0 = fmaxf(v0, 0.f); v1 = fmaxf(v1, 0.f);
                v2 = fmaxf(v2, 0.f); v3 = fmaxf(v3, 0.f);
            } else if (EPI == E_GELU) {
                v0 = gelu_f(v0); v1 = gelu_f(v1);
                v2 = gelu_f(v2); v3 = gelu_f(v3);
            } else if (EPI == E_RESGELU) {
                const float2 r0 = *(const float2*)(res + (size_t)gr0 * GN + gc);
                const float2 r1 = *(const float2*)(res + (size_t)gr1 * GN + gc);
                v0 = r0.x + gelu_f(v0); v1 = r0.y + gelu_f(v1);
                v2 = r1.x + gelu_f(v2); v3 = r1.y + gelu_f(v3);
            } else if (EPI == E_RESBIAS) {
                const float2 r0 = *(const float2*)(res + (size_t)gr0 * GN + gc);
                const float2 r1 = *(const float2*)(res + (size_t)gr1 * GN + gc);
                v0 += r0.x; v1 += r0.y; v2 += r1.x; v3 += r1.y;
            }
            if (SBUF >= 0) {
                slo += v0 + v1; qlo += v0 * v0 + v1 * v1;
                shi += v2 + v3; qhi += v2 * v2 + v3 * v3;
            }
            *(float2*)(out + (size_t)gr0 * GN + gc) = make_float2(v0, v1);
            *(float2*)(out + (size_t)gr1 * GN + gc) = make_float2(v2, v3);
        }
        if (SBUF >= 0) {
            slo += __shfl_xor_sync(0xffffffffu, slo, 1);
            slo += __shfl_xor_sync(0xffffffffu, slo, 2);
            qlo += __shfl_xor_sync(0xffffffffu, qlo, 1);
            qlo += __shfl_xor_sync(0xffffffffu, qlo, 2);
            shi += __shfl_xor_sync(0xffffffffu, shi, 1);
            shi += __shfl_xor_sync(0xffffffffu, shi, 2);
            qhi += __shfl_xor_sync(0xffffffffu, qhi, 1);
            qhi += __shfl_xor_sync(0xffffffffu, qhi, 2);
            if (tig == 0) {
                float* a  = (SBUF == 0) ? g_accA  : g_accB;
                float* a2 = (SBUF == 0) ? g_accA2 : g_accB2;
                atomicAdd(&a[gr0], slo);
                atomicAdd(&a2[gr0], qlo);
                atomicAdd(&a[gr1], shi);
                atomicAdd(&a2[gr1], qhi);
            }
        }
    }
}

// ---------------- cluster normalize (cn) ----------------
__global__ void cn_kernel(const float* __restrict__ ce) {
    __shared__ float red[256];
    int k = blockIdx.x, tid = threadIdx.x;
    float v0 = ce[k * HH + tid], v1 = ce[k * HH + tid + 256];
    red[tid] = v0 * v0 + v1 * v1;
    __syncthreads();
    for (int off = 128; off > 0; off >>= 1) {
        if (tid < off) red[tid] += red[tid + off];
        __syncthreads();
    }
    float nrm = fmaxf(sqrtf(red[0]), 1e-12f);
    g_cn[k * HH + tid] = v0 / nrm;
    g_cn[k * HH + tid + 256] = v1 / nrm;
}

// ---------------- Q = cluster_embeds @ wq + bq ----------------
__global__ void q_kernel(const float* __restrict__ ce,
                         const float* __restrict__ wq,
                         const float* __restrict__ bq) {
    __shared__ float csh[HH];
    int k = blockIdx.x, tid = threadIdx.x;
    csh[tid] = ce[k * HH + tid];
    csh[tid + 256] = ce[k * HH + tid + 256];
    __syncthreads();
    for (int n = tid; n < HH; n += 256) {
        float a = bq[n];
        for (int h = 0; h < HH; h++) a += csh[h] * wq[(size_t)h * HH + n];
        g_q[k * HH + n] = a;
    }
}

// ---------------- routing: warp per row; p = softmax(hn @ cn^T), bernoulli mask
__global__ __launch_bounds__(256) void routing_kernel(const float* __restrict__ h) {
    __shared__ float cnsh[KC * HH];   // 32KB
    int tid = threadIdx.x;
    for (int i = tid; i < KC * HH; i += 256) cnsh[i] = g_cn[i];
    __syncthreads();
    int w = tid >> 5, lane = tid & 31;
    int row = blockIdx.x * 8 + w;
    const float* hp = h + (size_t)row * HH;
    float acc[KC];
    #pragma unroll
    for (int k = 0; k < KC; k++) acc[k] = 0.f;
    float nsq = 0.f;
    #pragma unroll 4
    for (int i = 0; i < 16; i++) {
        int hh = i * 32 + lane;
        float hv = hp[hh];
        nsq += hv * hv;
        #pragma unroll
        for (int k = 0; k < KC; k++) acc[k] += hv * cnsh[k * HH + hh];
    }
    #pragma unroll
    for (int o = 16; o > 0; o >>= 1) nsq += __shfl_xor_sync(0xffffffffu, nsq, o);
    #pragma unroll
    for (int k = 0; k < KC; k++) {
        #pragma unroll
        for (int o = 16; o > 0; o >>= 1)
            acc[k] += __shfl_xor_sync(0xffffffffu, acc[k], o);
    }
    float inv = 1.0f / fmaxf(sqrtf(nsq), 1e-12f);
    float d = 0.f;
    #pragma unroll
    for (int k = 0; k < KC; k++) if (lane == k) d = acc[k];
    d *= inv;
    float mx = d;
    #pragma unroll
    for (int o = 8; o > 0; o >>= 1)
        mx = fmaxf(mx, __shfl_xor_sync(0xffffffffu, mx, o, 16));
    float e = expf(d - mx);
    float tot = e;
    #pragma unroll
    for (int o = 8; o > 0; o >>= 1)
        tot += __shfl_xor_sync(0xffffffffu, tot, o, 16);
    if (lane < KC) {
        float pv = e / tot;
        int idx = row * KC + lane;
        g_p[idx] = pv;
        uint32_t bits = threefry_rand((uint32_t)idx);
        float u = __uint_as_float((bits >> 9) | 0x3f800000u) - 1.0f;
        g_mask[idx] = (u < pv) ? 1.0f : 0.0f;
    }
}

// ---------------- attention phase 1: am = exp(score)*mask per row ----------------
__global__ __launch_bounds__(256) void scores_kernel() {
    __shared__ float qsh[KC * HH];   // [k][h], 32KB
    int tid = threadIdx.x;
    for (int i = tid; i < KC * HH; i += 256) qsh[i] = g_q[i];
    __syncthreads();
    int w = tid >> 5, lane = tid & 31;
    int row = blockIdx.x * 8 + w;
    const float* kp = g_kk + (size_t)row * HH;
    float acc[KC];
    #pragma unroll
    for (int k = 0; k < KC; k++) acc[k] = 0.f;
    #pragma unroll 4
    for (int i = 0; i < 16; i++) {
        int hh = i * 32 + lane;
        float kv = kp[hh];
        #pragma unroll
        for (int k = 0; k < KC; k++) acc[k] += kv * qsh[k * HH + hh];
    }
    #pragma unroll
    for (int k = 0; k < KC; k++) {
        #pragma unroll
        for (int o = 16; o > 0; o >>= 1)
            acc[k] += __shfl_xor_sync(0xffffffffu, acc[k], o);
    }
    if (lane < KC) {
        float am = expf(acc[lane] * 0.04419417382415922f) * g_mask[row * KC + lane];
        g_am[row * KC + lane] = am;
    }
}

// ---------------- attention phase 2: asum[b][k] = sum_c am ----------------
__global__ void asum_kernel() {
    int b = blockIdx.x;
    int k = threadIdx.x >> 5, lane = threadIdx.x & 31;
    float s = 0.f;
    for (int c = lane; c < CC; c += 32)
        s += g_am[((size_t)b * CC + c) * KC + k];
    #pragma unroll
    for (int o = 16; o > 0; o >>= 1) s += __shfl_down_sync(0xffffffffu, s, o);
    if (lane == 0) g_asum[b * KC + k] = s;
}

// ---------------- attention phase 3: Cc[b][k][h] = sum_c aw * V ----------------
__global__ __launch_bounds__(256) void vweight_kernel() {
    __shared__ float aw[KC * 514];
    __shared__ float inv_sh[KC];
    int b = blockIdx.x, h0 = blockIdx.y * 128;
    int tid = threadIdx.x;
    if (tid < KC) inv_sh[tid] = 1.0f / g_asum[b * KC + tid];
    __syncthreads();
    for (int idx = tid; idx < CC * KC; idx += 256) {
        int c = idx >> 4, k = idx & 15;
        aw[k * 514 + c] = g_am[((size_t)b * CC + c) * KC + k] * inv_sh[k];
    }
    __syncthreads();
    int kg = tid >> 6;
    int hg = tid & 63;
    const float* vp = g_v + (size_t)b * CC * HH + h0 + hg * 2;
    float a0[4], a1[4];
    #pragma unroll
    for (int k = 0; k < 4; k++) { a0[k] = 0.f; a1[k] = 0.f; }
    for (int c = 0; c < CC; c += 2) {
        float2 v0 = *(const float2*)(vp + (size_t)c * HH);
        float2 v1 = *(const float2*)(vp + (size_t)(c + 1) * HH);
        #pragma unroll
        for (int k = 0; k < 4; k++) {
            float2 a2 = *(const float2*)(&aw[(kg * 4 + k) * 514 + c]);
            a0[k] += a2.x * v0.x + a2.y * v1.x;
            a1[k] += a2.x * v0.y + a2.y * v1.y;
        }
    }
    #pragma unroll
    for (int k = 0; k < 4; k++) {
        size_t o = ((size_t)b * KC + kg * 4 + k) * HH + h0 + hg * 2;
        g_cc[o]     = a0[k];
        g_cc[o + 1] = a1[k];
    }
}

__global__ void ce_kernel() {
    int idx = blockIdx.x * 256 + threadIdx.x;
    float s = 0.f;
    for (int b = 0; b < BB; b++) s += g_cc[(size_t)b * KC * HH + idx];
    g_ce[idx] = s * (1.0f / BB);
}

// transpose per batch (h -> z) WITH fused LN-stats accumulation into accA
__global__ void transpose_stats_kernel(const float* __restrict__ in, float* __restrict__ out) {
    __shared__ float sh[32][33];
    int b = blockIdx.z;
    int i0 = blockIdx.y * 32, j0 = blockIdx.x * 32;
    const float* ib = in + (size_t)b * CC * HH;
    float* ob = out + (size_t)b * CC * HH;
    #pragma unroll
    for (int r = 0; r < 32; r += 8)
        sh[threadIdx.y + r][threadIdx.x] = ib[(size_t)(i0 + threadIdx.y + r) * HH + j0 + threadIdx.x];
    __syncthreads();
    #pragma unroll
    for (int r = 0; r < 32; r += 8) {
        float v = sh[threadIdx.x][threadIdx.y + r];
        ob[(size_t)(j0 + threadIdx.y + r) * HH + i0 + threadIdx.x] = v;
        float s = v, q = v * v;
        #pragma unroll
        for (int o = 16; o > 0; o >>= 1) {
            s += __shfl_xor_sync(0xffffffffu, s, o);
            q += __shfl_xor_sync(0xffffffffu, q, o);
        }
        if (threadIdx.x == 0) {
            int row = b * HH + j0 + threadIdx.y + r;
            atomicAdd(&g_accA[row], s);
            atomicAdd(&g_accA2[row], q);
        }
    }
}

// prod[b,c,h] = z[b,h,c] * theta[b,c,h], theta computed on the fly from p & ce
__global__ void prod_kernel() {
    __shared__ float sh[32][33];
    __shared__ float cesh[KC][32];
    __shared__ float psh[32][KC + 1];
    int b = blockIdx.z;
    int h0 = blockIdx.y * 32, c0 = blockIdx.x * 32;
    const float* zb = g_z + (size_t)b * HH * CC;
    float* ob = g_prod + (size_t)b * CC * HH;
    int tid = threadIdx.y * 32 + threadIdx.x;
    #pragma unroll
    for (int r = 0; r < 32; r += 8)
        sh[threadIdx.y + r][threadIdx.x] = zb[(size_t)(h0 + threadIdx.y + r) * CC + c0 + threadIdx.x];
    for (int t = tid; t < KC * 32; t += 256) {
        int k = t >> 5, xx = t & 31;
        cesh[k][xx] = g_ce[k * HH + h0 + xx];
    }
    for (int t = tid; t < 32 * KC; t += 256) {
        int c = t >> 4, k = t & 15;
        psh[c][k] = g_p[((size_t)b * CC + c0 + c) * KC + k];
    }
    __syncthreads();
    #pragma unroll
    for (int r = 0; r < 32; r += 8) {
        int cl = threadIdx.y + r;
        float th = 0.f;
        #pragma unroll
        for (int k = 0; k < KC; k++) th += psh[cl][k] * cesh[k][threadIdx.x];
        size_t o = (size_t)(c0 + cl) * HH + h0 + threadIdx.x;
        ob[o] = sh[threadIdx.x][cl] * th;
    }
}

// final: y[b,p,c] = denorm( sum_h prod[b,c,h]*out_w[c,h,p] + out_b[c,p] )
__global__ void final_kernel(const float* __restrict__ out_w,
                             const float* __restrict__ out_b,
                             const float* __restrict__ rev_w,
                             const float* __restrict__ rev_b,
                             float* __restrict__ y) {
    int c = blockIdx.x;
    __shared__ float Ws[32][PP];
    __shared__ float As[32][33];
    int tid = threadIdx.x;
    int tb = tid >> 3;
    int tp = (tid & 7) * 12;
    float acc[12];
    #pragma unroll
    for (int j = 0; j < 12; j++) acc[j] = 0.f;

    for (int h0 = 0; h0 < HH; h0 += 32) {
        for (int t = tid; t < 32 * PP; t += 256) {
            int i = t / PP, pp = t % PP;
            Ws[i][pp] = out_w[((size_t)c * HH + h0 + i) * PP + pp];
        }
        for (int t = tid; t < 32 * 32; t += 256) {
            int b = t >> 5, i = t & 31;
            As[b][i] = g_prod[((size_t)b * CC + c) * HH + h0 + i];
        }
        __syncthreads();
        #pragma unroll
        for (int i = 0; i < 32; i++) {
            float a = As[tb][i];
            #pragma unroll
            for (int j = 0; j < 12; j++) acc[j] += a * Ws[i][tp + j];
        }
        __syncthreads();
    }
    float rb = rev_b[c];
    float rwinv = 1.0f / (rev_w[c] + 1e-10f);
    float sd = g_std[tb * CC + c];
    float mn = g_mean[tb * CC + c];
    #pragma unroll
    for (int j = 0; j < 12; j++) {
        float v = acc[j] + out_b[(size_t)c * PP + tp + j];
        v = (v - rb) * rwinv;
        v = v * sd + mn;
        y[((size_t)tb * PP + tp + j) * CC + c] = v;
    }
}

// ---------------- host orchestration ----------------
extern "C" void kernel_launch(void* const* d_in, const int* in_sizes, int n_in,
                              void* d_out, int out_size) {
    const float* x       = (const float*)d_in[0];
    const float* rev_w   = (const float*)d_in[1];
    const float* rev_b   = (const float*)d_in[2];
    const float* mlp_w1  = (const float*)d_in[3];
    const float* mlp_b1  = (const float*)d_in[4];
    const float* mlp_w2  = (const float*)d_in[5];
    const float* mlp_b2  = (const float*)d_in[6];
    const float* cle     = (const float*)d_in[7];
    const float* wq      = (const float*)d_in[8];
    const float* bq      = (const float*)d_in[9];
    const float* wk      = (const float*)d_in[10];
    const float* bk      = (const float*)d_in[11];
    const float* wv      = (const float*)d_in[12];
    const float* bv      = (const float*)d_in[13];
    const float* ts_ln_g = (const float*)d_in[14];
    const float* ts_ln_b = (const float*)d_in[15];
    const float* ts_w    = (const float*)d_in[16];
    const float* ts_b    = (const float*)d_in[17];
    const float* ch_ln_g = (const float*)d_in[18];
    const float* ch_ln_b = (const float*)d_in[19];
    const float* ch_w1   = (const float*)d_in[20];
    const float* ch_b1   = (const float*)d_in[21];
    const float* ch_w2   = (const float*)d_in[22];
    const float* ch_b2   = (const float*)d_in[23];
    const float* out_w   = (const float*)d_in[24];
    const float* out_b   = (const float*)d_in[25];
    float* y = (float*)d_out;

    float *p_xt, *p_t, *p_h, *p_kk, *p_v, *p_z, *p_z2, *p_w;
    cudaGetSymbolAddress((void**)&p_xt, g_xt);
    cudaGetSymbolAddress((void**)&p_t,  g_t);
    cudaGetSymbolAddress((void**)&p_h,  g_h);
    cudaGetSymbolAddress((void**)&p_kk, g_kk);
    cudaGetSymbolAddress((void**)&p_v,  g_v);
    cudaGetSymbolAddress((void**)&p_z,  g_z);
    cudaGetSymbolAddress((void**)&p_z2, g_z2);
    cudaGetSymbolAddress((void**)&p_w,  g_wts);

    const size_t WSZ = (size_t)GK * GN;
    float* w_mlp1 = p_w + 0 * WSZ;
    float* w_mlp2 = p_w + 1 * WSZ;
    float* w_k    = p_w + 2 * WSZ;
    float* w_v    = p_w + 3 * WSZ;
    float* w_ts   = p_w + 4 * WSZ;
    float* w_ch1  = p_w + 5 * WSZ;
    float* w_ch2  = p_w + 6 * WSZ;

    dim3 tgrid(16, 16, BB), tblk(32, 8);
    dim3 ggrid(GN / 128, ROWS / 128);
    dim3 ggrid2(GN / 128, ROWS / 128, 2);
    const int RWB = (int)(WSZ / 256);

    // 0) zero LN accumulators + pre-round all weights to tf32
    zacc_kernel<<<ROWS / 256, 256>>>();
    round_all_kernel<<<dim3(RWB, 7), 256>>>(mlp_w1, mlp_w2, wk, wv, ts_w, ch_w1, ch_w2);

    // 1) RevIN stats + normalized transpose
    revin_stats_kernel<<<dim3(CC / 256, BB), 256>>>(x);
    build_xt_kernel<<<tgrid, tblk>>>(x, rev_w, rev_b);

    // 2) channel MLP: h = relu(xt@w1+b1)@w2+b2
    gemm_tc<E_RELU, -1, -1, -1><<<ggrid, 256>>>(p_xt, w_mlp1, mlp_b1, nullptr, p_t,
                                                nullptr, nullptr, w_mlp1, mlp_b1, p_t);
    gemm_tc<E_BIAS, -1, -1, -1><<<ggrid, 256>>>(p_t, w_mlp2, mlp_b2, nullptr, p_h,
                                                nullptr, nullptr, w_mlp2, mlp_b2, p_h);

    // 3) routing (p + threefry bernoulli mask)
    cn_kernel<<<KC, 256>>>(cle);
    q_kernel<<<KC, 256>>>(cle, wq, bq);
    routing_kernel<<<ROWS / 8, 256>>>(p_h);

    // 4) K/V projections (ONE launch, grid.z selects) + attention + ce_new
    gemm_tc<E_BIAS, -1, -1, -1><<<ggrid2, 256>>>(p_h, w_k, bk, nullptr, p_kk,
                                                 nullptr, nullptr, w_v, bv, p_v);
    scores_kernel<<<ROWS / 8, 256>>>();
    asum_kernel<<<BB, 512>>>();
    vweight_kernel<<<dim3(BB, HH / 128), 256>>>();
    ce_kernel<<<KC * HH / 256, 256>>>();

    // 5) mixer with fully fused LN: stats ping-pong A (z) / B (z2).
    //    transpose accumulates z-stats into A (A,B zeroed by zacc).
    //    RESGELU: LN from A, out z2, stats->B.
    //    GELU:    LN from B, zeroes A (A's readers done; next writer is RESBIAS).
    //    RESBIAS: out z, stats->A, zeroes B (B's readers done; next writer RESGELU).
    transpose_stats_kernel<<<tgrid, tblk>>>(p_h, p_z);
    for (int it = 0; it < NBITER; it++) {
        gemm_tc<E_RESGELU, 0, 1, -1><<<ggrid, 256>>>(p_z, w_ts, ts_b, p_z, p_z2,
                                                     ts_ln_g, ts_ln_b, w_ts, ts_b, p_z2);
        gemm_tc<E_GELU, 1, -1, 0><<<ggrid, 256>>>(p_z2, w_ch1, ch_b1, nullptr, p_t,
                                                  ch_ln_g, ch_ln_b, w_ch1, ch_b1, p_t);
        if (it < NBITER - 1)
            gemm_tc<E_RESBIAS, -1, 0, 1><<<ggrid, 256>>>(p_t, w_ch2, ch_b2, p_z2, p_z,
                                                         nullptr, nullptr, w_ch2, ch_b2, p_z);
        else
            gemm_tc<E_RESBIAS, -1, -1, -1><<<ggrid, 256>>>(p_t, w_ch2, ch_b2, p_z2, p_z,
                                                           nullptr, nullptr, w_ch2, ch_b2, p_z);
    }

    // 6) expert projection (theta fused) + RevIN denorm
    prod_kernel<<<tgrid, tblk>>>();
    final_kernel<<<CC, 256>>>(out_w, out_b, rev_w, rev_b, y);
}

// round 12
// speedup vs baseline: 1.2916x; 1.0327x over previous
#include <cuda_runtime.h>
#include <math.h>
#include <stdint.h>

// ---------------- problem constants ----------------
#define BB 32
#define LL 512
#define CC 512
#define HH 512
#define KC 16          // clusters
#define PP 96
#define NBITER 4
#define ROWS (BB*CC)   // 16384
#define EPSV 1e-5f
#define GN 512         // GEMM N (all GEMMs are 16384x512x512)
#define GK 512         // GEMM K

// ---------------- scratch (static device globals; no allocation) ----------------
__device__ float g_xt   [(size_t)ROWS*HH];
__device__ float g_t    [(size_t)ROWS*HH];
__device__ float g_h    [(size_t)ROWS*HH];
__device__ float g_kk   [(size_t)ROWS*HH];
__device__ float g_v    [(size_t)ROWS*HH];
__device__ float g_z    [(size_t)ROWS*HH];
__device__ float g_z2   [(size_t)ROWS*HH];
__device__ float g_prod [(size_t)ROWS*HH];
__device__ float g_wts  [(size_t)7*GK*GN];    // tf32-rounded weights
__device__ float g_mean [ROWS];
__device__ float g_std  [ROWS];
__device__ float g_accA [ROWS];   // LN stats (sum) for z
__device__ float g_accA2[ROWS];   // LN stats (sumsq) for z
__device__ float g_accB [ROWS];   // LN stats (sum) for z2
__device__ float g_accB2[ROWS];   // LN stats (sumsq) for z2
__device__ float g_cn   [KC*HH];
__device__ float g_q    [KC*HH];
__device__ float g_p    [ROWS*KC];
__device__ float g_mask [ROWS*KC];
__device__ float g_am   [ROWS*KC];
__device__ float g_cc   [BB*KC*HH];
__device__ float g_ce   [KC*HH];

// ---------------- helpers ----------------
__device__ __forceinline__ float gelu_f(float x) {
    return 0.5f * x * (1.0f + erff(x * 0.7071067811865476f));
}

__device__ __forceinline__ float f2tf32(float x) {
    uint32_t r;
    asm("cvt.rna.tf32.f32 %0, %1;" : "=r"(r) : "f"(x));
    return __uint_as_float(r);
}

__device__ __forceinline__ void cp16(uint32_t dst_smem, const void* src) {
    asm volatile("cp.async.ca.shared.global [%0], [%1], 16;"
                 :: "r"(dst_smem), "l"(src) : "memory");
}
__device__ __forceinline__ void cp_commit() {
    asm volatile("cp.async.commit_group;" ::: "memory");
}
template<int N>
__device__ __forceinline__ void cp_waitg() {
    asm volatile("cp.async.wait_group %0;" :: "n"(N) : "memory");
}

__device__ __forceinline__ uint32_t rotl32(uint32_t x, uint32_t d) {
    return (x << d) | (x >> (32u - d));
}

// JAX threefry2x32, PARTITIONABLE path. key = {0,42}; counter (0, idx);
// output word = out0 ^ out1.
__device__ uint32_t threefry_rand(uint32_t idx) {
    uint32_t x0 = 0u, x1 = idx;
    const uint32_t k0 = 0u, k1 = 42u;
    const uint32_t k2 = k0 ^ k1 ^ 0x1BD11BDAu;
    uint32_t ks[3] = {k0, k1, k2};
    x0 += ks[0]; x1 += ks[1];
    const uint32_t R[2][4] = {{13u,15u,26u,6u},{17u,29u,16u,24u}};
    #pragma unroll
    for (int i = 0; i < 5; i++) {
        #pragma unroll
        for (int j = 0; j < 4; j++) {
            x0 += x1; x1 = rotl32(x1, R[i & 1][j]); x1 ^= x0;
        }
        x0 += ks[(i + 1) % 3];
        x1 += ks[(i + 2) % 3] + (uint32_t)(i + 1);
    }
    return x0 ^ x1;
}

// ---------------- zero LN accumulators (once) ----------------
__global__ void zacc_kernel() {
    int i = blockIdx.x * 256 + threadIdx.x;
    g_accA[i] = 0.f;
    g_accA2[i] = 0.f;
    g_accB[i] = 0.f;
    g_accB2[i] = 0.f;
}

// ---------------- weight pre-round: all 7 matrices in one launch ----------------
__global__ void round_all_kernel(const float* s0, const float* s1, const float* s2,
                                 const float* s3, const float* s4, const float* s5,
                                 const float* s6) {
    int i = blockIdx.x * 256 + threadIdx.x;
    const float* s;
    switch (blockIdx.y) {
        case 0: s = s0; break; case 1: s = s1; break; case 2: s = s2; break;
        case 3: s = s3; break; case 4: s = s4; break; case 5: s = s5; break;
        default: s = s6; break;
    }
    g_wts[(size_t)blockIdx.y * GK * GN + i] = f2tf32(s[i]);
}

// ---------------- RevIN stats ----------------
__global__ void revin_stats_kernel(const float* __restrict__ x) {
    int b = blockIdx.y;
    int c = blockIdx.x * 256 + threadIdx.x;
    float s = 0.f, s2 = 0.f;
    const float* xp = x + (size_t)b * LL * CC + c;
    for (int l = 0; l < LL; l++) {
        float v = xp[(size_t)l * CC];
        s += v; s2 += v * v;
    }
    float m = s * (1.0f / LL);
    float var = fmaxf(s2 * (1.0f / LL) - m * m, 0.0f);
    g_mean[b * CC + c] = m;
    g_std [b * CC + c] = sqrtf(var + EPSV);
}

// xt[b,c,l] = (x[b,l,c]-mean)/std*rev_w[c]+rev_b[c]   (tiled transpose)
__global__ void build_xt_kernel(const float* __restrict__ x,
                                const float* __restrict__ rev_w,
                                const float* __restrict__ rev_b) {
    __shared__ float sh[32][33];
    int b = blockIdx.z;
    int l0 = blockIdx.x * 32, c0 = blockIdx.y * 32;
    const float* xb = x + (size_t)b * LL * CC;
    float* ob = g_xt + (size_t)b * CC * LL;
    #pragma unroll
    for (int r = 0; r < 32; r += 8)
        sh[threadIdx.y + r][threadIdx.x] = xb[(size_t)(l0 + threadIdx.y + r) * CC + c0 + threadIdx.x];
    __syncthreads();
    #pragma unroll
    for (int r = 0; r < 32; r += 8) {
        int c = c0 + threadIdx.y + r;
        float mn = g_mean[b * CC + c];
        float sd = g_std[b * CC + c];
        float v = sh[threadIdx.x][threadIdx.y + r];
        ob[(size_t)c * LL + l0 + threadIdx.x] = (v - mn) / sd * rev_w[c] + rev_b[c];
    }
}

// ---------------- TF32 tensor-core GEMM, K-tile 16, 3-stage cp.async B ----
// C[M,512] = A'[M,512] @ W[512,512] (+bias, +epilogue), A' = A or LayerNorm(A).
// W must be tf32-pre-rounded. A is truncated to tf32 by the MMA itself.
// Dual-output: blockIdx.z selects (W,bias,out) vs (W2,bias2,out2).
// LNBUF: -1 none, 0 = LN params from accA, 1 = from accB (raw sum/sumsq -> mu/rstd).
// SBUF : -1 none, 0 = accumulate output stats into accA, 1 = into accB.
// ZBUF : -1 none, 0 = zero accA at entry, 1 = zero accB at entry (bx==0,z==0 CTAs).
#define E_RELU    0
#define E_BIAS    1
#define E_GELU    2
#define E_RESGELU 3
#define E_RESBIAS 4

#define ASZ (128*16)   // A buffer floats
#define BSZ (16*132)   // B buffer floats

__device__ __forceinline__ void mma_tf32(float c[4],
                                         uint32_t a0, uint32_t a1, uint32_t a2, uint32_t a3,
                                         uint32_t b0, uint32_t b1) {
    asm volatile(
        "mma.sync.aligned.m16n8k8.row.col.f32.tf32.tf32.f32 "
        "{%0,%1,%2,%3}, {%4,%5,%6,%7}, {%8,%9}, {%0,%1,%2,%3};"
        : "+f"(c[0]), "+f"(c[1]), "+f"(c[2]), "+f"(c[3])
        : "r"(a0), "r"(a1), "r"(a2), "r"(a3), "r"(b0), "r"(b1));
}

template<int EPI, int LNBUF, int SBUF, int ZBUF>
__global__ __launch_bounds__(256, 2) void gemm_tc(
    const float* __restrict__ A, const float* __restrict__ W,
    const float* __restrict__ bias, const float* __restrict__ res,
    float* __restrict__ out,
    const float* __restrict__ ln_g, const float* __restrict__ ln_b,
    const float* __restrict__ W2, const float* __restrict__ bias2,
    float* __restrict__ out2) {
    __shared__ float As[2 * ASZ];
    __shared__ float Bs[3 * BSZ];
    if (blockIdx.z) { W = W2; bias = bias2; out = out2; }
    const int tid = threadIdx.x;
    const int warp = tid >> 5, lane = tid & 31;
    const int wm = (warp >> 2) * 64;    // warp M offset: 0 or 64
    const int wn = (warp & 3) * 32;     // warp N offset: 0,32,64,96
    const int gid = lane >> 2;          // 0..7
    const int tig = lane & 3;           // 0..3
    const int bx = blockIdx.x, by = blockIdx.y;

    const int arow = tid >> 1;          // 0..127
    const int ak   = (tid & 1) * 8;     // 0 or 8
    const int ssw  = (arow >> 1) & 3;   // store swizzle
    const int brow = tid >> 5;          // 0..7
    const int bn   = lane * 4;          // 0..124

    if (ZBUF >= 0) {
        if (bx == 0 && blockIdx.z == 0 && tid < 128) {
            int row = by * 128 + tid;
            if (ZBUF == 0) { g_accA[row] = 0.f; g_accA2[row] = 0.f; }
            else           { g_accB[row] = 0.f; g_accB2[row] = 0.f; }
        }
    }

    float acc[4][4][4];
    #pragma unroll
    for (int i = 0; i < 4; i++)
        #pragma unroll
        for (int j = 0; j < 4; j++)
            #pragma unroll
            for (int r = 0; r < 4; r++) acc[i][j][r] = 0.f;

    const float* Ap  = A + (size_t)(by * 128 + arow) * GK + ak;
    const float* Wp0 = W + (size_t)brow * GN + bx * 128 + bn;

    const uint32_t bdst = (uint32_t)__cvta_generic_to_shared(Bs + brow * 132 + bn);

    float mu = 0.f, rsd = 1.f;
    if (LNBUF >= 0) {
        int row = by * 128 + arow;
        float s  = (LNBUF == 0) ? g_accA[row]  : g_accB[row];
        float s2 = (LNBUF == 0) ? g_accA2[row] : g_accB2[row];
        mu = s * (1.0f / CC);
        float var = fmaxf(s2 * (1.0f / CC) - mu * mu, 0.0f);
        rsd = rsqrtf(var + EPSV);
    }

    const int NT = GK >> 4;

    auto issueB = [&](int buf, int kt) {
        const float* ws = Wp0 + (size_t)kt * 16 * GN;
        uint32_t d = bdst + (uint32_t)buf * (BSZ * 4);
        cp16(d, ws);
        cp16(d + 8 * 132 * 4, ws + (size_t)8 * GN);
        cp_commit();
    };

    float4 pa0, pa1;
    auto loadA = [&](int kt) {
        pa0 = *(const float4*)(Ap + kt * 16);
        pa1 = *(const float4*)(Ap + kt * 16 + 4);
    };

    auto store_tileA = [&](int buf, int kt) {
        float va[8] = {pa0.x, pa0.y, pa0.z, pa0.w, pa1.x, pa1.y, pa1.z, pa1.w};
        if (LNBUF >= 0) {
            const float* gp = ln_g + kt * 16 + ak;
            const float* bp = ln_b + kt * 16 + ak;
            #pragma unroll
            for (int j = 0; j < 8; j++) {
                float t = rsd * gp[j];
                va[j] = (va[j] - mu) * t + bp[j];
            }
        }
        float* Ab = As + buf * ASZ;
        const int abase = arow * 16 + (ak >> 2);
        #pragma unroll
        for (int j = 0; j < 4; j++) {
            *(float2*)(Ab + abase + ((j ^ ssw) << 2)) = make_float2(va[j], va[j + 4]);
        }
    };

    auto compute = [&](int abuf, int bbuf) {
        const float* Ab = As + abuf * ASZ;
        const float* Bb = Bs + bbuf * BSZ;
        #pragma unroll
        for (int ks = 0; ks < 2; ks++) {
            float2 fa0[4], fa1[4];
            #pragma unroll
            for (int i = 0; i < 4; i++) {
                int m0 = wm + i * 16 + gid;
                int sw = (m0 >> 1) & 3;
                int w = m0 * 16 + ((tig ^ sw) << 2) + ks * 2;
                fa0[i] = *(const float2*)(Ab + w);
                fa1[i] = *(const float2*)(Ab + w + 128);   // row m0+8: same swizzle
            }
            float fb0[4], fb1[4];
            #pragma unroll
            for (int j = 0; j < 4; j++) {
                int n0 = wn + j * 8 + gid;
                fb0[j] = Bb[(ks * 8 + tig) * 132 + n0];
                fb1[j] = Bb[(ks * 8 + tig + 4) * 132 + n0];
            }
            #pragma unroll
            for (int i = 0; i < 4; i++)
                #pragma unroll
                for (int j = 0; j < 4; j++)
                    mma_tf32(acc[i][j],
                             __float_as_uint(fa0[i].x), __float_as_uint(fa1[i].x),
                             __float_as_uint(fa0[i].y), __float_as_uint(fa1[i].y),
                             __float_as_uint(fb0[j]), __float_as_uint(fb1[j]));
        }
    };

    // prologue: B0 and B1 in flight, A0 staged, A1 in registers
    issueB(0, 0);
    issueB(1, 1);
    loadA(0);
    store_tileA(0, 0);
    loadA(1);
    cp_waitg<1>();          // B0 complete (B1 may be outstanding)
    __syncthreads();

    int bcur = 0;
    for (int kt = 0; kt < NT; kt++) {
        const int acur = kt & 1;
        int bn2 = bcur + 2; if (bn2 >= 3) bn2 -= 3;
        if (kt + 2 < NT) issueB(bn2, kt + 2);
        compute(acur, bcur);
        if (kt + 1 < NT) {
            store_tileA(acur ^ 1, kt + 1);
            if (kt + 2 < NT) loadA(kt + 2);
        }
        if (kt + 2 < NT) cp_waitg<1>(); else cp_waitg<0>();
        __syncthreads();
        bcur++; if (bcur >= 3) bcur -= 3;
    }

    // epilogue (+ optional fused LN-stats accumulation of the OUTPUT rows)
    #pragma unroll
    for (int i = 0; i < 4; i++) {
        int gr0 = by * 128 + wm + i * 16 + gid;
        int gr1 = gr0 + 8;
        float slo = 0.f, qlo = 0.f, shi = 0.f, qhi = 0.f;
        #pragma unroll
        for (int j = 0; j < 4; j++) {
            int gc = bx * 128 + wn + j * 8 + 2 * tig;
            float b0v = bias[gc], b1v = bias[gc + 1];
            float v0 = acc[i][j][0] + b0v, v1 = acc[i][j][1] + b1v;
            float v2 = acc[i][j][2] + b0v, v3 = acc[i][j][3] + b1v;
            if (EPI == E_RELU) {
                v0 = fmaxf(v0, 0.f); v1 = fmaxf(v1, 0.f);
                v2 = fmaxf(v2, 0.f); v3 = fmaxf(v3, 0.f);
            } else if (EPI == E_GELU) {
                v0 = gelu_f(v0); v1 = gelu_f(v1);
                v2 = gelu_f(v2); v3 = gelu_f(v3);
            } else if (EPI == E_RESGELU) {
                const float2 r0 = *(const float2*)(res + (size_t)gr0 * GN + gc);
                const float2 r1 = *(const float2*)(res + (size_t)gr1 * GN + gc);
                v0 = r0.x + gelu_f(v0); v1 = r0.y + gelu_f(v1);
                v2 = r1.x + gelu_f(v2); v3 = r1.y + gelu_f(v3);
            } else if (EPI == E_RESBIAS) {
                const float2 r0 = *(const float2*)(res + (size_t)gr0 * GN + gc);
                const float2 r1 = *(const float2*)(res + (size_t)gr1 * GN + gc);
                v0 += r0.x; v1 += r0.y; v2 += r1.x; v3 += r1.y;
            }
            if (SBUF >= 0) {
                slo += v0 + v1; qlo += v0 * v0 + v1 * v1;
                shi += v2 + v3; qhi += v2 * v2 + v3 * v3;
            }
            *(float2*)(out + (size_t)gr0 * GN + gc) = make_float2(v0, v1);
            *(float2*)(out + (size_t)gr1 * GN + gc) = make_float2(v2, v3);
        }
        if (SBUF >= 0) {
            slo += __shfl_xor_sync(0xffffffffu, slo, 1);
            slo += __shfl_xor_sync(0xffffffffu, slo, 2);
            qlo += __shfl_xor_sync(0xffffffffu, qlo, 1);
            qlo += __shfl_xor_sync(0xffffffffu, qlo, 2);
            shi += __shfl_xor_sync(0xffffffffu, shi, 1);
            shi += __shfl_xor_sync(0xffffffffu, shi, 2);
            qhi += __shfl_xor_sync(0xffffffffu, qhi, 1);
            qhi += __shfl_xor_sync(0xffffffffu, qhi, 2);
            if (tig == 0) {
                float* a  = (SBUF == 0) ? g_accA  : g_accB;
                float* a2 = (SBUF == 0) ? g_accA2 : g_accB2;
                atomicAdd(&a[gr0], slo);
                atomicAdd(&a2[gr0], qlo);
                atomicAdd(&a[gr1], shi);
                atomicAdd(&a2[gr1], qhi);
            }
        }
    }
}

// ---------------- cluster normalize (cn) ----------------
__global__ void cn_kernel(const float* __restrict__ ce) {
    __shared__ float red[256];
    int k = blockIdx.x, tid = threadIdx.x;
    float v0 = ce[k * HH + tid], v1 = ce[k * HH + tid + 256];
    red[tid] = v0 * v0 + v1 * v1;
    __syncthreads();
    for (int off = 128; off > 0; off >>= 1) {
        if (tid < off) red[tid] += red[tid + off];
        __syncthreads();
    }
    float nrm = fmaxf(sqrtf(red[0]), 1e-12f);
    g_cn[k * HH + tid] = v0 / nrm;
    g_cn[k * HH + tid + 256] = v1 / nrm;
}

// ---------------- Q = cluster_embeds @ wq + bq ----------------
__global__ void q_kernel(const float* __restrict__ ce,
                         const float* __restrict__ wq,
                         const float* __restrict__ bq) {
    __shared__ float csh[HH];
    int k = blockIdx.x, tid = threadIdx.x;
    csh[tid] = ce[k * HH + tid];
    csh[tid + 256] = ce[k * HH + tid + 256];
    __syncthreads();
    for (int n = tid; n < HH; n += 256) {
        float a = bq[n];
        for (int h = 0; h < HH; h++) a += csh[h] * wq[(size_t)h * HH + n];
        g_q[k * HH + n] = a;
    }
}

// ---------------- routing: warp per row; p = softmax(hn @ cn^T), bernoulli mask
__global__ __launch_bounds__(256) void routing_kernel(const float* __restrict__ h) {
    __shared__ float cnsh[KC * HH];   // 32KB
    int tid = threadIdx.x;
    for (int i = tid; i < KC * HH; i += 256) cnsh[i] = g_cn[i];
    __syncthreads();
    int w = tid >> 5, lane = tid & 31;
    int row = blockIdx.x * 8 + w;
    const float* hp = h + (size_t)row * HH;
    float acc[KC];
    #pragma unroll
    for (int k = 0; k < KC; k++) acc[k] = 0.f;
    float nsq = 0.f;
    #pragma unroll 4
    for (int i = 0; i < 16; i++) {
        int hh = i * 32 + lane;
        float hv = hp[hh];
        nsq += hv * hv;
        #pragma unroll
        for (int k = 0; k < KC; k++) acc[k] += hv * cnsh[k * HH + hh];
    }
    #pragma unroll
    for (int o = 16; o > 0; o >>= 1) nsq += __shfl_xor_sync(0xffffffffu, nsq, o);
    #pragma unroll
    for (int k = 0; k < KC; k++) {
        #pragma unroll
        for (int o = 16; o > 0; o >>= 1)
            acc[k] += __shfl_xor_sync(0xffffffffu, acc[k], o);
    }
    float inv = 1.0f / fmaxf(sqrtf(nsq), 1e-12f);
    float d = 0.f;
    #pragma unroll
    for (int k = 0; k < KC; k++) if (lane == k) d = acc[k];
    d *= inv;
    float mx = d;
    #pragma unroll
    for (int o = 8; o > 0; o >>= 1)
        mx = fmaxf(mx, __shfl_xor_sync(0xffffffffu, mx, o, 16));
    float e = expf(d - mx);
    float tot = e;
    #pragma unroll
    for (int o = 8; o > 0; o >>= 1)
        tot += __shfl_xor_sync(0xffffffffu, tot, o, 16);
    if (lane < KC) {
        float pv = e / tot;
        int idx = row * KC + lane;
        g_p[idx] = pv;
        uint32_t bits = threefry_rand((uint32_t)idx);
        float u = __uint_as_float((bits >> 9) | 0x3f800000u) - 1.0f;
        g_mask[idx] = (u < pv) ? 1.0f : 0.0f;
    }
}

// ---------------- attention phase 1: am = exp(score)*mask per row ----------------
__global__ __launch_bounds__(256) void scores_kernel() {
    __shared__ float qsh[KC * HH];   // [k][h], 32KB
    int tid = threadIdx.x;
    for (int i = tid; i < KC * HH; i += 256) qsh[i] = g_q[i];
    __syncthreads();
    int w = tid >> 5, lane = tid & 31;
    int row = blockIdx.x * 8 + w;
    const float* kp = g_kk + (size_t)row * HH;
    float acc[KC];
    #pragma unroll
    for (int k = 0; k < KC; k++) acc[k] = 0.f;
    #pragma unroll 4
    for (int i = 0; i < 16; i++) {
        int hh = i * 32 + lane;
        float kv = kp[hh];
        #pragma unroll
        for (int k = 0; k < KC; k++) acc[k] += kv * qsh[k * HH + hh];
    }
    #pragma unroll
    for (int k = 0; k < KC; k++) {
        #pragma unroll
        for (int o = 16; o > 0; o >>= 1)
            acc[k] += __shfl_xor_sync(0xffffffffu, acc[k], o);
    }
    if (lane < KC) {
        float am = expf(acc[lane] * 0.04419417382415922f) * g_mask[row * KC + lane];
        g_am[row * KC + lane] = am;
    }
}

// ---------------- attention: Cc[b][k][h] = sum_c am*V / sum_c am (sums in-block) ----
__global__ __launch_bounds__(256) void vweight_kernel() {
    __shared__ float aw[KC * 514];
    __shared__ float part[KC][17];
    __shared__ float inv_sh[KC];
    int b = blockIdx.x, h0 = blockIdx.y * 128;
    int tid = threadIdx.x;
    for (int idx = tid; idx < CC * KC; idx += 256) {
        int c = idx >> 4, k = idx & 15;
        aw[k * 514 + c] = g_am[((size_t)b * CC + c) * KC + k];
    }
    __syncthreads();
    // per-k sum over c (computed redundantly per block; cheap)
    {
        int k = tid & 15, ci = tid >> 4;  // ci 0..15
        float ps = 0.f;
        for (int c = ci; c < CC; c += 16) ps += aw[k * 514 + c];
        part[k][ci] = ps;
    }
    __syncthreads();
    if (tid < KC) {
        float s = 0.f;
        #pragma unroll
        for (int i = 0; i < 16; i++) s += part[tid][i];
        inv_sh[tid] = 1.0f / s;
    }
    __syncthreads();
    int kg = tid >> 6;
    int hg = tid & 63;
    const float* vp = g_v + (size_t)b * CC * HH + h0 + hg * 2;
    float a0[4], a1[4];
    #pragma unroll
    for (int k = 0; k < 4; k++) { a0[k] = 0.f; a1[k] = 0.f; }
    for (int c = 0; c < CC; c += 2) {
        float2 v0 = *(const float2*)(vp + (size_t)c * HH);
        float2 v1 = *(const float2*)(vp + (size_t)(c + 1) * HH);
        #pragma unroll
        for (int k = 0; k < 4; k++) {
            float2 a2 = *(const float2*)(&aw[(kg * 4 + k) * 514 + c]);
            a0[k] += a2.x * v0.x + a2.y * v1.x;
            a1[k] += a2.x * v0.y + a2.y * v1.y;
        }
    }
    #pragma unroll
    for (int k = 0; k < 4; k++) {
        float inv = inv_sh[kg * 4 + k];
        size_t o = ((size_t)b * KC + kg * 4 + k) * HH + h0 + hg * 2;
        g_cc[o]     = a0[k] * inv;
        g_cc[o + 1] = a1[k] * inv;
    }
}

__global__ void ce_kernel() {
    int idx = blockIdx.x * 256 + threadIdx.x;
    float s = 0.f;
    for (int b = 0; b < BB; b++) s += g_cc[(size_t)b * KC * HH + idx];
    g_ce[idx] = s * (1.0f / BB);
}

// transpose per batch (h -> z) WITH fused LN-stats accumulation into accA
__global__ void transpose_stats_kernel(const float* __restrict__ in, float* __restrict__ out) {
    __shared__ float sh[32][33];
    int b = blockIdx.z;
    int i0 = blockIdx.y * 32, j0 = blockIdx.x * 32;
    const float* ib = in + (size_t)b * CC * HH;
    float* ob = out + (size_t)b * CC * HH;
    #pragma unroll
    for (int r = 0; r < 32; r += 8)
        sh[threadIdx.y + r][threadIdx.x] = ib[(size_t)(i0 + threadIdx.y + r) * HH + j0 + threadIdx.x];
    __syncthreads();
    #pragma unroll
    for (int r = 0; r < 32; r += 8) {
        float v = sh[threadIdx.x][threadIdx.y + r];
        ob[(size_t)(j0 + threadIdx.y + r) * HH + i0 + threadIdx.x] = v;
        float s = v, q = v * v;
        #pragma unroll
        for (int o = 16; o > 0; o >>= 1) {
            s += __shfl_xor_sync(0xffffffffu, s, o);
            q += __shfl_xor_sync(0xffffffffu, q, o);
        }
        if (threadIdx.x == 0) {
            int row = b * HH + j0 + threadIdx.y + r;
            atomicAdd(&g_accA[row], s);
            atomicAdd(&g_accA2[row], q);
        }
    }
}

// prod[b,c,h] = z[b,h,c] * theta[b,c,h], theta computed on the fly from p & ce
__global__ void prod_kernel() {
    __shared__ float sh[32][33];
    __shared__ float cesh[KC][32];
    __shared__ float psh[32][KC + 1];
    int b = blockIdx.z;
    int h0 = blockIdx.y * 32, c0 = blockIdx.x * 32;
    const float* zb = g_z + (size_t)b * HH * CC;
    float* ob = g_prod + (size_t)b * CC * HH;
    int tid = threadIdx.y * 32 + threadIdx.x;
    #pragma unroll
    for (int r = 0; r < 32; r += 8)
        sh[threadIdx.y + r][threadIdx.x] = zb[(size_t)(h0 + threadIdx.y + r) * CC + c0 + threadIdx.x];
    for (int t = tid; t < KC * 32; t += 256) {
        int k = t >> 5, xx = t & 31;
        cesh[k][xx] = g_ce[k * HH + h0 + xx];
    }
    for (int t = tid; t < 32 * KC; t += 256) {
        int c = t >> 4, k = t & 15;
        psh[c][k] = g_p[((size_t)b * CC + c0 + c) * KC + k];
    }
    __syncthreads();
    #pragma unroll
    for (int r = 0; r < 32; r += 8) {
        int cl = threadIdx.y + r;
        float th = 0.f;
        #pragma unroll
        for (int k = 0; k < KC; k++) th += psh[cl][k] * cesh[k][threadIdx.x];
        size_t o = (size_t)(c0 + cl) * HH + h0 + threadIdx.x;
        ob[o] = sh[threadIdx.x][cl] * th;
    }
}

// final: y[b,p,c] = denorm( sum_h prod[b,c,h]*out_w[c,h,p] + out_b[c,p] )
// block = 128 threads = 2 channels x 64 threads; thread = 4 batches x 12 p.
__global__ __launch_bounds__(128) void final_kernel(
    const float* __restrict__ out_w, const float* __restrict__ out_b,
    const float* __restrict__ rev_w, const float* __restrict__ rev_b,
    float* __restrict__ y) {
    __shared__ float As[2][32][33];
    __shared__ float Ws[2][32][PP];
    int tid = threadIdx.x;
    int cg = tid >> 6;                  // 0/1
    int t  = tid & 63;
    int c  = blockIdx.x * 2 + cg;
    int b4 = t >> 3;                    // batch group: batches 4*b4..4*b4+3
    int tp = (t & 7) * 12;              // p base
    float acc[4][12];
    #pragma unroll
    for (int k = 0; k < 4; k++)
        #pragma unroll
        for (int j = 0; j < 12; j++) acc[k][j] = 0.f;

    for (int h0 = 0; h0 < HH; h0 += 32) {
        // stage A: 32 batches x 32 h for this c (256 float4 / 64 threads)
        #pragma unroll
        for (int j = 0; j < 4; j++) {
            int u = j * 64 + t;
            int b = u >> 3, hq = (u & 7) * 4;
            float4 v = *(const float4*)(g_prod + ((size_t)b * CC + c) * HH + h0 + hq);
            As[cg][b][hq + 0] = v.x; As[cg][b][hq + 1] = v.y;
            As[cg][b][hq + 2] = v.z; As[cg][b][hq + 3] = v.w;
        }
        // stage W: 32 h x 96 p for this c (768 float4 / 64 threads)
        #pragma unroll
        for (int j = 0; j < 12; j++) {
            int u = j * 64 + t;
            int row = u / 24, col = (u % 24) * 4;
            *(float4*)&Ws[cg][row][col] =
                *(const float4*)(out_w + ((size_t)c * HH + h0 + row) * PP + col);
        }
        __syncthreads();
        #pragma unroll 4
        for (int i = 0; i < 32; i++) {
            float a0 = As[cg][b4 * 4 + 0][i];
            float a1 = As[cg][b4 * 4 + 1][i];
            float a2 = As[cg][b4 * 4 + 2][i];
            float a3 = As[cg][b4 * 4 + 3][i];
            const float4 w0 = *(const float4*)&Ws[cg][i][tp];
            const float4 w1 = *(const float4*)&Ws[cg][i][tp + 4];
            const float4 w2 = *(const float4*)&Ws[cg][i][tp + 8];
            const float wv[12] = {w0.x, w0.y, w0.z, w0.w, w1.x, w1.y, w1.z, w1.w,
                                  w2.x, w2.y, w2.z, w2.w};
            #pragma unroll
            for (int j = 0; j < 12; j++) {
                acc[0][j] += a0 * wv[j];
                acc[1][j] += a1 * wv[j];
                acc[2][j] += a2 * wv[j];
                acc[3][j] += a3 * wv[j];
            }
        }
        __syncthreads();
    }
    float rb = rev_b[c];
    float rwinv = 1.0f / (rev_w[c] + 1e-10f);
    #pragma unroll
    for (int k = 0; k < 4; k++) {
        int b = b4 * 4 + k;
        float sd = g_std[b * CC + c];
        float mn = g_mean[b * CC + c];
        #pragma unroll
        for (int j = 0; j < 12; j++) {
            float v = acc[k][j] + out_b[(size_t)c * PP + tp + j];
            v = (v - rb) * rwinv;
            v = v * sd + mn;
            y[((size_t)b * PP + tp + j) * CC + c] = v;
        }
    }
}

// ---------------- host orchestration ----------------
extern "C" void kernel_launch(void* const* d_in, const int* in_sizes, int n_in,
                              void* d_out, int out_size) {
    const float* x       = (const float*)d_in[0];
    const float* rev_w   = (const float*)d_in[1];
    const float* rev_b   = (const float*)d_in[2];
    const float* mlp_w1  = (const float*)d_in[3];
    const float* mlp_b1  = (const float*)d_in[4];
    const float* mlp_w2  = (const float*)d_in[5];
    const float* mlp_b2  = (const float*)d_in[6];
    const float* cle     = (const float*)d_in[7];
    const float* wq      = (const float*)d_in[8];
    const float* bq      = (const float*)d_in[9];
    const float* wk      = (const float*)d_in[10];
    const float* bk      = (const float*)d_in[11];
    const float* wv      = (const float*)d_in[12];
    const float* bv      = (const float*)d_in[13];
    const float* ts_ln_g = (const float*)d_in[14];
    const float* ts_ln_b = (const float*)d_in[15];
    const float* ts_w    = (const float*)d_in[16];
    const float* ts_b    = (const float*)d_in[17];
    const float* ch_ln_g = (const float*)d_in[18];
    const float* ch_ln_b = (const float*)d_in[19];
    const float* ch_w1   = (const float*)d_in[20];
    const float* ch_b1   = (const float*)d_in[21];
    const float* ch_w2   = (const float*)d_in[22];
    const float* ch_b2   = (const float*)d_in[23];
    const float* out_w   = (const float*)d_in[24];
    const float* out_b   = (const float*)d_in[25];
    float* y = (float*)d_out;

    float *p_xt, *p_t, *p_h, *p_kk, *p_v, *p_z, *p_z2, *p_w;
    cudaGetSymbolAddress((void**)&p_xt, g_xt);
    cudaGetSymbolAddress((void**)&p_t,  g_t);
    cudaGetSymbolAddress((void**)&p_h,  g_h);
    cudaGetSymbolAddress((void**)&p_kk, g_kk);
    cudaGetSymbolAddress((void**)&p_v,  g_v);
    cudaGetSymbolAddress((void**)&p_z,  g_z);
    cudaGetSymbolAddress((void**)&p_z2, g_z2);
    cudaGetSymbolAddress((void**)&p_w,  g_wts);

    const size_t WSZ = (size_t)GK * GN;
    float* w_mlp1 = p_w + 0 * WSZ;
    float* w_mlp2 = p_w + 1 * WSZ;
    float* w_k    = p_w + 2 * WSZ;
    float* w_v    = p_w + 3 * WSZ;
    float* w_ts   = p_w + 4 * WSZ;
    float* w_ch1  = p_w + 5 * WSZ;
    float* w_ch2  = p_w + 6 * WSZ;

    dim3 tgrid(16, 16, BB), tblk(32, 8);
    dim3 ggrid(GN / 128, ROWS / 128);
    dim3 ggrid2(GN / 128, ROWS / 128, 2);
    const int RWB = (int)(WSZ / 256);

    // 0) zero LN accumulators + pre-round all weights to tf32
    zacc_kernel<<<ROWS / 256, 256>>>();
    round_all_kernel<<<dim3(RWB, 7), 256>>>(mlp_w1, mlp_w2, wk, wv, ts_w, ch_w1, ch_w2);

    // 1) RevIN stats + normalized transpose
    revin_stats_kernel<<<dim3(CC / 256, BB), 256>>>(x);
    build_xt_kernel<<<tgrid, tblk>>>(x, rev_w, rev_b);

    // 2) channel MLP: h = relu(xt@w1+b1)@w2+b2
    gemm_tc<E_RELU, -1, -1, -1><<<ggrid, 256>>>(p_xt, w_mlp1, mlp_b1, nullptr, p_t,
                                                nullptr, nullptr, w_mlp1, mlp_b1, p_t);
    gemm_tc<E_BIAS, -1, -1, -1><<<ggrid, 256>>>(p_t, w_mlp2, mlp_b2, nullptr, p_h,
                                                nullptr, nullptr, w_mlp2, mlp_b2, p_h);

    // 3) routing (p + threefry bernoulli mask)
    cn_kernel<<<KC, 256>>>(cle);
    q_kernel<<<KC, 256>>>(cle, wq, bq);
    routing_kernel<<<ROWS / 8, 256>>>(p_h);

    // 4) K/V projections (ONE launch, grid.z selects) + attention + ce_new
    gemm_tc<E_BIAS, -1, -1, -1><<<ggrid2, 256>>>(p_h, w_k, bk, nullptr, p_kk,
                                                 nullptr, nullptr, w_v, bv, p_v);
    scores_kernel<<<ROWS / 8, 256>>>();
    vweight_kernel<<<dim3(BB, HH / 128), 256>>>();
    ce_kernel<<<KC * HH / 256, 256>>>();

    // 5) mixer with fully fused LN: stats ping-pong A (z) / B (z2).
    transpose_stats_kernel<<<tgrid, tblk>>>(p_h, p_z);
    for (int it = 0; it < NBITER; it++) {
        gemm_tc<E_RESGELU, 0, 1, -1><<<ggrid, 256>>>(p_z, w_ts, ts_b, p_z, p_z2,
                                                     ts_ln_g, ts_ln_b, w_ts, ts_b, p_z2);
        gemm_tc<E_GELU, 1, -1, 0><<<ggrid, 256>>>(p_z2, w_ch1, ch_b1, nullptr, p_t,
                                                  ch_ln_g, ch_ln_b, w_ch1, ch_b1, p_t);
        if (it < NBITER - 1)
            gemm_tc<E_RESBIAS, -1, 0, 1><<<ggrid, 256>>>(p_t, w_ch2, ch_b2, p_z2, p_z,
                                                         nullptr, nullptr, w_ch2, ch_b2, p_z);
        else
            gemm_tc<E_RESBIAS, -1, -1, -1><<<ggrid, 256>>>(p_t, w_ch2, ch_b2, p_z2, p_z,
                                                           nullptr, nullptr, w_ch2, ch_b2, p_z);
    }

    // 6) expert projection (theta fused) + RevIN denorm
    prod_kernel<<<tgrid, tblk>>>();
    final_kernel<<<CC / 2, 128>>>(out_w, out_b, rev_w, rev_b, y);
}

// round 13
// speedup vs baseline: 1.3752x; 1.0647x over previous
#include <cuda_runtime.h>
#include <math.h>
#include <stdint.h>

// ---------------- problem constants ----------------
#define BB 32
#define LL 512
#define CC 512
#define HH 512
#define KC 16          // clusters
#define PP 96
#define NBITER 4
#define ROWS (BB*CC)   // 16384
#define EPSV 1e-5f
#define GN 512         // GEMM N (all GEMMs are 16384x512x512)
#define GK 512         // GEMM K

// ---------------- scratch (static device globals; no allocation) ----------------
__device__ float g_xt   [(size_t)ROWS*HH];
__device__ float g_t    [(size_t)ROWS*HH];
__device__ float g_h    [(size_t)ROWS*HH];
__device__ float g_kk   [(size_t)ROWS*HH];
__device__ float g_v    [(size_t)ROWS*HH];
__device__ float g_z    [(size_t)ROWS*HH];
__device__ float g_z2   [(size_t)ROWS*HH];
__device__ float g_prod [(size_t)ROWS*HH];
__device__ float g_wts  [(size_t)7*GK*GN];    // tf32-rounded weights
__device__ float g_mean [ROWS];
__device__ float g_std  [ROWS];
__device__ float g_accA [ROWS];   // LN stats (sum) for z
__device__ float g_accA2[ROWS];   // LN stats (sumsq) for z
__device__ float g_accB [ROWS];   // LN stats (sum) for z2
__device__ float g_accB2[ROWS];   // LN stats (sumsq) for z2
__device__ float g_cn   [KC*HH];
__device__ float g_q    [KC*HH];
__device__ float g_p    [ROWS*KC];
__device__ float g_mask [ROWS*KC];
__device__ float g_am   [ROWS*KC];
__device__ float g_cc   [BB*KC*HH];
__device__ float g_ce   [KC*HH];

// ---------------- helpers ----------------
__device__ __forceinline__ float gelu_f(float x) {
    return 0.5f * x * (1.0f + erff(x * 0.7071067811865476f));
}

__device__ __forceinline__ float f2tf32(float x) {
    uint32_t r;
    asm("cvt.rna.tf32.f32 %0, %1;" : "=r"(r) : "f"(x));
    return __uint_as_float(r);
}

__device__ __forceinline__ void cp16(uint32_t dst_smem, const void* src) {
    asm volatile("cp.async.ca.shared.global [%0], [%1], 16;"
                 :: "r"(dst_smem), "l"(src) : "memory");
}
__device__ __forceinline__ void cp_commit() {
    asm volatile("cp.async.commit_group;" ::: "memory");
}
template<int N>
__device__ __forceinline__ void cp_waitg() {
    asm volatile("cp.async.wait_group %0;" :: "n"(N) : "memory");
}

__device__ __forceinline__ uint32_t rotl32(uint32_t x, uint32_t d) {
    return (x << d) | (x >> (32u - d));
}

// JAX threefry2x32, PARTITIONABLE path. key = {0,42}; counter (0, idx);
// output word = out0 ^ out1.
__device__ uint32_t threefry_rand(uint32_t idx) {
    uint32_t x0 = 0u, x1 = idx;
    const uint32_t k0 = 0u, k1 = 42u;
    const uint32_t k2 = k0 ^ k1 ^ 0x1BD11BDAu;
    uint32_t ks[3] = {k0, k1, k2};
    x0 += ks[0]; x1 += ks[1];
    const uint32_t R[2][4] = {{13u,15u,26u,6u},{17u,29u,16u,24u}};
    #pragma unroll
    for (int i = 0; i < 5; i++) {
        #pragma unroll
        for (int j = 0; j < 4; j++) {
            x0 += x1; x1 = rotl32(x1, R[i & 1][j]); x1 ^= x0;
        }
        x0 += ks[(i + 1) % 3];
        x1 += ks[(i + 2) % 3] + (uint32_t)(i + 1);
    }
    return x0 ^ x1;
}

// ---------------- zero LN accumulators (once) ----------------
__global__ void zacc_kernel() {
    int i = blockIdx.x * 256 + threadIdx.x;
    g_accA[i] = 0.f;
    g_accA2[i] = 0.f;
    g_accB[i] = 0.f;
    g_accB2[i] = 0.f;
}

// ---------------- weight pre-round: all 7 matrices in one launch ----------------
__global__ void round_all_kernel(const float* s0, const float* s1, const float* s2,
                                 const float* s3, const float* s4, const float* s5,
                                 const float* s6) {
    int i = blockIdx.x * 256 + threadIdx.x;
    const float* s;
    switch (blockIdx.y) {
        case 0: s = s0; break; case 1: s = s1; break; case 2: s = s2; break;
        case 3: s = s3; break; case 4: s = s4; break; case 5: s = s5; break;
        default: s = s6; break;
    }
    g_wts[(size_t)blockIdx.y * GK * GN + i] = f2tf32(s[i]);
}

// ---------------- RevIN stats ----------------
__global__ void revin_stats_kernel(const float* __restrict__ x) {
    int b = blockIdx.y;
    int c = blockIdx.x * 256 + threadIdx.x;
    float s = 0.f, s2 = 0.f;
    const float* xp = x + (size_t)b * LL * CC + c;
    for (int l = 0; l < LL; l++) {
        float v = xp[(size_t)l * CC];
        s += v; s2 += v * v;
    }
    float m = s * (1.0f / LL);
    float var = fmaxf(s2 * (1.0f / LL) - m * m, 0.0f);
    g_mean[b * CC + c] = m;
    g_std [b * CC + c] = sqrtf(var + EPSV);
}

// xt[b,c,l] = (x[b,l,c]-mean)/std*rev_w[c]+rev_b[c]   (tiled transpose)
__global__ void build_xt_kernel(const float* __restrict__ x,
                                const float* __restrict__ rev_w,
                                const float* __restrict__ rev_b) {
    __shared__ float sh[32][33];
    int b = blockIdx.z;
    int l0 = blockIdx.x * 32, c0 = blockIdx.y * 32;
    const float* xb = x + (size_t)b * LL * CC;
    float* ob = g_xt + (size_t)b * CC * LL;
    #pragma unroll
    for (int r = 0; r < 32; r += 8)
        sh[threadIdx.y + r][threadIdx.x] = xb[(size_t)(l0 + threadIdx.y + r) * CC + c0 + threadIdx.x];
    __syncthreads();
    #pragma unroll
    for (int r = 0; r < 32; r += 8) {
        int c = c0 + threadIdx.y + r;
        float mn = g_mean[b * CC + c];
        float sd = g_std[b * CC + c];
        float v = sh[threadIdx.x][threadIdx.y + r];
        ob[(size_t)c * LL + l0 + threadIdx.x] = (v - mn) / sd * rev_w[c] + rev_b[c];
    }
}

// ---------------- TF32 tensor-core GEMM, K-tile 16, 3-stage cp.async B ----
// Conflict-free smem layouts:
//  A: word(m,k) = m*16 + ((j^sw)<<2) + (2*akbit ^ (m&2)) + half,
//     j=k&3 (of low-8 k), half=(k>>2)&1, akbit=k>>3, sw=(m>>1)&3.
//  B: row stride 136 (bank = (8*tig+gid)%32, bijective).
#define E_RELU    0
#define E_BIAS    1
#define E_GELU    2
#define E_RESGELU 3
#define E_RESBIAS 4

#define ASZ (128*16)   // A buffer floats
#define BSTR 136       // B row stride (words)
#define BSZ (16*BSTR)  // B buffer floats

__device__ __forceinline__ void mma_tf32(float c[4],
                                         uint32_t a0, uint32_t a1, uint32_t a2, uint32_t a3,
                                         uint32_t b0, uint32_t b1) {
    asm volatile(
        "mma.sync.aligned.m16n8k8.row.col.f32.tf32.tf32.f32 "
        "{%0,%1,%2,%3}, {%4,%5,%6,%7}, {%8,%9}, {%0,%1,%2,%3};"
        : "+f"(c[0]), "+f"(c[1]), "+f"(c[2]), "+f"(c[3])
        : "r"(a0), "r"(a1), "r"(a2), "r"(a3), "r"(b0), "r"(b1));
}

template<int EPI, int LNBUF, int SBUF, int ZBUF>
__global__ __launch_bounds__(256, 2) void gemm_tc(
    const float* __restrict__ A, const float* __restrict__ W,
    const float* __restrict__ bias, const float* __restrict__ res,
    float* __restrict__ out,
    const float* __restrict__ ln_g, const float* __restrict__ ln_b,
    const float* __restrict__ W2, const float* __restrict__ bias2,
    float* __restrict__ out2) {
    __shared__ float As[2 * ASZ];
    __shared__ float Bs[3 * BSZ];
    if (blockIdx.z) { W = W2; bias = bias2; out = out2; }
    const int tid = threadIdx.x;
    const int warp = tid >> 5, lane = tid & 31;
    const int wm = (warp >> 2) * 64;    // warp M offset: 0 or 64
    const int wn = (warp & 3) * 32;     // warp N offset: 0,32,64,96
    const int gid = lane >> 2;          // 0..7
    const int tig = lane & 3;           // 0..3
    const int bx = blockIdx.x, by = blockIdx.y;

    const int arow = tid >> 1;          // 0..127
    const int ak   = (tid & 1) * 8;     // 0 or 8
    const int ssw  = (arow >> 1) & 3;   // store swizzle
    const int soff = (ak >> 2) ^ (arow & 2);  // ks-slot offset with m&2 XOR
    const int brow = tid >> 5;          // 0..7
    const int bn   = lane * 4;          // 0..124

    if (ZBUF >= 0) {
        if (bx == 0 && blockIdx.z == 0 && tid < 128) {
            int row = by * 128 + tid;
            if (ZBUF == 0) { g_accA[row] = 0.f; g_accA2[row] = 0.f; }
            else           { g_accB[row] = 0.f; g_accB2[row] = 0.f; }
        }
    }

    float acc[4][4][4];
    #pragma unroll
    for (int i = 0; i < 4; i++)
        #pragma unroll
        for (int j = 0; j < 4; j++)
            #pragma unroll
            for (int r = 0; r < 4; r++) acc[i][j][r] = 0.f;

    const float* Ap  = A + (size_t)(by * 128 + arow) * GK + ak;
    const float* Wp0 = W + (size_t)brow * GN + bx * 128 + bn;

    const uint32_t bdst = (uint32_t)__cvta_generic_to_shared(Bs + brow * BSTR + bn);

    float mu = 0.f, rsd = 1.f;
    if (LNBUF >= 0) {
        int row = by * 128 + arow;
        float s  = (LNBUF == 0) ? g_accA[row]  : g_accB[row];
        float s2 = (LNBUF == 0) ? g_accA2[row] : g_accB2[row];
        mu = s * (1.0f / CC);
        float var = fmaxf(s2 * (1.0f / CC) - mu * mu, 0.0f);
        rsd = rsqrtf(var + EPSV);
    }

    const int NT = GK >> 4;

    auto issueB = [&](int buf, int kt) {
        const float* ws = Wp0 + (size_t)kt * 16 * GN;
        uint32_t d = bdst + (uint32_t)buf * (BSZ * 4);
        cp16(d, ws);
        cp16(d + 8 * BSTR * 4, ws + (size_t)8 * GN);
        cp_commit();
    };

    float4 pa0, pa1;
    auto loadA = [&](int kt) {
        pa0 = *(const float4*)(Ap + kt * 16);
        pa1 = *(const float4*)(Ap + kt * 16 + 4);
    };

    auto store_tileA = [&](int buf, int kt) {
        float va[8] = {pa0.x, pa0.y, pa0.z, pa0.w, pa1.x, pa1.y, pa1.z, pa1.w};
        if (LNBUF >= 0) {
            const float* gp = ln_g + kt * 16 + ak;
            const float* bp = ln_b + kt * 16 + ak;
            #pragma unroll
            for (int j = 0; j < 8; j++) {
                float t = rsd * gp[j];
                va[j] = (va[j] - mu) * t + bp[j];
            }
        }
        float* Ab = As + buf * ASZ;
        const int abase = arow * 16 + soff;
        #pragma unroll
        for (int j = 0; j < 4; j++) {
            *(float2*)(Ab + abase + ((j ^ ssw) << 2)) = make_float2(va[j], va[j + 4]);
        }
    };

    auto compute = [&](int abuf, int bbuf) {
        const float* Ab = As + abuf * ASZ;
        const float* Bb = Bs + bbuf * BSZ;
        #pragma unroll
        for (int ks = 0; ks < 2; ks++) {
            float2 fa0[4], fa1[4];
            #pragma unroll
            for (int i = 0; i < 4; i++) {
                int m0 = wm + i * 16 + gid;
                int sw = (m0 >> 1) & 3;
                int w = m0 * 16 + ((tig ^ sw) << 2) + ((ks * 2) ^ (m0 & 2));
                fa0[i] = *(const float2*)(Ab + w);
                fa1[i] = *(const float2*)(Ab + w + 128);   // row m0+8: same swizzle
            }
            float fb0[4], fb1[4];
            #pragma unroll
            for (int j = 0; j < 4; j++) {
                int n0 = wn + j * 8 + gid;
                fb0[j] = Bb[(ks * 8 + tig) * BSTR + n0];
                fb1[j] = Bb[(ks * 8 + tig + 4) * BSTR + n0];
            }
            #pragma unroll
            for (int i = 0; i < 4; i++)
                #pragma unroll
                for (int j = 0; j < 4; j++)
                    mma_tf32(acc[i][j],
                             __float_as_uint(fa0[i].x), __float_as_uint(fa1[i].x),
                             __float_as_uint(fa0[i].y), __float_as_uint(fa1[i].y),
                             __float_as_uint(fb0[j]), __float_as_uint(fb1[j]));
        }
    };

    // prologue: B0 and B1 in flight, A0 staged, A1 in registers
    issueB(0, 0);
    issueB(1, 1);
    loadA(0);
    store_tileA(0, 0);
    loadA(1);
    cp_waitg<1>();          // B0 complete (B1 may be outstanding)
    __syncthreads();

    int bcur = 0;
    for (int kt = 0; kt < NT; kt++) {
        const int acur = kt & 1;
        int bn2 = bcur + 2; if (bn2 >= 3) bn2 -= 3;
        if (kt + 2 < NT) issueB(bn2, kt + 2);
        compute(acur, bcur);
        if (kt + 1 < NT) {
            store_tileA(acur ^ 1, kt + 1);
            if (kt + 2 < NT) loadA(kt + 2);
        }
        if (kt + 2 < NT) cp_waitg<1>(); else cp_waitg<0>();
        __syncthreads();
        bcur++; if (bcur >= 3) bcur -= 3;
    }

    // epilogue (+ optional fused LN-stats accumulation of the OUTPUT rows)
    #pragma unroll
    for (int i = 0; i < 4; i++) {
        int gr0 = by * 128 + wm + i * 16 + gid;
        int gr1 = gr0 + 8;
        float slo = 0.f, qlo = 0.f, shi = 0.f, qhi = 0.f;
        #pragma unroll
        for (int j = 0; j < 4; j++) {
            int gc = bx * 128 + wn + j * 8 + 2 * tig;
            float b0v = bias[gc], b1v = bias[gc + 1];
            float v0 = acc[i][j][0] + b0v, v1 = acc[i][j][1] + b1v;
            float v2 = acc[i][j][2] + b0v, v3 = acc[i][j][3] + b1v;
            if (EPI == E_RELU) {
                v0 = fmaxf(v0, 0.f); v1 = fmaxf(v1, 0.f);
                v2 = fmaxf(v2, 0.f); v3 = fmaxf(v3, 0.f);
            } else if (EPI == E_GELU) {
                v0 = gelu_f(v0); v1 = gelu_f(v1);
                v2 = gelu_f(v2); v3 = gelu_f(v3);
            } else if (EPI == E_RESGELU) {
                const float2 r0 = *(const float2*)(res + (size_t)gr0 * GN + gc);
                const float2 r1 = *(const float2*)(res + (size_t)gr1 * GN + gc);
                v0 = r0.x + gelu_f(v0); v1 = r0.y + gelu_f(v1);
                v2 = r1.x + gelu_f(v2); v3 = r1.y + gelu_f(v3);
            } else if (EPI == E_RESBIAS) {
                const float2 r0 = *(const float2*)(res + (size_t)gr0 * GN + gc);
                const float2 r1 = *(const float2*)(res + (size_t)gr1 * GN + gc);
                v0 += r0.x; v1 += r0.y; v2 += r1.x; v3 += r1.y;
            }
            if (SBUF >= 0) {
                slo += v0 + v1; qlo += v0 * v0 + v1 * v1;
                shi += v2 + v3; qhi += v2 * v2 + v3 * v3;
            }
            *(float2*)(out + (size_t)gr0 * GN + gc) = make_float2(v0, v1);
            *(float2*)(out + (size_t)gr1 * GN + gc) = make_float2(v2, v3);
        }
        if (SBUF >= 0) {
            slo += __shfl_xor_sync(0xffffffffu, slo, 1);
            slo += __shfl_xor_sync(0xffffffffu, slo, 2);
            qlo += __shfl_xor_sync(0xffffffffu, qlo, 1);
            qlo += __shfl_xor_sync(0xffffffffu, qlo, 2);
            shi += __shfl_xor_sync(0xffffffffu, shi, 1);
            shi += __shfl_xor_sync(0xffffffffu, shi, 2);
            qhi += __shfl_xor_sync(0xffffffffu, qhi, 1);
            qhi += __shfl_xor_sync(0xffffffffu, qhi, 2);
            if (tig == 0) {
                float* a  = (SBUF == 0) ? g_accA  : g_accB;
                float* a2 = (SBUF == 0) ? g_accA2 : g_accB2;
                atomicAdd(&a[gr0], slo);
                atomicAdd(&a2[gr0], qlo);
                atomicAdd(&a[gr1], shi);
                atomicAdd(&a2[gr1], qhi);
            }
        }
    }
}

// ---------------- cluster normalize (cn) ----------------
__global__ void cn_kernel(const float* __restrict__ ce) {
    __shared__ float red[256];
    int k = blockIdx.x, tid = threadIdx.x;
    float v0 = ce[k * HH + tid], v1 = ce[k * HH + tid + 256];
    red[tid] = v0 * v0 + v1 * v1;
    __syncthreads();
    for (int off = 128; off > 0; off >>= 1) {
        if (tid < off) red[tid] += red[tid + off];
        __syncthreads();
    }
    float nrm = fmaxf(sqrtf(red[0]), 1e-12f);
    g_cn[k * HH + tid] = v0 / nrm;
    g_cn[k * HH + tid + 256] = v1 / nrm;
}

// ---------------- Q = cluster_embeds @ wq + bq ----------------
__global__ void q_kernel(const float* __restrict__ ce,
                         const float* __restrict__ wq,
                         const float* __restrict__ bq) {
    __shared__ float csh[HH];
    int k = blockIdx.x, tid = threadIdx.x;
    csh[tid] = ce[k * HH + tid];
    csh[tid + 256] = ce[k * HH + tid + 256];
    __syncthreads();
    for (int n = tid; n < HH; n += 256) {
        float a = bq[n];
        for (int h = 0; h < HH; h++) a += csh[h] * wq[(size_t)h * HH + n];
        g_q[k * HH + n] = a;
    }
}

// ---------------- routing: warp per row; p = softmax(hn @ cn^T), bernoulli mask
__global__ __launch_bounds__(256) void routing_kernel(const float* __restrict__ h) {
    __shared__ float cnsh[KC * HH];   // 32KB
    int tid = threadIdx.x;
    for (int i = tid; i < KC * HH; i += 256) cnsh[i] = g_cn[i];
    __syncthreads();
    int w = tid >> 5, lane = tid & 31;
    int row = blockIdx.x * 8 + w;
    const float* hp = h + (size_t)row * HH;
    float acc[KC];
    #pragma unroll
    for (int k = 0; k < KC; k++) acc[k] = 0.f;
    float nsq = 0.f;
    #pragma unroll 4
    for (int i = 0; i < 16; i++) {
        int hh = i * 32 + lane;
        float hv = hp[hh];
        nsq += hv * hv;
        #pragma unroll
        for (int k = 0; k < KC; k++) acc[k] += hv * cnsh[k * HH + hh];
    }
    #pragma unroll
    for (int o = 16; o > 0; o >>= 1) nsq += __shfl_xor_sync(0xffffffffu, nsq, o);
    #pragma unroll
    for (int k = 0; k < KC; k++) {
        #pragma unroll
        for (int o = 16; o > 0; o >>= 1)
            acc[k] += __shfl_xor_sync(0xffffffffu, acc[k], o);
    }
    float inv = 1.0f / fmaxf(sqrtf(nsq), 1e-12f);
    float d = 0.f;
    #pragma unroll
    for (int k = 0; k < KC; k++) if (lane == k) d = acc[k];
    d *= inv;
    float mx = d;
    #pragma unroll
    for (int o = 8; o > 0; o >>= 1)
        mx = fmaxf(mx, __shfl_xor_sync(0xffffffffu, mx, o, 16));
    float e = expf(d - mx);
    float tot = e;
    #pragma unroll
    for (int o = 8; o > 0; o >>= 1)
        tot += __shfl_xor_sync(0xffffffffu, tot, o, 16);
    if (lane < KC) {
        float pv = e / tot;
        int idx = row * KC + lane;
        g_p[idx] = pv;
        uint32_t bits = threefry_rand((uint32_t)idx);
        float u = __uint_as_float((bits >> 9) | 0x3f800000u) - 1.0f;
        g_mask[idx] = (u < pv) ? 1.0f : 0.0f;
    }
}

// ---------------- attention phase 1: am = exp(score)*mask per row ----------------
__global__ __launch_bounds__(256) void scores_kernel() {
    __shared__ float qsh[KC * HH];   // [k][h], 32KB
    int tid = threadIdx.x;
    for (int i = tid; i < KC * HH; i += 256) qsh[i] = g_q[i];
    __syncthreads();
    int w = tid >> 5, lane = tid & 31;
    int row = blockIdx.x * 8 + w;
    const float* kp = g_kk + (size_t)row * HH;
    float acc[KC];
    #pragma unroll
    for (int k = 0; k < KC; k++) acc[k] = 0.f;
    #pragma unroll 4
    for (int i = 0; i < 16; i++) {
        int hh = i * 32 + lane;
        float kv = kp[hh];
        #pragma unroll
        for (int k = 0; k < KC; k++) acc[k] += kv * qsh[k * HH + hh];
    }
    #pragma unroll
    for (int k = 0; k < KC; k++) {
        #pragma unroll
        for (int o = 16; o > 0; o >>= 1)
            acc[k] += __shfl_xor_sync(0xffffffffu, acc[k], o);
    }
    if (lane < KC) {
        float am = expf(acc[lane] * 0.04419417382415922f) * g_mask[row * KC + lane];
        g_am[row * KC + lane] = am;
    }
}

// ---------------- attention: Cc[b][k][h] = sum_c am*V / sum_c am (sums in-block) ----
__global__ __launch_bounds__(256) void vweight_kernel() {
    __shared__ float aw[KC * 514];
    __shared__ float part[KC][17];
    __shared__ float inv_sh[KC];
    int b = blockIdx.x, h0 = blockIdx.y * 128;
    int tid = threadIdx.x;
    for (int idx = tid; idx < CC * KC; idx += 256) {
        int c = idx >> 4, k = idx & 15;
        aw[k * 514 + c] = g_am[((size_t)b * CC + c) * KC + k];
    }
    __syncthreads();
    {
        int k = tid & 15, ci = tid >> 4;  // ci 0..15
        float ps = 0.f;
        for (int c = ci; c < CC; c += 16) ps += aw[k * 514 + c];
        part[k][ci] = ps;
    }
    __syncthreads();
    if (tid < KC) {
        float s = 0.f;
        #pragma unroll
        for (int i = 0; i < 16; i++) s += part[tid][i];
        inv_sh[tid] = 1.0f / s;
    }
    __syncthreads();
    int kg = tid >> 6;
    int hg = tid & 63;
    const float* vp = g_v + (size_t)b * CC * HH + h0 + hg * 2;
    float a0[4], a1[4];
    #pragma unroll
    for (int k = 0; k < 4; k++) { a0[k] = 0.f; a1[k] = 0.f; }
    for (int c = 0; c < CC; c += 2) {
        float2 v0 = *(const float2*)(vp + (size_t)c * HH);
        float2 v1 = *(const float2*)(vp + (size_t)(c + 1) * HH);
        #pragma unroll
        for (int k = 0; k < 4; k++) {
            float2 a2 = *(const float2*)(&aw[(kg * 4 + k) * 514 + c]);
            a0[k] += a2.x * v0.x + a2.y * v1.x;
            a1[k] += a2.x * v0.y + a2.y * v1.y;
        }
    }
    #pragma unroll
    for (int k = 0; k < 4; k++) {
        float inv = inv_sh[kg * 4 + k];
        size_t o = ((size_t)b * KC + kg * 4 + k) * HH + h0 + hg * 2;
        g_cc[o]     = a0[k] * inv;
        g_cc[o + 1] = a1[k] * inv;
    }
}

__global__ void ce_kernel() {
    int idx = blockIdx.x * 256 + threadIdx.x;
    float s = 0.f;
    for (int b = 0; b < BB; b++) s += g_cc[(size_t)b * KC * HH + idx];
    g_ce[idx] = s * (1.0f / BB);
}

// transpose per batch (h -> z) WITH fused LN-stats accumulation into accA
__global__ void transpose_stats_kernel(const float* __restrict__ in, float* __restrict__ out) {
    __shared__ float sh[32][33];
    int b = blockIdx.z;
    int i0 = blockIdx.y * 32, j0 = blockIdx.x * 32;
    const float* ib = in + (size_t)b * CC * HH;
    float* ob = out + (size_t)b * CC * HH;
    #pragma unroll
    for (int r = 0; r < 32; r += 8)
        sh[threadIdx.y + r][threadIdx.x] = ib[(size_t)(i0 + threadIdx.y + r) * HH + j0 + threadIdx.x];
    __syncthreads();
    #pragma unroll
    for (int r = 0; r < 32; r += 8) {
        float v = sh[threadIdx.x][threadIdx.y + r];
        ob[(size_t)(j0 + threadIdx.y + r) * HH + i0 + threadIdx.x] = v;
        float s = v, q = v * v;
        #pragma unroll
        for (int o = 16; o > 0; o >>= 1) {
            s += __shfl_xor_sync(0xffffffffu, s, o);
            q += __shfl_xor_sync(0xffffffffu, q, o);
        }
        if (threadIdx.x == 0) {
            int row = b * HH + j0 + threadIdx.y + r;
            atomicAdd(&g_accA[row], s);
            atomicAdd(&g_accA2[row], q);
        }
    }
}

// prod[b,c,h] = z[b,h,c] * theta[b,c,h], theta computed on the fly from p & ce
__global__ void prod_kernel() {
    __shared__ float sh[32][33];
    __shared__ float cesh[KC][32];
    __shared__ float psh[32][KC + 1];
    int b = blockIdx.z;
    int h0 = blockIdx.y * 32, c0 = blockIdx.x * 32;
    const float* zb = g_z + (size_t)b * HH * CC;
    float* ob = g_prod + (size_t)b * CC * HH;
    int tid = threadIdx.y * 32 + threadIdx.x;
    #pragma unroll
    for (int r = 0; r < 32; r += 8)
        sh[threadIdx.y + r][threadIdx.x] = zb[(size_t)(h0 + threadIdx.y + r) * CC + c0 + threadIdx.x];
    for (int t = tid; t < KC * 32; t += 256) {
        int k = t >> 5, xx = t & 31;
        cesh[k][xx] = g_ce[k * HH + h0 + xx];
    }
    for (int t = tid; t < 32 * KC; t += 256) {
        int c = t >> 4, k = t & 15;
        psh[c][k] = g_p[((size_t)b * CC + c0 + c) * KC + k];
    }
    __syncthreads();
    #pragma unroll
    for (int r = 0; r < 32; r += 8) {
        int cl = threadIdx.y + r;
        float th = 0.f;
        #pragma unroll
        for (int k = 0; k < KC; k++) th += psh[cl][k] * cesh[k][threadIdx.x];
        size_t o = (size_t)(c0 + cl) * HH + h0 + threadIdx.x;
        ob[o] = sh[threadIdx.x][cl] * th;
    }
}

// final: y[b,p,c] = denorm( sum_h prod[b,c,h]*out_w[c,h,p] + out_b[c,p] )
// block = 128 threads = 2 channels x 64 threads; thread = 4 batches x 12 p.
__global__ __launch_bounds__(128) void final_kernel(
    const float* __restrict__ out_w, const float* __restrict__ out_b,
    const float* __restrict__ rev_w, const float* __restrict__ rev_b,
    float* __restrict__ y) {
    __shared__ float As[2][32][33];
    __shared__ float Ws[2][32][PP];
    int tid = threadIdx.x;
    int cg = tid >> 6;                  // 0/1
    int t  = tid & 63;
    int c  = blockIdx.x * 2 + cg;
    int b4 = t >> 3;                    // batch group: batches 4*b4..4*b4+3
    int tp = (t & 7) * 12;              // p base
    float acc[4][12];
    #pragma unroll
    for (int k = 0; k < 4; k++)
        #pragma unroll
        for (int j = 0; j < 12; j++) acc[k][j] = 0.f;

    for (int h0 = 0; h0 < HH; h0 += 32) {
        #pragma unroll
        for (int j = 0; j < 4; j++) {
            int u = j * 64 + t;
            int b = u >> 3, hq = (u & 7) * 4;
            float4 v = *(const float4*)(g_prod + ((size_t)b * CC + c) * HH + h0 + hq);
            As[cg][b][hq + 0] = v.x; As[cg][b][hq + 1] = v.y;
            As[cg][b][hq + 2] = v.z; As[cg][b][hq + 3] = v.w;
        }
        #pragma unroll
        for (int j = 0; j < 12; j++) {
            int u = j * 64 + t;
            int row = u / 24, col = (u % 24) * 4;
            *(float4*)&Ws[cg][row][col] =
                *(const float4*)(out_w + ((size_t)c * HH + h0 + row) * PP + col);
        }
        __syncthreads();
        #pragma unroll 4
        for (int i = 0; i < 32; i++) {
            float a0 = As[cg][b4 * 4 + 0][i];
            float a1 = As[cg][b4 * 4 + 1][i];
            float a2 = As[cg][b4 * 4 + 2][i];
            float a3 = As[cg][b4 * 4 + 3][i];
            const float4 w0 = *(const float4*)&Ws[cg][i][tp];
            const float4 w1 = *(const float4*)&Ws[cg][i][tp + 4];
            const float4 w2 = *(const float4*)&Ws[cg][i][tp + 8];
            const float wv[12] = {w0.x, w0.y, w0.z, w0.w, w1.x, w1.y, w1.z, w1.w,
                                  w2.x, w2.y, w2.z, w2.w};
            #pragma unroll
            for (int j = 0; j < 12; j++) {
                acc[0][j] += a0 * wv[j];
                acc[1][j] += a1 * wv[j];
                acc[2][j] += a2 * wv[j];
                acc[3][j] += a3 * wv[j];
            }
        }
        __syncthreads();
    }
    float rb = rev_b[c];
    float rwinv = 1.0f / (rev_w[c] + 1e-10f);
    #pragma unroll
    for (int k = 0; k < 4; k++) {
        int b = b4 * 4 + k;
        float sd = g_std[b * CC + c];
        float mn = g_mean[b * CC + c];
        #pragma unroll
        for (int j = 0; j < 12; j++) {
            float v = acc[k][j] + out_b[(size_t)c * PP + tp + j];
            v = (v - rb) * rwinv;
            v = v * sd + mn;
            y[((size_t)b * PP + tp + j) * CC + c] = v;
        }
    }
}

// ---------------- host orchestration ----------------
extern "C" void kernel_launch(void* const* d_in, const int* in_sizes, int n_in,
                              void* d_out, int out_size) {
    const float* x       = (const float*)d_in[0];
    const float* rev_w   = (const float*)d_in[1];
    const float* rev_b   = (const float*)d_in[2];
    const float* mlp_w1  = (const float*)d_in[3];
    const float* mlp_b1  = (const float*)d_in[4];
    const float* mlp_w2  = (const float*)d_in[5];
    const float* mlp_b2  = (const float*)d_in[6];
    const float* cle     = (const float*)d_in[7];
    const float* wq      = (const float*)d_in[8];
    const float* bq      = (const float*)d_in[9];
    const float* wk      = (const float*)d_in[10];
    const float* bk      = (const float*)d_in[11];
    const float* wv      = (const float*)d_in[12];
    const float* bv      = (const float*)d_in[13];
    const float* ts_ln_g = (const float*)d_in[14];
    const float* ts_ln_b = (const float*)d_in[15];
    const float* ts_w    = (const float*)d_in[16];
    const float* ts_b    = (const float*)d_in[17];
    const float* ch_ln_g = (const float*)d_in[18];
    const float* ch_ln_b = (const float*)d_in[19];
    const float* ch_w1   = (const float*)d_in[20];
    const float* ch_b1   = (const float*)d_in[21];
    const float* ch_w2   = (const float*)d_in[22];
    const float* ch_b2   = (const float*)d_in[23];
    const float* out_w   = (const float*)d_in[24];
    const float* out_b   = (const float*)d_in[25];
    float* y = (float*)d_out;

    float *p_xt, *p_t, *p_h, *p_kk, *p_v, *p_z, *p_z2, *p_w;
    cudaGetSymbolAddress((void**)&p_xt, g_xt);
    cudaGetSymbolAddress((void**)&p_t,  g_t);
    cudaGetSymbolAddress((void**)&p_h,  g_h);
    cudaGetSymbolAddress((void**)&p_kk, g_kk);
    cudaGetSymbolAddress((void**)&p_v,  g_v);
    cudaGetSymbolAddress((void**)&p_z,  g_z);
    cudaGetSymbolAddress((void**)&p_z2, g_z2);
    cudaGetSymbolAddress((void**)&p_w,  g_wts);

    const size_t WSZ = (size_t)GK * GN;
    float* w_mlp1 = p_w + 0 * WSZ;
    float* w_mlp2 = p_w + 1 * WSZ;
    float* w_k    = p_w + 2 * WSZ;
    float* w_v    = p_w + 3 * WSZ;
    float* w_ts   = p_w + 4 * WSZ;
    float* w_ch1  = p_w + 5 * WSZ;
    float* w_ch2  = p_w + 6 * WSZ;

    dim3 tgrid(16, 16, BB), tblk(32, 8);
    dim3 ggrid(GN / 128, ROWS / 128);
    dim3 ggrid2(GN / 128, ROWS / 128, 2);
    const int RWB = (int)(WSZ / 256);

    // 0) zero LN accumulators + pre-round all weights to tf32
    zacc_kernel<<<ROWS / 256, 256>>>();
    round_all_kernel<<<dim3(RWB, 7), 256>>>(mlp_w1, mlp_w2, wk, wv, ts_w, ch_w1, ch_w2);

    // 1) RevIN stats + normalized transpose
    revin_stats_kernel<<<dim3(CC / 256, BB), 256>>>(x);
    build_xt_kernel<<<tgrid, tblk>>>(x, rev_w, rev_b);

    // 2) channel MLP: h = relu(xt@w1+b1)@w2+b2
    gemm_tc<E_RELU, -1, -1, -1><<<ggrid, 256>>>(p_xt, w_mlp1, mlp_b1, nullptr, p_t,
                                                nullptr, nullptr, w_mlp1, mlp_b1, p_t);
    gemm_tc<E_BIAS, -1, -1, -1><<<ggrid, 256>>>(p_t, w_mlp2, mlp_b2, nullptr, p_h,
                                                nullptr, nullptr, w_mlp2, mlp_b2, p_h);

    // 3) routing (p + threefry bernoulli mask)
    cn_kernel<<<KC, 256>>>(cle);
    q_kernel<<<KC, 256>>>(cle, wq, bq);
    routing_kernel<<<ROWS / 8, 256>>>(p_h);

    // 4) K/V projections (ONE launch, grid.z selects) + attention + ce_new
    gemm_tc<E_BIAS, -1, -1, -1><<<ggrid2, 256>>>(p_h, w_k, bk, nullptr, p_kk,
                                                 nullptr, nullptr, w_v, bv, p_v);
    scores_kernel<<<ROWS / 8, 256>>>();
    vweight_kernel<<<dim3(BB, HH / 128), 256>>>();
    ce_kernel<<<KC * HH / 256, 256>>>();

    // 5) mixer with fully fused LN: stats ping-pong A (z) / B (z2).
    transpose_stats_kernel<<<tgrid, tblk>>>(p_h, p_z);
    for (int it = 0; it < NBITER; it++) {
        gemm_tc<E_RESGELU, 0, 1, -1><<<ggrid, 256>>>(p_z, w_ts, ts_b, p_z, p_z2,
                                                     ts_ln_g, ts_ln_b, w_ts, ts_b, p_z2);
        gemm_tc<E_GELU, 1, -1, 0><<<ggrid, 256>>>(p_z2, w_ch1, ch_b1, nullptr, p_t,
                                                  ch_ln_g, ch_ln_b, w_ch1, ch_b1, p_t);
        if (it < NBITER - 1)
            gemm_tc<E_RESBIAS, -1, 0, 1><<<ggrid, 256>>>(p_t, w_ch2, ch_b2, p_z2, p_z,
                                                         nullptr, nullptr, w_ch2, ch_b2, p_z);
        else
            gemm_tc<E_RESBIAS, -1, -1, -1><<<ggrid, 256>>>(p_t, w_ch2, ch_b2, p_z2, p_z,
                                                           nullptr, nullptr, w_ch2, ch_b2, p_z);
    }

    // 6) expert projection (theta fused) + RevIN denorm
    prod_kernel<<<tgrid, tblk>>>();
    final_kernel<<<CC / 2, 128>>>(out_w, out_b, rev_w, rev_b, y);
}

// round 14
// speedup vs baseline: 1.3819x; 1.0049x over previous
#include <cuda_runtime.h>
#include <math.h>
#include <stdint.h>

// ---------------- problem constants ----------------
#define BB 32
#define LL 512
#define CC 512
#define HH 512
#define KC 16          // clusters
#define PP 96
#define NBITER 4
#define ROWS (BB*CC)   // 16384
#define EPSV 1e-5f
#define GN 512         // GEMM N (all GEMMs are 16384x512x512)
#define GK 512         // GEMM K

// ---------------- scratch (static device globals; no allocation) ----------------
__device__ float g_xt   [(size_t)ROWS*HH];
__device__ float g_t    [(size_t)ROWS*HH];
__device__ float g_h    [(size_t)ROWS*HH];
__device__ float g_kk   [(size_t)ROWS*HH];
__device__ float g_v    [(size_t)ROWS*HH];
__device__ float g_z    [(size_t)ROWS*HH];
__device__ float g_z2   [(size_t)ROWS*HH];
__device__ float g_prod [(size_t)ROWS*HH];
__device__ float g_wts  [(size_t)7*GK*GN];    // tf32-rounded weights
__device__ float g_mean [ROWS];
__device__ float g_std  [ROWS];
__device__ float g_accA [ROWS];   // LN stats (sum) for z
__device__ float g_accA2[ROWS];   // LN stats (sumsq) for z
__device__ float g_accB [ROWS];   // LN stats (sum) for z2
__device__ float g_accB2[ROWS];   // LN stats (sumsq) for z2
__device__ float g_cn   [KC*HH];
__device__ float g_q    [KC*HH];
__device__ float g_p    [ROWS*KC];
__device__ float g_mask [ROWS*KC];
__device__ float g_am   [ROWS*KC];
__device__ float g_ce   [KC*HH];

// ---------------- helpers ----------------
__device__ __forceinline__ float gelu_f(float x) {
    return 0.5f * x * (1.0f + erff(x * 0.7071067811865476f));
}

__device__ __forceinline__ float f2tf32(float x) {
    uint32_t r;
    asm("cvt.rna.tf32.f32 %0, %1;" : "=r"(r) : "f"(x));
    return __uint_as_float(r);
}

__device__ __forceinline__ void cp16(uint32_t dst_smem, const void* src) {
    asm volatile("cp.async.ca.shared.global [%0], [%1], 16;"
                 :: "r"(dst_smem), "l"(src) : "memory");
}
__device__ __forceinline__ void cp_commit() {
    asm volatile("cp.async.commit_group;" ::: "memory");
}
template<int N>
__device__ __forceinline__ void cp_waitg() {
    asm volatile("cp.async.wait_group %0;" :: "n"(N) : "memory");
}

__device__ __forceinline__ uint32_t rotl32(uint32_t x, uint32_t d) {
    return (x << d) | (x >> (32u - d));
}

// JAX threefry2x32, PARTITIONABLE path. key = {0,42}; counter (0, idx);
// output word = out0 ^ out1.
__device__ uint32_t threefry_rand(uint32_t idx) {
    uint32_t x0 = 0u, x1 = idx;
    const uint32_t k0 = 0u, k1 = 42u;
    const uint32_t k2 = k0 ^ k1 ^ 0x1BD11BDAu;
    uint32_t ks[3] = {k0, k1, k2};
    x0 += ks[0]; x1 += ks[1];
    const uint32_t R[2][4] = {{13u,15u,26u,6u},{17u,29u,16u,24u}};
    #pragma unroll
    for (int i = 0; i < 5; i++) {
        #pragma unroll
        for (int j = 0; j < 4; j++) {
            x0 += x1; x1 = rotl32(x1, R[i & 1][j]); x1 ^= x0;
        }
        x0 += ks[(i + 1) % 3];
        x1 += ks[(i + 2) % 3] + (uint32_t)(i + 1);
    }
    return x0 ^ x1;
}

// ---------------- zero LN accumulators + ce (once) ----------------
__global__ void zacc_kernel() {
    int i = blockIdx.x * 256 + threadIdx.x;
    g_accA[i] = 0.f;
    g_accA2[i] = 0.f;
    g_accB[i] = 0.f;
    g_accB2[i] = 0.f;
    if (i < KC * HH) g_ce[i] = 0.f;
}

// ---------------- weight pre-round: all 7 matrices in one launch ----------------
__global__ void round_all_kernel(const float* s0, const float* s1, const float* s2,
                                 const float* s3, const float* s4, const float* s5,
                                 const float* s6) {
    int i = blockIdx.x * 256 + threadIdx.x;
    const float* s;
    switch (blockIdx.y) {
        case 0: s = s0; break; case 1: s = s1; break; case 2: s = s2; break;
        case 3: s = s3; break; case 4: s = s4; break; case 5: s = s5; break;
        default: s = s6; break;
    }
    g_wts[(size_t)blockIdx.y * GK * GN + i] = f2tf32(s[i]);
}

// ---------------- RevIN stats: 4 threads per channel, coalesced ----------------
__global__ void revin_stats_kernel(const float* __restrict__ x) {
    __shared__ float shs[4][64];
    __shared__ float shq[4][64];
    int b = blockIdx.y;
    int cl = threadIdx.x & 63;
    int sub = threadIdx.x >> 6;          // 0..3
    int c = blockIdx.x * 64 + cl;
    const float* xp = x + (size_t)b * LL * CC + (size_t)(sub * 128) * CC + c;
    float s = 0.f, s2 = 0.f;
    #pragma unroll 4
    for (int l = 0; l < 128; l++) {
        float v = xp[(size_t)l * CC];
        s += v; s2 += v * v;
    }
    shs[sub][cl] = s;
    shq[sub][cl] = s2;
    __syncthreads();
    if (sub == 0) {
        float ts = shs[0][cl] + shs[1][cl] + shs[2][cl] + shs[3][cl];
        float tq = shq[0][cl] + shq[1][cl] + shq[2][cl] + shq[3][cl];
        float m = ts * (1.0f / LL);
        float var = fmaxf(tq * (1.0f / LL) - m * m, 0.0f);
        g_mean[b * CC + c] = m;
        g_std [b * CC + c] = sqrtf(var + EPSV);
    }
}

// xt[b,c,l] = (x[b,l,c]-mean)/std*rev_w[c]+rev_b[c]   (tiled transpose)
__global__ void build_xt_kernel(const float* __restrict__ x,
                                const float* __restrict__ rev_w,
                                const float* __restrict__ rev_b) {
    __shared__ float sh[32][33];
    int b = blockIdx.z;
    int l0 = blockIdx.x * 32, c0 = blockIdx.y * 32;
    const float* xb = x + (size_t)b * LL * CC;
    float* ob = g_xt + (size_t)b * CC * LL;
    #pragma unroll
    for (int r = 0; r < 32; r += 8)
        sh[threadIdx.y + r][threadIdx.x] = xb[(size_t)(l0 + threadIdx.y + r) * CC + c0 + threadIdx.x];
    __syncthreads();
    #pragma unroll
    for (int r = 0; r < 32; r += 8) {
        int c = c0 + threadIdx.y + r;
        float mn = g_mean[b * CC + c];
        float sd = g_std[b * CC + c];
        float v = sh[threadIdx.x][threadIdx.y + r];
        ob[(size_t)c * LL + l0 + threadIdx.x] = (v - mn) / sd * rev_w[c] + rev_b[c];
    }
}

// ---------------- TF32 tensor-core GEMM, K-tile 16, 3-stage cp.async B ----
// Conflict-free smem layouts:
//  A: word(m,k) = m*16 + ((j^sw)<<2) + (2*akbit ^ (m&2)) + half.
//  B: row stride 136 (bank = (8*tig+gid)%32, bijective).
#define E_RELU    0
#define E_BIAS    1
#define E_GELU    2
#define E_RESGELU 3
#define E_RESBIAS 4

#define ASZ (128*16)   // A buffer floats
#define BSTR 136       // B row stride (words)
#define BSZ (16*BSTR)  // B buffer floats

__device__ __forceinline__ void mma_tf32(float c[4],
                                         uint32_t a0, uint32_t a1, uint32_t a2, uint32_t a3,
                                         uint32_t b0, uint32_t b1) {
    asm volatile(
        "mma.sync.aligned.m16n8k8.row.col.f32.tf32.tf32.f32 "
        "{%0,%1,%2,%3}, {%4,%5,%6,%7}, {%8,%9}, {%0,%1,%2,%3};"
        : "+f"(c[0]), "+f"(c[1]), "+f"(c[2]), "+f"(c[3])
        : "r"(a0), "r"(a1), "r"(a2), "r"(a3), "r"(b0), "r"(b1));
}

template<int EPI, int LNBUF, int SBUF, int ZBUF>
__global__ __launch_bounds__(256, 2) void gemm_tc(
    const float* __restrict__ A, const float* __restrict__ W,
    const float* __restrict__ bias, const float* __restrict__ res,
    float* __restrict__ out,
    const float* __restrict__ ln_g, const float* __restrict__ ln_b,
    const float* __restrict__ W2, const float* __restrict__ bias2,
    float* __restrict__ out2) {
    __shared__ float As[2 * ASZ];
    __shared__ float Bs[3 * BSZ];
    if (blockIdx.z) { W = W2; bias = bias2; out = out2; }
    const int tid = threadIdx.x;
    const int warp = tid >> 5, lane = tid & 31;
    const int wm = (warp >> 2) * 64;    // warp M offset: 0 or 64
    const int wn = (warp & 3) * 32;     // warp N offset: 0,32,64,96
    const int gid = lane >> 2;          // 0..7
    const int tig = lane & 3;           // 0..3
    const int bx = blockIdx.x, by = blockIdx.y;

    const int arow = tid >> 1;          // 0..127
    const int ak   = (tid & 1) * 8;     // 0 or 8
    const int ssw  = (arow >> 1) & 3;   // store swizzle
    const int soff = (ak >> 2) ^ (arow & 2);  // ks-slot offset with m&2 XOR
    const int brow = tid >> 5;          // 0..7
    const int bn   = lane * 4;          // 0..124

    if (ZBUF >= 0) {
        if (bx == 0 && blockIdx.z == 0 && tid < 128) {
            int row = by * 128 + tid;
            if (ZBUF == 0) { g_accA[row] = 0.f; g_accA2[row] = 0.f; }
            else           { g_accB[row] = 0.f; g_accB2[row] = 0.f; }
        }
    }

    float acc[4][4][4];
    #pragma unroll
    for (int i = 0; i < 4; i++)
        #pragma unroll
        for (int j = 0; j < 4; j++)
            #pragma unroll
            for (int r = 0; r < 4; r++) acc[i][j][r] = 0.f;

    const float* Ap  = A + (size_t)(by * 128 + arow) * GK + ak;
    const float* Wp0 = W + (size_t)brow * GN + bx * 128 + bn;

    const uint32_t bdst = (uint32_t)__cvta_generic_to_shared(Bs + brow * BSTR + bn);

    float mu = 0.f, rsd = 1.f;
    if (LNBUF >= 0) {
        int row = by * 128 + arow;
        float s  = (LNBUF == 0) ? g_accA[row]  : g_accB[row];
        float s2 = (LNBUF == 0) ? g_accA2[row] : g_accB2[row];
        mu = s * (1.0f / CC);
        float var = fmaxf(s2 * (1.0f / CC) - mu * mu, 0.0f);
        rsd = rsqrtf(var + EPSV);
    }

    const int NT = GK >> 4;

    auto issueB = [&](int buf, int kt) {
        const float* ws = Wp0 + (size_t)kt * 16 * GN;
        uint32_t d = bdst + (uint32_t)buf * (BSZ * 4);
        cp16(d, ws);
        cp16(d + 8 * BSTR * 4, ws + (size_t)8 * GN);
        cp_commit();
    };

    float4 pa0, pa1;
    auto loadA = [&](int kt) {
        pa0 = *(const float4*)(Ap + kt * 16);
        pa1 = *(const float4*)(Ap + kt * 16 + 4);
    };

    auto store_tileA = [&](int buf, int kt) {
        float va[8] = {pa0.x, pa0.y, pa0.z, pa0.w, pa1.x, pa1.y, pa1.z, pa1.w};
        if (LNBUF >= 0) {
            const float* gp = ln_g + kt * 16 + ak;
            const float* bp = ln_b + kt * 16 + ak;
            #pragma unroll
            for (int j = 0; j < 8; j++) {
                float t = rsd * gp[j];
                va[j] = (va[j] - mu) * t + bp[j];
            }
        }
        float* Ab = As + buf * ASZ;
        const int abase = arow * 16 + soff;
        #pragma unroll
        for (int j = 0; j < 4; j++) {
            *(float2*)(Ab + abase + ((j ^ ssw) << 2)) = make_float2(va[j], va[j + 4]);
        }
    };

    auto compute = [&](int abuf, int bbuf) {
        const float* Ab = As + abuf * ASZ;
        const float* Bb = Bs + bbuf * BSZ;
        #pragma unroll
        for (int ks = 0; ks < 2; ks++) {
            float2 fa0[4], fa1[4];
            #pragma unroll
            for (int i = 0; i < 4; i++) {
                int m0 = wm + i * 16 + gid;
                int sw = (m0 >> 1) & 3;
                int w = m0 * 16 + ((tig ^ sw) << 2) + ((ks * 2) ^ (m0 & 2));
                fa0[i] = *(const float2*)(Ab + w);
                fa1[i] = *(const float2*)(Ab + w + 128);   // row m0+8: same swizzle
            }
            float fb0[4], fb1[4];
            #pragma unroll
            for (int j = 0; j < 4; j++) {
                int n0 = wn + j * 8 + gid;
                fb0[j] = Bb[(ks * 8 + tig) * BSTR + n0];
                fb1[j] = Bb[(ks * 8 + tig + 4) * BSTR + n0];
            }
            #pragma unroll
            for (int i = 0; i < 4; i++)
                #pragma unroll
                for (int j = 0; j < 4; j++)
                    mma_tf32(acc[i][j],
                             __float_as_uint(fa0[i].x), __float_as_uint(fa1[i].x),
                             __float_as_uint(fa0[i].y), __float_as_uint(fa1[i].y),
                             __float_as_uint(fb0[j]), __float_as_uint(fb1[j]));
        }
    };

    // prologue: B0 and B1 in flight, A0 staged, A1 in registers
    issueB(0, 0);
    issueB(1, 1);
    loadA(0);
    store_tileA(0, 0);
    loadA(1);
    cp_waitg<1>();          // B0 complete (B1 may be outstanding)
    __syncthreads();

    int bcur = 0;
    for (int kt = 0; kt < NT; kt++) {
        const int acur = kt & 1;
        int bn2 = bcur + 2; if (bn2 >= 3) bn2 -= 3;
        if (kt + 2 < NT) issueB(bn2, kt + 2);
        compute(acur, bcur);
        if (kt + 1 < NT) {
            store_tileA(acur ^ 1, kt + 1);
            if (kt + 2 < NT) loadA(kt + 2);
        }
        if (kt + 2 < NT) cp_waitg<1>(); else cp_waitg<0>();
        __syncthreads();
        bcur++; if (bcur >= 3) bcur -= 3;
    }

    // epilogue (+ optional fused LN-stats accumulation of the OUTPUT rows)
    #pragma unroll
    for (int i = 0; i < 4; i++) {
        int gr0 = by * 128 + wm + i * 16 + gid;
        int gr1 = gr0 + 8;
        float slo = 0.f, qlo = 0.f, shi = 0.f, qhi = 0.f;
        #pragma unroll
        for (int j = 0; j < 4; j++) {
            int gc = bx * 128 + wn + j * 8 + 2 * tig;
            float b0v = bias[gc], b1v = bias[gc + 1];
            float v0 = acc[i][j][0] + b0v, v1 = acc[i][j][1] + b1v;
            float v2 = acc[i][j][2] + b0v, v3 = acc[i][j][3] + b1v;
            if (EPI == E_RELU) {
                v0 = fmaxf(v0, 0.f); v1 = fmaxf(v1, 0.f);
                v2 = fmaxf(v2, 0.f); v3 = fmaxf(v3, 0.f);
            } else if (EPI == E_GELU) {
                v0 = gelu_f(v0); v1 = gelu_f(v1);
                v2 = gelu_f(v2); v3 = gelu_f(v3);
            } else if (EPI == E_RESGELU) {
                const float2 r0 = *(const float2*)(res + (size_t)gr0 * GN + gc);
                const float2 r1 = *(const float2*)(res + (size_t)gr1 * GN + gc);
                v0 = r0.x + gelu_f(v0); v1 = r0.y + gelu_f(v1);
                v2 = r1.x + gelu_f(v2); v3 = r1.y + gelu_f(v3);
            } else if (EPI == E_RESBIAS) {
                const float2 r0 = *(const float2*)(res + (size_t)gr0 * GN + gc);
                const float2 r1 = *(const float2*)(res + (size_t)gr1 * GN + gc);
                v0 += r0.x; v1 += r0.y; v2 += r1.x; v3 += r1.y;
            }
            if (SBUF >= 0) {
                slo += v0 + v1; qlo += v0 * v0 + v1 * v1;
                shi += v2 + v3; qhi += v2 * v2 + v3 * v3;
            }
            *(float2*)(out + (size_t)gr0 * GN + gc) = make_float2(v0, v1);
            *(float2*)(out + (size_t)gr1 * GN + gc) = make_float2(v2, v3);
        }
        if (SBUF >= 0) {
            slo += __shfl_xor_sync(0xffffffffu, slo, 1);
            slo += __shfl_xor_sync(0xffffffffu, slo, 2);
            qlo += __shfl_xor_sync(0xffffffffu, qlo, 1);
            qlo += __shfl_xor_sync(0xffffffffu, qlo, 2);
            shi += __shfl_xor_sync(0xffffffffu, shi, 1);
            shi += __shfl_xor_sync(0xffffffffu, shi, 2);
            qhi += __shfl_xor_sync(0xffffffffu, qhi, 1);
            qhi += __shfl_xor_sync(0xffffffffu, qhi, 2);
            if (tig == 0) {
                float* a  = (SBUF == 0) ? g_accA  : g_accB;
                float* a2 = (SBUF == 0) ? g_accA2 : g_accB2;
                atomicAdd(&a[gr0], slo);
                atomicAdd(&a2[gr0], qlo);
                atomicAdd(&a[gr1], shi);
                atomicAdd(&a2[gr1], qhi);
            }
        }
    }
}

// ---------------- cluster normalize + Q projection (merged) ----------------
__global__ void cnq_kernel(const float* __restrict__ ce,
                           const float* __restrict__ wq,
                           const float* __restrict__ bq) {
    __shared__ float csh[HH];
    __shared__ float red[256];
    int k = blockIdx.x, tid = threadIdx.x;
    float v0 = ce[k * HH + tid], v1 = ce[k * HH + tid + 256];
    csh[tid] = v0;
    csh[tid + 256] = v1;
    red[tid] = v0 * v0 + v1 * v1;
    __syncthreads();
    for (int off = 128; off > 0; off >>= 1) {
        if (tid < off) red[tid] += red[tid + off];
        __syncthreads();
    }
    float nrm = fmaxf(sqrtf(red[0]), 1e-12f);
    g_cn[k * HH + tid] = v0 / nrm;
    g_cn[k * HH + tid + 256] = v1 / nrm;
    // q = ce_k @ wq + bq
    for (int n = tid; n < HH; n += 256) {
        float a = bq[n];
        for (int h = 0; h < HH; h++) a += csh[h] * wq[(size_t)h * HH + n];
        g_q[k * HH + n] = a;
    }
}

// ---------------- routing: warp per row; p = softmax(hn @ cn^T), bernoulli mask
__global__ __launch_bounds__(256) void routing_kernel(const float* __restrict__ h) {
    __shared__ float cnsh[KC * HH];   // 32KB
    int tid = threadIdx.x;
    for (int i = tid; i < KC * HH; i += 256) cnsh[i] = g_cn[i];
    __syncthreads();
    int w = tid >> 5, lane = tid & 31;
    int row = blockIdx.x * 8 + w;
    const float* hp = h + (size_t)row * HH;
    float acc[KC];
    #pragma unroll
    for (int k = 0; k < KC; k++) acc[k] = 0.f;
    float nsq = 0.f;
    #pragma unroll 4
    for (int i = 0; i < 16; i++) {
        int hh = i * 32 + lane;
        float hv = hp[hh];
        nsq += hv * hv;
        #pragma unroll
        for (int k = 0; k < KC; k++) acc[k] += hv * cnsh[k * HH + hh];
    }
    #pragma unroll
    for (int o = 16; o > 0; o >>= 1) nsq += __shfl_xor_sync(0xffffffffu, nsq, o);
    #pragma unroll
    for (int k = 0; k < KC; k++) {
        #pragma unroll
        for (int o = 16; o > 0; o >>= 1)
            acc[k] += __shfl_xor_sync(0xffffffffu, acc[k], o);
    }
    float inv = 1.0f / fmaxf(sqrtf(nsq), 1e-12f);
    float d = 0.f;
    #pragma unroll
    for (int k = 0; k < KC; k++) if (lane == k) d = acc[k];
    d *= inv;
    float mx = d;
    #pragma unroll
    for (int o = 8; o > 0; o >>= 1)
        mx = fmaxf(mx, __shfl_xor_sync(0xffffffffu, mx, o, 16));
    float e = expf(d - mx);
    float tot = e;
    #pragma unroll
    for (int o = 8; o > 0; o >>= 1)
        tot += __shfl_xor_sync(0xffffffffu, tot, o, 16);
    if (lane < KC) {
        float pv = e / tot;
        int idx = row * KC + lane;
        g_p[idx] = pv;
        uint32_t bits = threefry_rand((uint32_t)idx);
        float u = __uint_as_float((bits >> 9) | 0x3f800000u) - 1.0f;
        g_mask[idx] = (u < pv) ? 1.0f : 0.0f;
    }
}

// ---------------- attention phase 1: am = exp(score)*mask per row ----------------
__global__ __launch_bounds__(256) void scores_kernel() {
    __shared__ float qsh[KC * HH];   // [k][h], 32KB
    int tid = threadIdx.x;
    for (int i = tid; i < KC * HH; i += 256) qsh[i] = g_q[i];
    __syncthreads();
    int w = tid >> 5, lane = tid & 31;
    int row = blockIdx.x * 8 + w;
    const float* kp = g_kk + (size_t)row * HH;
    float acc[KC];
    #pragma unroll
    for (int k = 0; k < KC; k++) acc[k] = 0.f;
    #pragma unroll 4
    for (int i = 0; i < 16; i++) {
        int hh = i * 32 + lane;
        float kv = kp[hh];
        #pragma unroll
        for (int k = 0; k < KC; k++) acc[k] += kv * qsh[k * HH + hh];
    }
    #pragma unroll
    for (int k = 0; k < KC; k++) {
        #pragma unroll
        for (int o = 16; o > 0; o >>= 1)
            acc[k] += __shfl_xor_sync(0xffffffffu, acc[k], o);
    }
    if (lane < KC) {
        float am = expf(acc[lane] * 0.04419417382415922f) * g_mask[row * KC + lane];
        g_am[row * KC + lane] = am;
    }
}

// ---------------- attention: ce[k][h] += (sum_c aw*V / sum_c aw) / BB --------
__global__ __launch_bounds__(256) void vweight_kernel() {
    __shared__ float aw[KC * 514];
    __shared__ float part[KC][17];
    __shared__ float inv_sh[KC];
    int b = blockIdx.x, h0 = blockIdx.y * 128;
    int tid = threadIdx.x;
    for (int idx = tid; idx < CC * KC; idx += 256) {
        int c = idx >> 4, k = idx & 15;
        aw[k * 514 + c] = g_am[((size_t)b * CC + c) * KC + k];
    }
    __syncthreads();
    {
        int k = tid & 15, ci = tid >> 4;  // ci 0..15
        float ps = 0.f;
        for (int c = ci; c < CC; c += 16) ps += aw[k * 514 + c];
        part[k][ci] = ps;
    }
    __syncthreads();
    if (tid < KC) {
        float s = 0.f;
        #pragma unroll
        for (int i = 0; i < 16; i++) s += part[tid][i];
        inv_sh[tid] = 1.0f / (s * (float)BB);   // normalize + batch-mean factor
    }
    __syncthreads();
    int kg = tid >> 6;
    int hg = tid & 63;
    const float* vp = g_v + (size_t)b * CC * HH + h0 + hg * 2;
    float a0[4], a1[4];
    #pragma unroll
    for (int k = 0; k < 4; k++) { a0[k] = 0.f; a1[k] = 0.f; }
    for (int c = 0; c < CC; c += 2) {
        float2 v0 = *(const float2*)(vp + (size_t)c * HH);
        float2 v1 = *(const float2*)(vp + (size_t)(c + 1) * HH);
        #pragma unroll
        for (int k = 0; k < 4; k++) {
            float2 a2 = *(const float2*)(&aw[(kg * 4 + k) * 514 + c]);
            a0[k] += a2.x * v0.x + a2.y * v1.x;
            a1[k] += a2.x * v0.y + a2.y * v1.y;
        }
    }
    #pragma unroll
    for (int k = 0; k < 4; k++) {
        float inv = inv_sh[kg * 4 + k];
        size_t o = (size_t)(kg * 4 + k) * HH + h0 + hg * 2;
        atomicAdd(&g_ce[o],     a0[k] * inv);
        atomicAdd(&g_ce[o + 1], a1[k] * inv);
    }
}

// transpose per batch (h -> z) WITH fused LN-stats accumulation into accA
__global__ void transpose_stats_kernel(const float* __restrict__ in, float* __restrict__ out) {
    __shared__ float sh[32][33];
    int b = blockIdx.z;
    int i0 = blockIdx.y * 32, j0 = blockIdx.x * 32;
    const float* ib = in + (size_t)b * CC * HH;
    float* ob = out + (size_t)b * CC * HH;
    #pragma unroll
    for (int r = 0; r < 32; r += 8)
        sh[threadIdx.y + r][threadIdx.x] = ib[(size_t)(i0 + threadIdx.y + r) * HH + j0 + threadIdx.x];
    __syncthreads();
    #pragma unroll
    for (int r = 0; r < 32; r += 8) {
        float v = sh[threadIdx.x][threadIdx.y + r];
        ob[(size_t)(j0 + threadIdx.y + r) * HH + i0 + threadIdx.x] = v;
        float s = v, q = v * v;
        #pragma unroll
        for (int o = 16; o > 0; o >>= 1) {
            s += __shfl_xor_sync(0xffffffffu, s, o);
            q += __shfl_xor_sync(0xffffffffu, q, o);
        }
        if (threadIdx.x == 0) {
            int row = b * HH + j0 + threadIdx.y + r;
            atomicAdd(&g_accA[row], s);
            atomicAdd(&g_accA2[row], q);
        }
    }
}

// prod[b,c,h] = z[b,h,c] * theta[b,c,h], theta computed on the fly from p & ce
__global__ void prod_kernel() {
    __shared__ float sh[32][33];
    __shared__ float cesh[KC][32];
    __shared__ float psh[32][KC + 1];
    int b = blockIdx.z;
    int h0 = blockIdx.y * 32, c0 = blockIdx.x * 32;
    const float* zb = g_z + (size_t)b * HH * CC;
    float* ob = g_prod + (size_t)b * CC * HH;
    int tid = threadIdx.y * 32 + threadIdx.x;
    #pragma unroll
    for (int r = 0; r < 32; r += 8)
        sh[threadIdx.y + r][threadIdx.x] = zb[(size_t)(h0 + threadIdx.y + r) * CC + c0 + threadIdx.x];
    for (int t = tid; t < KC * 32; t += 256) {
        int k = t >> 5, xx = t & 31;
        cesh[k][xx] = g_ce[k * HH + h0 + xx];
    }
    for (int t = tid; t < 32 * KC; t += 256) {
        int c = t >> 4, k = t & 15;
        psh[c][k] = g_p[((size_t)b * CC + c0 + c) * KC + k];
    }
    __syncthreads();
    #pragma unroll
    for (int r = 0; r < 32; r += 8) {
        int cl = threadIdx.y + r;
        float th = 0.f;
        #pragma unroll
        for (int k = 0; k < KC; k++) th += psh[cl][k] * cesh[k][threadIdx.x];
        size_t o = (size_t)(c0 + cl) * HH + h0 + threadIdx.x;
        ob[o] = sh[threadIdx.x][cl] * th;
    }
}

// final: y[b,p,c] = denorm( sum_h prod[b,c,h]*out_w[c,h,p] + out_b[c,p] )
// block = 128 threads = 2 channels x 64 threads; thread = 4 batches x 12 p.
__global__ __launch_bounds__(128) void final_kernel(
    const float* __restrict__ out_w, const float* __restrict__ out_b,
    const float* __restrict__ rev_w, const float* __restrict__ rev_b,
    float* __restrict__ y) {
    __shared__ float As[2][32][33];
    __shared__ float Ws[2][32][PP];
    int tid = threadIdx.x;
    int cg = tid >> 6;                  // 0/1
    int t  = tid & 63;
    int c  = blockIdx.x * 2 + cg;
    int b4 = t >> 3;                    // batch group: batches 4*b4..4*b4+3
    int tp = (t & 7) * 12;              // p base
    float acc[4][12];
    #pragma unroll
    for (int k = 0; k < 4; k++)
        #pragma unroll
        for (int j = 0; j < 12; j++) acc[k][j] = 0.f;

    for (int h0 = 0; h0 < HH; h0 += 32) {
        #pragma unroll
        for (int j = 0; j < 4; j++) {
            int u = j * 64 + t;
            int b = u >> 3, hq = (u & 7) * 4;
            float4 v = *(const float4*)(g_prod + ((size_t)b * CC + c) * HH + h0 + hq);
            As[cg][b][hq + 0] = v.x; As[cg][b][hq + 1] = v.y;
            As[cg][b][hq + 2] = v.z; As[cg][b][hq + 3] = v.w;
        }
        #pragma unroll
        for (int j = 0; j < 12; j++) {
            int u = j * 64 + t;
            int row = u / 24, col = (u % 24) * 4;
            *(float4*)&Ws[cg][row][col] =
                *(const float4*)(out_w + ((size_t)c * HH + h0 + row) * PP + col);
        }
        __syncthreads();
        #pragma unroll 4
        for (int i = 0; i < 32; i++) {
            float a0 = As[cg][b4 * 4 + 0][i];
            float a1 = As[cg][b4 * 4 + 1][i];
            float a2 = As[cg][b4 * 4 + 2][i];
            float a3 = As[cg][b4 * 4 + 3][i];
            const float4 w0 = *(const float4*)&Ws[cg][i][tp];
            const float4 w1 = *(const float4*)&Ws[cg][i][tp + 4];
            const float4 w2 = *(const float4*)&Ws[cg][i][tp + 8];
            const float wv[12] = {w0.x, w0.y, w0.z, w0.w, w1.x, w1.y, w1.z, w1.w,
                                  w2.x, w2.y, w2.z, w2.w};
            #pragma unroll
            for (int j = 0; j < 12; j++) {
                acc[0][j] += a0 * wv[j];
                acc[1][j] += a1 * wv[j];
                acc[2][j] += a2 * wv[j];
                acc[3][j] += a3 * wv[j];
            }
        }
        __syncthreads();
    }
    float rb = rev_b[c];
    float rwinv = 1.0f / (rev_w[c] + 1e-10f);
    #pragma unroll
    for (int k = 0; k < 4; k++) {
        int b = b4 * 4 + k;
        float sd = g_std[b * CC + c];
        float mn = g_mean[b * CC + c];
        #pragma unroll
        for (int j = 0; j < 12; j++) {
            float v = acc[k][j] + out_b[(size_t)c * PP + tp + j];
            v = (v - rb) * rwinv;
            v = v * sd + mn;
            y[((size_t)b * PP + tp + j) * CC + c] = v;
        }
    }
}

// ---------------- host orchestration ----------------
extern "C" void kernel_launch(void* const* d_in, const int* in_sizes, int n_in,
                              void* d_out, int out_size) {
    const float* x       = (const float*)d_in[0];
    const float* rev_w   = (const float*)d_in[1];
    const float* rev_b   = (const float*)d_in[2];
    const float* mlp_w1  = (const float*)d_in[3];
    const float* mlp_b1  = (const float*)d_in[4];
    const float* mlp_w2  = (const float*)d_in[5];
    const float* mlp_b2  = (const float*)d_in[6];
    const float* cle     = (const float*)d_in[7];
    const float* wq      = (const float*)d_in[8];
    const float* bq      = (const float*)d_in[9];
    const float* wk      = (const float*)d_in[10];
    const float* bk      = (const float*)d_in[11];
    const float* wv      = (const float*)d_in[12];
    const float* bv      = (const float*)d_in[13];
    const float* ts_ln_g = (const float*)d_in[14];
    const float* ts_ln_b = (const float*)d_in[15];
    const float* ts_w    = (const float*)d_in[16];
    const float* ts_b    = (const float*)d_in[17];
    const float* ch_ln_g = (const float*)d_in[18];
    const float* ch_ln_b = (const float*)d_in[19];
    const float* ch_w1   = (const float*)d_in[20];
    const float* ch_b1   = (const float*)d_in[21];
    const float* ch_w2   = (const float*)d_in[22];
    const float* ch_b2   = (const float*)d_in[23];
    const float* out_w   = (const float*)d_in[24];
    const float* out_b   = (const float*)d_in[25];
    float* y = (float*)d_out;

    float *p_xt, *p_t, *p_h, *p_kk, *p_v, *p_z, *p_z2, *p_w;
    cudaGetSymbolAddress((void**)&p_xt, g_xt);
    cudaGetSymbolAddress((void**)&p_t,  g_t);
    cudaGetSymbolAddress((void**)&p_h,  g_h);
    cudaGetSymbolAddress((void**)&p_kk, g_kk);
    cudaGetSymbolAddress((void**)&p_v,  g_v);
    cudaGetSymbolAddress((void**)&p_z,  g_z);
    cudaGetSymbolAddress((void**)&p_z2, g_z2);
    cudaGetSymbolAddress((void**)&p_w,  g_wts);

    const size_t WSZ = (size_t)GK * GN;
    float* w_mlp1 = p_w + 0 * WSZ;
    float* w_mlp2 = p_w + 1 * WSZ;
    float* w_k    = p_w + 2 * WSZ;
    float* w_v    = p_w + 3 * WSZ;
    float* w_ts   = p_w + 4 * WSZ;
    float* w_ch1  = p_w + 5 * WSZ;
    float* w_ch2  = p_w + 6 * WSZ;

    dim3 tgrid(16, 16, BB), tblk(32, 8);
    dim3 ggrid(GN / 128, ROWS / 128);
    dim3 ggrid2(GN / 128, ROWS / 128, 2);
    const int RWB = (int)(WSZ / 256);

    // 0) zero LN accumulators + g_ce; pre-round all weights to tf32
    zacc_kernel<<<ROWS / 256, 256>>>();
    round_all_kernel<<<dim3(RWB, 7), 256>>>(mlp_w1, mlp_w2, wk, wv, ts_w, ch_w1, ch_w2);

    // 1) RevIN stats + normalized transpose
    revin_stats_kernel<<<dim3(CC / 64, BB), 256>>>(x);
    build_xt_kernel<<<tgrid, tblk>>>(x, rev_w, rev_b);

    // 2) channel MLP: h = relu(xt@w1+b1)@w2+b2
    gemm_tc<E_RELU, -1, -1, -1><<<ggrid, 256>>>(p_xt, w_mlp1, mlp_b1, nullptr, p_t,
                                                nullptr, nullptr, w_mlp1, mlp_b1, p_t);
    gemm_tc<E_BIAS, -1, -1, -1><<<ggrid, 256>>>(p_t, w_mlp2, mlp_b2, nullptr, p_h,
                                                nullptr, nullptr, w_mlp2, mlp_b2, p_h);

    // 3) routing (p + threefry bernoulli mask)
    cnq_kernel<<<KC, 256>>>(cle, wq, bq);
    routing_kernel<<<ROWS / 8, 256>>>(p_h);

    // 4) K/V projections (ONE launch) + attention; ce accumulated in vweight
    gemm_tc<E_BIAS, -1, -1, -1><<<ggrid2, 256>>>(p_h, w_k, bk, nullptr, p_kk,
                                                 nullptr, nullptr, w_v, bv, p_v);
    scores_kernel<<<ROWS / 8, 256>>>();
    vweight_kernel<<<dim3(BB, HH / 128), 256>>>();

    // 5) mixer with fully fused LN: stats ping-pong A (z) / B (z2).
    transpose_stats_kernel<<<tgrid, tblk>>>(p_h, p_z);
    for (int it = 0; it < NBITER; it++) {
        gemm_tc<E_RESGELU, 0, 1, -1><<<ggrid, 256>>>(p_z, w_ts, ts_b, p_z, p_z2,
                                                     ts_ln_g, ts_ln_b, w_ts, ts_b, p_z2);
        gemm_tc<E_GELU, 1, -1, 0><<<ggrid, 256>>>(p_z2, w_ch1, ch_b1, nullptr, p_t,
                                                  ch_ln_g, ch_ln_b, w_ch1, ch_b1, p_t);
        if (it < NBITER - 1)
            gemm_tc<E_RESBIAS, -1, 0, 1><<<ggrid, 256>>>(p_t, w_ch2, ch_b2, p_z2, p_z,
                                                         nullptr, nullptr, w_ch2, ch_b2, p_z);
        else
            gemm_tc<E_RESBIAS, -1, -1, -1><<<ggrid, 256>>>(p_t, w_ch2, ch_b2, p_z2, p_z,
                                                           nullptr, nullptr, w_ch2, ch_b2, p_z);
    }

    // 6) expert projection (theta fused) + RevIN denorm
    prod_kernel<<<tgrid, tblk>>>();
    final_kernel<<<CC / 2, 128>>>(out_w, out_b, rev_w, rev_b, y);
}